// round 1
// baseline (speedup 1.0000x reference)
#include <cuda_runtime.h>
#include <math.h>

// Problem constants
#define S_    2048
#define H_    2048
#define NH_   16
#define HD_   128
#define ROT_  32
#define FF_   8192
#define L_    2
#define V_    32000
#define EPS_  1e-5f

// ---------------------------------------------------------------------------
// Scratch (static device globals; no runtime allocation)
// ---------------------------------------------------------------------------
__device__ float g_h  [(size_t)S_ * H_];
__device__ float g_ln1[(size_t)S_ * H_];
__device__ float g_ln2[(size_t)S_ * H_];
__device__ float g_qkv[(size_t)S_ * 3 * H_];
__device__ float g_ctx[(size_t)S_ * H_];
__device__ float g_fc1[(size_t)S_ * FF_];
__device__ float g_scores[(size_t)NH_ * S_ * S_];

// ---------------------------------------------------------------------------
// Embedding gather: h[s,:] = embed[x[s],:]
// ---------------------------------------------------------------------------
__global__ void embed_kernel(const int* __restrict__ x,
                             const float* __restrict__ embed,
                             float* __restrict__ h) {
    int s = blockIdx.y;
    int c = blockIdx.x * 256 + threadIdx.x;
    h[(size_t)s * H_ + c] = embed[(size_t)x[s] * H_ + c];
}

// ---------------------------------------------------------------------------
// LayerNorm: one block (256 thr) per row of H_=2048; row held in registers.
// ---------------------------------------------------------------------------
__global__ void ln_kernel(const float* __restrict__ in,
                          const float* __restrict__ g,
                          const float* __restrict__ b,
                          float* __restrict__ out) {
    const int s = blockIdx.x;
    const int tid = threadIdx.x;
    const float* row = in + (size_t)s * H_;
    __shared__ float red[256];

    float v[8];
    float lsum = 0.f;
#pragma unroll
    for (int i = 0; i < 8; i++) {
        v[i] = row[tid + i * 256];
        lsum += v[i];
    }
    red[tid] = lsum; __syncthreads();
    for (int o = 128; o > 0; o >>= 1) {
        if (tid < o) red[tid] += red[tid + o];
        __syncthreads();
    }
    const float mean = red[0] * (1.f / H_);
    __syncthreads();

    float lvar = 0.f;
#pragma unroll
    for (int i = 0; i < 8; i++) {
        float d = v[i] - mean;
        lvar += d * d;
    }
    red[tid] = lvar; __syncthreads();
    for (int o = 128; o > 0; o >>= 1) {
        if (tid < o) red[tid] += red[tid + o];
        __syncthreads();
    }
    const float rstd = rsqrtf(red[0] * (1.f / H_) + EPS_);

#pragma unroll
    for (int i = 0; i < 8; i++) {
        int c = tid + i * 256;
        out[(size_t)s * H_ + c] = (v[i] - mean) * rstd * g[c] + b[c];
    }
}

// ---------------------------------------------------------------------------
// Rotary (in place on qkv): first ROT_ dims of q and k per head.
// cos/sin[s,d] use inv_freq[d mod 16] = 10000^(-(d mod 16)/16).
// rotate_half over 32 dims: out[d]   = x[d]*c - x[d+16]*s (d<16)
//                           out[d+16]= x[d+16]*c + x[d]*s
// ---------------------------------------------------------------------------
__global__ void rotary_kernel(float* __restrict__ qkv) {
    int idx = blockIdx.x * 256 + threadIdx.x;   // S_*NH_*16 threads
    int i = idx & 15;
    int n = (idx >> 4) & 15;
    int s = idx >> 8;
    // ln(10000)/16
    float inv = expf(-(float)i * 0.575646273248511f);
    float ang = (float)s * inv;
    float sn, cs;
    sincosf(ang, &sn, &cs);
    float* p = qkv + (size_t)s * (3 * H_) + n * (3 * HD_);
    // q
    float a = p[i], c2 = p[i + 16];
    p[i]      = a * cs - c2 * sn;
    p[i + 16] = c2 * cs + a * sn;
    // k
    float* pk = p + HD_;
    a = pk[i]; c2 = pk[i + 16];
    pk[i]      = a * cs - c2 * sn;
    pk[i + 16] = c2 * cs + a * sn;
}

// ---------------------------------------------------------------------------
// Causal softmax: one block per (q, head). Only k <= q is read (exact match:
// masked entries contribute exp(-10000-max)=0 in fp32). Zeroes k>q so ctx
// GEMM can read dense rows.
// ---------------------------------------------------------------------------
__global__ void softmax_kernel(float* __restrict__ scores) {
    const int q = blockIdx.x;
    const int n = blockIdx.y;
    float* row = scores + ((size_t)n * S_ + q) * (size_t)S_;
    const int len = q + 1;
    const int tid = threadIdx.x;
    __shared__ float red[256];

    float mx = -3.4e38f;
    for (int i = tid; i < len; i += 256) mx = fmaxf(mx, row[i]);
    red[tid] = mx; __syncthreads();
    for (int o = 128; o > 0; o >>= 1) {
        if (tid < o) red[tid] = fmaxf(red[tid], red[tid + o]);
        __syncthreads();
    }
    mx = red[0]; __syncthreads();

    float sum = 0.f;
    for (int i = tid; i < len; i += 256) {
        float e = expf(row[i] - mx);
        row[i] = e;
        sum += e;
    }
    red[tid] = sum; __syncthreads();
    for (int o = 128; o > 0; o >>= 1) {
        if (tid < o) red[tid] += red[tid + o];
        __syncthreads();
    }
    const float inv = 1.f / red[0];

    for (int i = tid; i < len; i += 256) row[i] *= inv;
    for (int i = len + tid; i < S_; i += 256) row[i] = 0.f;
}

// ---------------------------------------------------------------------------
// Generic 128x128x8 tiled SGEMM, 256 threads, 8x8 per-thread tile.
//   C[M,N] = alpha * A[M,K] @ op(B) (+ bias) with epilogue EPI:
//     EPI=0: store,  EPI=1: gelu then store,  EPI=2: accumulate into C.
//   TRANSB: B given as [N,K] row-major (used for q@k^T).
//   CAUSAL: skip blocks fully above the diagonal (masked region never read).
//   blockIdx.z batches with strides sA/sB/sC (heads).
// Dims must be multiples of (128,128,8) — all shapes in this model are.
// ---------------------------------------------------------------------------
__device__ __forceinline__ float gelu_f(float x) {
    float t = tanhf(0.79788456f * x * (1.f + 0.044715f * x * x));
    return 0.5f * x * (1.f + t);
}

template <bool TRANSB, int EPI, bool CAUSAL>
__global__ void __launch_bounds__(256, 2) gemm128(
    const float* __restrict__ A, int lda, long long sA,
    const float* __restrict__ B, int ldb, long long sB,
    const float* __restrict__ bias,
    float* __restrict__ C, int ldc, long long sC,
    int K, float alpha) {

    A += (size_t)blockIdx.z * sA;
    B += (size_t)blockIdx.z * sB;
    C += (size_t)blockIdx.z * sC;

    const int row0 = blockIdx.y * 128;
    const int col0 = blockIdx.x * 128;
    if (CAUSAL && col0 > row0 + 127) return;

    __shared__ float As[8][128];
    __shared__ float Bs[8][128];

    const int tid = threadIdx.x;
    const int tx = tid & 15;
    const int ty = tid >> 4;

    float acc[8][8];
#pragma unroll
    for (int i = 0; i < 8; i++)
#pragma unroll
        for (int j = 0; j < 8; j++) acc[i][j] = 0.f;

    const int lr = tid >> 1;         // 0..127
    const int lk = (tid & 1) * 4;    // 0 or 4
    const int bk = tid >> 5;         // 0..7  (NN B row)
    const int bc = (tid & 31) * 4;   // 0..124 (NN B col)

    const float* Aptr = A + (size_t)(row0 + lr) * lda + lk;
    const float* Bptr = TRANSB ? (B + (size_t)(col0 + lr) * ldb + lk)
                               : (B + (size_t)bk * ldb + col0 + bc);

    for (int k0 = 0; k0 < K; k0 += 8) {
        float4 av = *(const float4*)(Aptr + k0);
        As[lk + 0][lr] = av.x;
        As[lk + 1][lr] = av.y;
        As[lk + 2][lr] = av.z;
        As[lk + 3][lr] = av.w;
        if (TRANSB) {
            float4 bv = *(const float4*)(Bptr + k0);
            Bs[lk + 0][lr] = bv.x;
            Bs[lk + 1][lr] = bv.y;
            Bs[lk + 2][lr] = bv.z;
            Bs[lk + 3][lr] = bv.w;
        } else {
            float4 bv = *(const float4*)(Bptr + (size_t)k0 * ldb);
            *(float4*)&Bs[bk][bc] = bv;
        }
        __syncthreads();

#pragma unroll
        for (int kk = 0; kk < 8; kk++) {
            float a[8], b[8];
            *(float4*)(a)     = *(const float4*)&As[kk][ty * 8];
            *(float4*)(a + 4) = *(const float4*)&As[kk][ty * 8 + 4];
            *(float4*)(b)     = *(const float4*)&Bs[kk][tx * 8];
            *(float4*)(b + 4) = *(const float4*)&Bs[kk][tx * 8 + 4];
#pragma unroll
            for (int i = 0; i < 8; i++)
#pragma unroll
                for (int j = 0; j < 8; j++)
                    acc[i][j] = fmaf(a[i], b[j], acc[i][j]);
        }
        __syncthreads();
    }

#pragma unroll
    for (int i = 0; i < 8; i++) {
        const int r = row0 + ty * 8 + i;
        float* crow = C + (size_t)r * ldc + col0;
#pragma unroll
        for (int j = 0; j < 8; j++) {
            const int c = tx * 8 + j;
            float val = acc[i][j] * alpha;
            if (bias) val += bias[col0 + c];
            if (EPI == 1) val = gelu_f(val);
            if (EPI == 2) crow[c] += val;
            else          crow[c] = val;
        }
    }
}

// ---------------------------------------------------------------------------
// Launcher
// ---------------------------------------------------------------------------
extern "C" void kernel_launch(void* const* d_in, const int* in_sizes, int n_in,
                              void* d_out, int out_size) {
    const int*   x        = (const int*)  d_in[0];
    const float* embed    = (const float*)d_in[1];
    const float* ln1_g    = (const float*)d_in[2];
    const float* ln1_b    = (const float*)d_in[3];
    const float* ln2_g    = (const float*)d_in[4];
    const float* ln2_b    = (const float*)d_in[5];
    const float* qkv_w    = (const float*)d_in[6];
    const float* qkv_b    = (const float*)d_in[7];
    const float* dense_w  = (const float*)d_in[8];
    const float* dense_b  = (const float*)d_in[9];
    const float* fc1_w    = (const float*)d_in[10];
    const float* fc1_b    = (const float*)d_in[11];
    const float* fc2_w    = (const float*)d_in[12];
    const float* fc2_b    = (const float*)d_in[13];
    const float* fln_g    = (const float*)d_in[14];
    const float* fln_b    = (const float*)d_in[15];
    const float* logits_w = (const float*)d_in[16];
    float* out = (float*)d_out;

    float *h, *ln1v, *ln2v, *qkv, *ctx, *fc1, *scores;
    cudaGetSymbolAddress((void**)&h,      g_h);
    cudaGetSymbolAddress((void**)&ln1v,   g_ln1);
    cudaGetSymbolAddress((void**)&ln2v,   g_ln2);
    cudaGetSymbolAddress((void**)&qkv,    g_qkv);
    cudaGetSymbolAddress((void**)&ctx,    g_ctx);
    cudaGetSymbolAddress((void**)&fc1,    g_fc1);
    cudaGetSymbolAddress((void**)&scores, g_scores);

    const float inv_sqrt_hd = 0.08838834764831845f;  // 1/sqrt(128)

    embed_kernel<<<dim3(H_ / 256, S_), 256>>>(x, embed, h);

    for (int l = 0; l < L_; l++) {
        // Both LayerNorms read the pre-update h.
        ln_kernel<<<S_, 256>>>(h, ln1_g + (size_t)l * H_, ln1_b + (size_t)l * H_, ln1v);
        ln_kernel<<<S_, 256>>>(h, ln2_g + (size_t)l * H_, ln2_b + (size_t)l * H_, ln2v);

        // qkv = ln1 @ qkv_w + qkv_b     [S, 3H]
        gemm128<false, 0, false><<<dim3(3 * H_ / 128, S_ / 128, 1), 256>>>(
            ln1v, H_, 0,
            qkv_w + (size_t)l * H_ * 3 * H_, 3 * H_, 0,
            qkv_b + (size_t)l * 3 * H_,
            qkv, 3 * H_, 0, H_, 1.f);

        rotary_kernel<<<(S_ * NH_ * 16) / 256, 256>>>(qkv);

        // scores[h] = q[h] @ k[h]^T / sqrt(HD)   (causal blocks only)
        gemm128<true, 0, true><<<dim3(S_ / 128, S_ / 128, NH_), 256>>>(
            qkv, 3 * H_, 3 * HD_,             // A: q, per-head stride 384
            qkv + HD_, 3 * H_, 3 * HD_,       // B: k, [N,K] transposed access
            nullptr,
            scores, S_, (long long)S_ * S_, HD_, inv_sqrt_hd);

        softmax_kernel<<<dim3(S_, NH_), 256>>>(scores);

        // ctx[h] = probs[h] @ v[h]     [S, HD] per head -> [S, H]
        gemm128<false, 0, false><<<dim3(HD_ / 128, S_ / 128, NH_), 256>>>(
            scores, S_, (long long)S_ * S_,
            qkv + 2 * HD_, 3 * H_, 3 * HD_,
            nullptr,
            ctx, H_, HD_, S_, 1.f);

        // h += ctx @ dense_w + dense_b   (residual fused in epilogue)
        gemm128<false, 2, false><<<dim3(H_ / 128, S_ / 128, 1), 256>>>(
            ctx, H_, 0,
            dense_w + (size_t)l * H_ * H_, H_, 0,
            dense_b + (size_t)l * H_,
            h, H_, 0, H_, 1.f);

        // fc1 = gelu(ln2 @ fc1_w + fc1_b)
        gemm128<false, 1, false><<<dim3(FF_ / 128, S_ / 128, 1), 256>>>(
            ln2v, H_, 0,
            fc1_w + (size_t)l * H_ * FF_, FF_, 0,
            fc1_b + (size_t)l * FF_,
            fc1, FF_, 0, H_, 1.f);

        // h += fc1 @ fc2_w + fc2_b
        gemm128<false, 2, false><<<dim3(H_ / 128, S_ / 128, 1), 256>>>(
            fc1, FF_, 0,
            fc2_w + (size_t)l * FF_ * H_, H_, 0,
            fc2_b + (size_t)l * H_,
            h, H_, 0, FF_, 1.f);
    }

    // Final LN (reuse ln1 buffer) + logits GEMM
    ln_kernel<<<S_, 256>>>(h, fln_g, fln_b, ln1v);
    gemm128<false, 0, false><<<dim3(V_ / 128, S_ / 128, 1), 256>>>(
        ln1v, H_, 0,
        logits_w, V_, 0,
        nullptr,
        out, V_, 0, H_, 1.f);
}

// round 3
// speedup vs baseline: 1.9934x; 1.9934x over previous
#include <cuda_runtime.h>
#include <cuda_bf16.h>
#include <math.h>
#include <stdint.h>

// Problem constants
#define S_    2048
#define H_    2048
#define NH_   16
#define HD_   128
#define ROT_  32
#define FF_   8192
#define L_    2
#define V_    32000
#define EPS_  1e-5f

// ---------------------------------------------------------------------------
// Scratch (static device globals)
// ---------------------------------------------------------------------------
__device__ float g_h  [(size_t)S_ * H_];
__device__ float g_ln1[(size_t)S_ * H_];
__device__ float g_ln2[(size_t)S_ * H_];
__device__ float g_qkv[(size_t)S_ * 3 * H_];
__device__ float g_ctx[(size_t)S_ * H_];
__device__ float g_fc1[(size_t)S_ * FF_];
__device__ float g_scores[(size_t)NH_ * S_ * S_];

// ---------------------------------------------------------------------------
// Helpers
// ---------------------------------------------------------------------------
__device__ __forceinline__ uint32_t smem_u32(const void* p) {
    uint32_t a;
    asm("{ .reg .u64 t; cvta.to.shared.u64 t, %1; cvt.u32.u64 %0, t; }"
        : "=r"(a) : "l"(p));
    return a;
}
// SW128 swizzle for 128-byte rows
__device__ __forceinline__ uint32_t swz(uint32_t off) {
    return off ^ ((off >> 3) & 0x70);
}
__device__ __forceinline__ float gelu_f(float x) {
    float t = tanhf(0.79788456f * x * (1.f + 0.044715f * x * x));
    return 0.5f * x * (1.f + t);
}
// split fp32 pair into packed bf16x2 hi + bf16x2 lo
__device__ __forceinline__ uint32_t pack2(float x, float y, uint32_t& lo) {
    __nv_bfloat16 hx = __float2bfloat16_rn(x);
    __nv_bfloat16 hy = __float2bfloat16_rn(y);
    __nv_bfloat16 lx = __float2bfloat16_rn(x - __bfloat162float(hx));
    __nv_bfloat16 ly = __float2bfloat16_rn(y - __bfloat162float(hy));
    lo = (uint32_t)__bfloat16_as_ushort(lx) | ((uint32_t)__bfloat16_as_ushort(ly) << 16);
    return (uint32_t)__bfloat16_as_ushort(hx) | ((uint32_t)__bfloat16_as_ushort(hy) << 16);
}

__device__ __forceinline__ void ldsm4(uint32_t (&r)[4], uint32_t addr) {
    asm volatile("ldmatrix.sync.aligned.m8n8.x4.shared.b16 {%0,%1,%2,%3}, [%4];"
                 : "=r"(r[0]), "=r"(r[1]), "=r"(r[2]), "=r"(r[3]) : "r"(addr));
}
__device__ __forceinline__ void mma16816(float (&d)[4], const uint32_t (&a)[4],
                                         const uint32_t* b) {
    asm volatile(
        "mma.sync.aligned.m16n8k16.row.col.f32.bf16.bf16.f32 "
        "{%0,%1,%2,%3}, {%4,%5,%6,%7}, {%8,%9}, {%0,%1,%2,%3};"
        : "+f"(d[0]), "+f"(d[1]), "+f"(d[2]), "+f"(d[3])
        : "r"(a[0]), "r"(a[1]), "r"(a[2]), "r"(a[3]), "r"(b[0]), "r"(b[1]));
}

// ---------------------------------------------------------------------------
// bf16x3 tensor-core GEMM via mma.sync:
//   C[M,N] = A[M,K] @ B[K,N] (+bias), EPI: 0 store, 1 gelu, 2 accumulate.
//   CTA tile 128x128, BK=64. 8 warps = 4(m) x 2(n), each 32m x 64n.
//   smem: sAh/sAl [128][64] bf16 SW128, sBh/sBl [128 n][64 k] bf16 SW128.
// ---------------------------------------------------------------------------
#define MMA_SMEM_BYTES 65536

template <int EPI>
__global__ void __launch_bounds__(256, 2) gemm_mma(
    const float* __restrict__ A, int lda,
    const float* __restrict__ B, int ldb,
    const float* __restrict__ bias,
    float* __restrict__ C, int ldc,
    int K) {

    extern __shared__ char smem[];
    const uint32_t sAh = smem_u32(smem);
    const uint32_t sAl = sAh + 16384;
    const uint32_t sBh = sAh + 32768;
    const uint32_t sBl = sAh + 49152;

    const int tid  = threadIdx.x;
    const int lane = tid & 31;
    const int wid  = tid >> 5;
    const int wm   = wid & 3;     // 0..3 -> m offset wm*32
    const int wn   = wid >> 2;    // 0..1 -> n offset wn*64

    const int row0 = blockIdx.y * 128;
    const int n0   = blockIdx.x * 128;

    float acc[2][8][4];
#pragma unroll
    for (int i = 0; i < 2; i++)
#pragma unroll
        for (int j = 0; j < 8; j++)
#pragma unroll
            for (int e = 0; e < 4; e++) acc[i][j][e] = 0.f;

    // staging index precomputes
    const int ar = (tid >> 4);           // unused pattern below uses idx
    (void)ar;

    for (int k0 = 0; k0 < K; k0 += 64) {
        // ---- stage A tile: 128 rows x 64 k fp32 -> bf16 hi/lo SW128 ----
        {
            const float* Ab = A + (size_t)row0 * lda + k0;
#pragma unroll
            for (int i = 0; i < 8; i++) {
                int idx = tid + i * 256;
                int r  = idx >> 4;        // 0..127
                int kq = idx & 15;        // k quad (4 floats)
                float4 v = *(const float4*)(Ab + (size_t)r * lda + (kq << 2));
                uint32_t l0, l1;
                uint32_t h0 = pack2(v.x, v.y, l0);
                uint32_t h1 = pack2(v.z, v.w, l1);
                uint32_t off = swz((uint32_t)(r * 128 + kq * 8));
                *(uint2*)(smem + off)         = make_uint2(h0, h1);
                *(uint2*)(smem + 16384 + off) = make_uint2(l0, l1);
            }
        }
        // ---- stage B tile transposed: B[k0..+63][n0..+127] -> smem[n][k] ----
        {
#pragma unroll
            for (int t = 0; t < 2; t++) {
                int bb = tid + t * 256;   // 0..511
                int nb = bb & 31;         // n quad
                int kb = bb >> 5;         // k quad 0..15
                const float* Bb = B + (size_t)(k0 + kb * 4) * ldb + n0 + nb * 4;
                float4 w0 = *(const float4*)(Bb);
                float4 w1 = *(const float4*)(Bb + ldb);
                float4 w2 = *(const float4*)(Bb + 2 * (size_t)ldb);
                float4 w3 = *(const float4*)(Bb + 3 * (size_t)ldb);
                const float* r0 = (const float*)&w0;
                const float* r1 = (const float*)&w1;
                const float* r2 = (const float*)&w2;
                const float* r3 = (const float*)&w3;
#pragma unroll
                for (int e = 0; e < 4; e++) {
                    uint32_t l0, l1;
                    uint32_t h0 = pack2(r0[e], r1[e], l0);
                    uint32_t h1 = pack2(r2[e], r3[e], l1);
                    uint32_t off = swz((uint32_t)((nb * 4 + e) * 128 + kb * 8));
                    *(uint2*)(smem + 32768 + off) = make_uint2(h0, h1);
                    *(uint2*)(smem + 49152 + off) = make_uint2(l0, l1);
                }
            }
        }
        __syncthreads();

        // ---- compute: 4 x k16 steps ----
#pragma unroll
        for (int ks = 0; ks < 4; ks++) {
            const int kk = ks * 16;
            // A fragments (hi and lo) for both m16 tiles
            uint32_t ah[2][4], al[2][4];
            {
                const uint32_t arow = (uint32_t)(wm * 32 + (lane & 15));
                const uint32_t acol = (uint32_t)(kk + (lane >> 4) * 8);
#pragma unroll
                for (int mi = 0; mi < 2; mi++) {
                    uint32_t off = swz((arow + mi * 16) * 128 + acol * 2);
                    ldsm4(ah[mi], sAh + off);
                    ldsm4(al[mi], sAl + off);
                }
            }
            const uint32_t brow = (uint32_t)(wn * 64 + ((lane >> 4) & 1) * 8 + (lane & 7));
            const uint32_t bcol = (uint32_t)(kk + ((lane >> 3) & 1) * 8);
#pragma unroll
            for (int ng = 0; ng < 4; ng++) {
                uint32_t bh[4], bl[4];
                uint32_t off = swz((brow + ng * 16) * 128 + bcol * 2);
                ldsm4(bh, sBh + off);
                ldsm4(bl, sBl + off);
#pragma unroll
                for (int mi = 0; mi < 2; mi++) {
#pragma unroll
                    for (int half = 0; half < 2; half++) {
                        const int nt = ng * 2 + half;
                        mma16816(acc[mi][nt], ah[mi], bh + half * 2);
                        mma16816(acc[mi][nt], ah[mi], bl + half * 2);
                        mma16816(acc[mi][nt], al[mi], bh + half * 2);
                    }
                }
            }
        }
        __syncthreads();
    }

    // ---- epilogue ----
    const int g = lane >> 2;
    const int t = lane & 3;
#pragma unroll
    for (int mi = 0; mi < 2; mi++) {
        const int r = row0 + wm * 32 + mi * 16 + g;
#pragma unroll
        for (int nt = 0; nt < 8; nt++) {
            const int col = n0 + wn * 64 + nt * 8 + 2 * t;
            float2 v0 = make_float2(acc[mi][nt][0], acc[mi][nt][1]);
            float2 v1 = make_float2(acc[mi][nt][2], acc[mi][nt][3]);
            if (bias) {
                float2 bv = *(const float2*)(bias + col);
                v0.x += bv.x; v0.y += bv.y;
                v1.x += bv.x; v1.y += bv.y;
            }
            if (EPI == 1) {
                v0.x = gelu_f(v0.x); v0.y = gelu_f(v0.y);
                v1.x = gelu_f(v1.x); v1.y = gelu_f(v1.y);
            }
            float* p0 = C + (size_t)r * ldc + col;
            float* p1 = C + (size_t)(r + 8) * ldc + col;
            if (EPI == 2) {
                float2 o0 = *(const float2*)p0;
                float2 o1 = *(const float2*)p1;
                v0.x += o0.x; v0.y += o0.y;
                v1.x += o1.x; v1.y += o1.y;
            }
            *(float2*)p0 = v0;
            *(float2*)p1 = v1;
        }
    }
}

// ---------------------------------------------------------------------------
// Embedding gather
// ---------------------------------------------------------------------------
__global__ void embed_kernel(const int* __restrict__ x,
                             const float* __restrict__ embed,
                             float* __restrict__ h) {
    int s = blockIdx.y;
    int c = blockIdx.x * 256 + threadIdx.x;
    h[(size_t)s * H_ + c] = embed[(size_t)x[s] * H_ + c];
}

// ---------------------------------------------------------------------------
// LayerNorm (one block per row)
// ---------------------------------------------------------------------------
__global__ void ln_kernel(const float* __restrict__ in,
                          const float* __restrict__ g,
                          const float* __restrict__ b,
                          float* __restrict__ out) {
    const int s = blockIdx.x;
    const int tid = threadIdx.x;
    const float* row = in + (size_t)s * H_;
    __shared__ float red[256];

    float v[8];
    float lsum = 0.f;
#pragma unroll
    for (int i = 0; i < 8; i++) { v[i] = row[tid + i * 256]; lsum += v[i]; }
    red[tid] = lsum; __syncthreads();
    for (int o = 128; o > 0; o >>= 1) {
        if (tid < o) red[tid] += red[tid + o];
        __syncthreads();
    }
    const float mean = red[0] * (1.f / H_);
    __syncthreads();

    float lvar = 0.f;
#pragma unroll
    for (int i = 0; i < 8; i++) { float d = v[i] - mean; lvar += d * d; }
    red[tid] = lvar; __syncthreads();
    for (int o = 128; o > 0; o >>= 1) {
        if (tid < o) red[tid] += red[tid + o];
        __syncthreads();
    }
    const float rstd = rsqrtf(red[0] * (1.f / H_) + EPS_);

#pragma unroll
    for (int i = 0; i < 8; i++) {
        int c = tid + i * 256;
        out[(size_t)s * H_ + c] = (v[i] - mean) * rstd * g[c] + b[c];
    }
}

// ---------------------------------------------------------------------------
// Rotary (in-place on qkv)
// ---------------------------------------------------------------------------
__global__ void rotary_kernel(float* __restrict__ qkv) {
    int idx = blockIdx.x * 256 + threadIdx.x;
    int i = idx & 15;
    int n = (idx >> 4) & 15;
    int s = idx >> 8;
    float inv = expf(-(float)i * 0.575646273248511f);
    float ang = (float)s * inv;
    float sn, cs;
    sincosf(ang, &sn, &cs);
    float* p = qkv + (size_t)s * (3 * H_) + n * (3 * HD_);
    float a = p[i], c2 = p[i + 16];
    p[i]      = a * cs - c2 * sn;
    p[i + 16] = c2 * cs + a * sn;
    float* pk = p + HD_;
    a = pk[i]; c2 = pk[i + 16];
    pk[i]      = a * cs - c2 * sn;
    pk[i + 16] = c2 * cs + a * sn;
}

// ---------------------------------------------------------------------------
// Causal softmax (one block per (q, head)); zeroes k>q.
// ---------------------------------------------------------------------------
__global__ void softmax_kernel(float* __restrict__ scores) {
    const int q = blockIdx.x;
    const int n = blockIdx.y;
    float* row = scores + ((size_t)n * S_ + q) * (size_t)S_;
    const int len = q + 1;
    const int tid = threadIdx.x;
    __shared__ float red[256];

    float mx = -3.4e38f;
    for (int i = tid; i < len; i += 256) mx = fmaxf(mx, row[i]);
    red[tid] = mx; __syncthreads();
    for (int o = 128; o > 0; o >>= 1) {
        if (tid < o) red[tid] = fmaxf(red[tid], red[tid + o]);
        __syncthreads();
    }
    mx = red[0]; __syncthreads();

    float sum = 0.f;
    for (int i = tid; i < len; i += 256) {
        float e = expf(row[i] - mx);
        row[i] = e;
        sum += e;
    }
    red[tid] = sum; __syncthreads();
    for (int o = 128; o > 0; o >>= 1) {
        if (tid < o) red[tid] += red[tid + o];
        __syncthreads();
    }
    const float inv = 1.f / red[0];
    for (int i = tid; i < len; i += 256) row[i] *= inv;
    for (int i = len + tid; i < S_; i += 256) row[i] = 0.f;
}

// ---------------------------------------------------------------------------
// fp32 SIMT GEMM (attention scores/ctx)
// ---------------------------------------------------------------------------
template <bool TRANSB, int EPI, bool CAUSAL>
__global__ void __launch_bounds__(256, 2) gemm128(
    const float* __restrict__ A, int lda, long long sA,
    const float* __restrict__ B, int ldb, long long sB,
    const float* __restrict__ bias,
    float* __restrict__ C, int ldc, long long sC,
    int K, float alpha) {

    A += (size_t)blockIdx.z * sA;
    B += (size_t)blockIdx.z * sB;
    C += (size_t)blockIdx.z * sC;

    const int row0 = blockIdx.y * 128;
    const int col0 = blockIdx.x * 128;
    if (CAUSAL && col0 > row0 + 127) return;

    __shared__ float As[8][128];
    __shared__ float Bs[8][128];

    const int tid = threadIdx.x;
    const int tx = tid & 15;
    const int ty = tid >> 4;

    float acc[8][8];
#pragma unroll
    for (int i = 0; i < 8; i++)
#pragma unroll
        for (int j = 0; j < 8; j++) acc[i][j] = 0.f;

    const int lr = tid >> 1;
    const int lk = (tid & 1) * 4;
    const int bk = tid >> 5;
    const int bc = (tid & 31) * 4;

    const float* Aptr = A + (size_t)(row0 + lr) * lda + lk;
    const float* Bptr = TRANSB ? (B + (size_t)(col0 + lr) * ldb + lk)
                               : (B + (size_t)bk * ldb + col0 + bc);

    for (int k0 = 0; k0 < K; k0 += 8) {
        float4 av = *(const float4*)(Aptr + k0);
        As[lk + 0][lr] = av.x;
        As[lk + 1][lr] = av.y;
        As[lk + 2][lr] = av.z;
        As[lk + 3][lr] = av.w;
        if (TRANSB) {
            float4 bv = *(const float4*)(Bptr + k0);
            Bs[lk + 0][lr] = bv.x;
            Bs[lk + 1][lr] = bv.y;
            Bs[lk + 2][lr] = bv.z;
            Bs[lk + 3][lr] = bv.w;
        } else {
            float4 bv = *(const float4*)(Bptr + (size_t)k0 * ldb);
            *(float4*)&Bs[bk][bc] = bv;
        }
        __syncthreads();

#pragma unroll
        for (int kk = 0; kk < 8; kk++) {
            float a[8], b[8];
            *(float4*)(a)     = *(const float4*)&As[kk][ty * 8];
            *(float4*)(a + 4) = *(const float4*)&As[kk][ty * 8 + 4];
            *(float4*)(b)     = *(const float4*)&Bs[kk][tx * 8];
            *(float4*)(b + 4) = *(const float4*)&Bs[kk][tx * 8 + 4];
#pragma unroll
            for (int i = 0; i < 8; i++)
#pragma unroll
                for (int j = 0; j < 8; j++)
                    acc[i][j] = fmaf(a[i], b[j], acc[i][j]);
        }
        __syncthreads();
    }

#pragma unroll
    for (int i = 0; i < 8; i++) {
        const int r = row0 + ty * 8 + i;
        float* crow = C + (size_t)r * ldc + col0;
#pragma unroll
        for (int j = 0; j < 8; j++) {
            const int c = tx * 8 + j;
            float val = acc[i][j] * alpha;
            if (bias) val += bias[col0 + c];
            if (EPI == 1) val = gelu_f(val);
            if (EPI == 2) crow[c] += val;
            else          crow[c] = val;
        }
    }
}

// ---------------------------------------------------------------------------
// Launcher
// ---------------------------------------------------------------------------
extern "C" void kernel_launch(void* const* d_in, const int* in_sizes, int n_in,
                              void* d_out, int out_size) {
    const int*   x        = (const int*)  d_in[0];
    const float* embed    = (const float*)d_in[1];
    const float* ln1_g    = (const float*)d_in[2];
    const float* ln1_b    = (const float*)d_in[3];
    const float* ln2_g    = (const float*)d_in[4];
    const float* ln2_b    = (const float*)d_in[5];
    const float* qkv_w    = (const float*)d_in[6];
    const float* qkv_b    = (const float*)d_in[7];
    const float* dense_w  = (const float*)d_in[8];
    const float* dense_b  = (const float*)d_in[9];
    const float* fc1_w    = (const float*)d_in[10];
    const float* fc1_b    = (const float*)d_in[11];
    const float* fc2_w    = (const float*)d_in[12];
    const float* fc2_b    = (const float*)d_in[13];
    const float* fln_g    = (const float*)d_in[14];
    const float* fln_b    = (const float*)d_in[15];
    const float* logits_w = (const float*)d_in[16];
    float* out = (float*)d_out;

    float *h, *ln1v, *ln2v, *qkv, *ctx, *fc1, *scores;
    cudaGetSymbolAddress((void**)&h,      g_h);
    cudaGetSymbolAddress((void**)&ln1v,   g_ln1);
    cudaGetSymbolAddress((void**)&ln2v,   g_ln2);
    cudaGetSymbolAddress((void**)&qkv,    g_qkv);
    cudaGetSymbolAddress((void**)&ctx,    g_ctx);
    cudaGetSymbolAddress((void**)&fc1,    g_fc1);
    cudaGetSymbolAddress((void**)&scores, g_scores);

    cudaFuncSetAttribute(gemm_mma<0>, cudaFuncAttributeMaxDynamicSharedMemorySize, MMA_SMEM_BYTES);
    cudaFuncSetAttribute(gemm_mma<1>, cudaFuncAttributeMaxDynamicSharedMemorySize, MMA_SMEM_BYTES);
    cudaFuncSetAttribute(gemm_mma<2>, cudaFuncAttributeMaxDynamicSharedMemorySize, MMA_SMEM_BYTES);

    const float inv_sqrt_hd = 0.08838834764831845f;  // 1/sqrt(128)

    embed_kernel<<<dim3(H_ / 256, S_), 256>>>(x, embed, h);

    for (int l = 0; l < L_; l++) {
        ln_kernel<<<S_, 256>>>(h, ln1_g + (size_t)l * H_, ln1_b + (size_t)l * H_, ln1v);
        ln_kernel<<<S_, 256>>>(h, ln2_g + (size_t)l * H_, ln2_b + (size_t)l * H_, ln2v);

        // qkv = ln1 @ qkv_w + qkv_b   [2048 x 6144]
        gemm_mma<0><<<dim3(3 * H_ / 128, S_ / 128), 256, MMA_SMEM_BYTES>>>(
            ln1v, H_, qkv_w + (size_t)l * H_ * 3 * H_, 3 * H_,
            qkv_b + (size_t)l * 3 * H_, qkv, 3 * H_, H_);

        rotary_kernel<<<(S_ * NH_ * 16) / 256, 256>>>(qkv);

        // scores = q @ k^T / sqrt(HD)  (fp32, causal skip)
        gemm128<true, 0, true><<<dim3(S_ / 128, S_ / 128, NH_), 256>>>(
            qkv, 3 * H_, 3 * HD_,
            qkv + HD_, 3 * H_, 3 * HD_,
            nullptr,
            scores, S_, (long long)S_ * S_, HD_, inv_sqrt_hd);

        softmax_kernel<<<dim3(S_, NH_), 256>>>(scores);

        // ctx = probs @ v  (fp32)
        gemm128<false, 0, false><<<dim3(HD_ / 128, S_ / 128, NH_), 256>>>(
            scores, S_, (long long)S_ * S_,
            qkv + 2 * HD_, 3 * H_, 3 * HD_,
            nullptr,
            ctx, H_, HD_, S_, 1.f);

        // h += ctx @ dense_w + dense_b
        gemm_mma<2><<<dim3(H_ / 128, S_ / 128), 256, MMA_SMEM_BYTES>>>(
            ctx, H_, dense_w + (size_t)l * H_ * H_, H_,
            dense_b + (size_t)l * H_, h, H_, H_);

        // fc1 = gelu(ln2 @ fc1_w + fc1_b)
        gemm_mma<1><<<dim3(FF_ / 128, S_ / 128), 256, MMA_SMEM_BYTES>>>(
            ln2v, H_, fc1_w + (size_t)l * H_ * FF_, FF_,
            fc1_b + (size_t)l * FF_, fc1, FF_, H_);

        // h += fc1 @ fc2_w + fc2_b
        gemm_mma<2><<<dim3(H_ / 128, S_ / 128), 256, MMA_SMEM_BYTES>>>(
            fc1, FF_, fc2_w + (size_t)l * FF_ * H_, H_,
            fc2_b + (size_t)l * H_, h, H_, FF_);
    }

    // Final LN + logits GEMM
    ln_kernel<<<S_, 256>>>(h, fln_g, fln_b, ln1v);
    gemm_mma<0><<<dim3(V_ / 128, S_ / 128), 256, MMA_SMEM_BYTES>>>(
        ln1v, H_, logits_w, V_, nullptr, out, V_, H_);
}

// round 4
// speedup vs baseline: 2.7254x; 1.3672x over previous
#include <cuda_runtime.h>
#include <cuda_bf16.h>
#include <math.h>
#include <stdint.h>

// Problem constants
#define S_    2048
#define H_    2048
#define NH_   16
#define HD_   128
#define ROT_  32
#define FF_   8192
#define L_    2
#define V_    32000
#define EPS_  1e-5f

// ---------------------------------------------------------------------------
// Scratch (static device globals)
// ---------------------------------------------------------------------------
__device__ float g_h  [(size_t)S_ * H_];
__device__ float g_qkv[(size_t)S_ * 3 * H_];
__device__ float g_ctx[(size_t)S_ * H_];
__device__ float g_scores[(size_t)NH_ * S_ * S_];

// bf16 hi/lo activation buffers
__device__ __nv_bfloat16 g_a1h[(size_t)S_ * H_];
__device__ __nv_bfloat16 g_a1l[(size_t)S_ * H_];
__device__ __nv_bfloat16 g_a2h[(size_t)S_ * H_];
__device__ __nv_bfloat16 g_a2l[(size_t)S_ * H_];
__device__ __nv_bfloat16 g_fh [(size_t)S_ * FF_];
__device__ __nv_bfloat16 g_fl [(size_t)S_ * FF_];

// transposed/split weight scratch (sized for largest: logits 32000x2048)
__device__ __nv_bfloat16 g_wth[(size_t)V_ * H_];
__device__ __nv_bfloat16 g_wtl[(size_t)V_ * H_];

// ---------------------------------------------------------------------------
// Helpers
// ---------------------------------------------------------------------------
__device__ __forceinline__ uint32_t smem_u32(const void* p) {
    uint32_t a;
    asm("{ .reg .u64 t; cvta.to.shared.u64 t, %1; cvt.u32.u64 %0, t; }"
        : "=r"(a) : "l"(p));
    return a;
}
__device__ __forceinline__ uint32_t swz(uint32_t off) {
    return off ^ ((off >> 3) & 0x70);
}
__device__ __forceinline__ float gelu_f(float x) {
    float t = tanhf(0.79788456f * x * (1.f + 0.044715f * x * x));
    return 0.5f * x * (1.f + t);
}
__device__ __forceinline__ uint32_t pack2(float x, float y, uint32_t& lo) {
    __nv_bfloat16 hx = __float2bfloat16_rn(x);
    __nv_bfloat16 hy = __float2bfloat16_rn(y);
    __nv_bfloat16 lx = __float2bfloat16_rn(x - __bfloat162float(hx));
    __nv_bfloat16 ly = __float2bfloat16_rn(y - __bfloat162float(hy));
    lo = (uint32_t)__bfloat16_as_ushort(lx) | ((uint32_t)__bfloat16_as_ushort(ly) << 16);
    return (uint32_t)__bfloat16_as_ushort(hx) | ((uint32_t)__bfloat16_as_ushort(hy) << 16);
}
__device__ __forceinline__ void split1(float x, __nv_bfloat16& h, __nv_bfloat16& l) {
    h = __float2bfloat16_rn(x);
    l = __float2bfloat16_rn(x - __bfloat162float(h));
}
__device__ __forceinline__ void ldsm4(uint32_t (&r)[4], uint32_t addr) {
    asm volatile("ldmatrix.sync.aligned.m8n8.x4.shared.b16 {%0,%1,%2,%3}, [%4];"
                 : "=r"(r[0]), "=r"(r[1]), "=r"(r[2]), "=r"(r[3]) : "r"(addr));
}
__device__ __forceinline__ void mma16816(float (&d)[4], const uint32_t (&a)[4],
                                         const uint32_t* b) {
    asm volatile(
        "mma.sync.aligned.m16n8k16.row.col.f32.bf16.bf16.f32 "
        "{%0,%1,%2,%3}, {%4,%5,%6,%7}, {%8,%9}, {%0,%1,%2,%3};"
        : "+f"(d[0]), "+f"(d[1]), "+f"(d[2]), "+f"(d[3])
        : "r"(a[0]), "r"(a[1]), "r"(a[2]), "r"(a[3]), "r"(b[0]), "r"(b[1]));
}
__device__ __forceinline__ void cpa16(uint32_t s, const void* g) {
    asm volatile("cp.async.cg.shared.global [%0], [%1], 16;" :: "r"(s), "l"(g));
}

// ---------------------------------------------------------------------------
// Weight transpose + split: W[K][N] fp32 -> WTh/WTl[N][K] bf16
// ---------------------------------------------------------------------------
__global__ void wsplit_kernel(const float* __restrict__ W, int Kd, int N,
                              __nv_bfloat16* __restrict__ WTh,
                              __nv_bfloat16* __restrict__ WTl) {
    __shared__ float s[32][33];
    const int k0 = blockIdx.x * 32;
    const int n0 = blockIdx.y * 32;
    const int tid = threadIdx.x;
    const int r  = tid >> 3;
    const int c4 = (tid & 7) * 4;

    float4 v = *(const float4*)(W + (size_t)(k0 + r) * N + n0 + c4);
    s[r][c4 + 0] = v.x; s[r][c4 + 1] = v.y;
    s[r][c4 + 2] = v.z; s[r][c4 + 3] = v.w;
    __syncthreads();

    float x0 = s[c4 + 0][r], x1 = s[c4 + 1][r];
    float x2 = s[c4 + 2][r], x3 = s[c4 + 3][r];
    uint32_t l0, l1;
    uint32_t h0 = pack2(x0, x1, l0);
    uint32_t h1 = pack2(x2, x3, l1);
    size_t o = (size_t)(n0 + r) * Kd + k0 + c4;
    *(uint2*)(WTh + o) = make_uint2(h0, h1);
    *(uint2*)(WTl + o) = make_uint2(l0, l1);
}

// ---------------------------------------------------------------------------
// Elementwise fp32 -> bf16 hi/lo split (for ctx)
// ---------------------------------------------------------------------------
__global__ void split_kernel(const float* __restrict__ in,
                             __nv_bfloat16* __restrict__ oh,
                             __nv_bfloat16* __restrict__ ol) {
    int i = (blockIdx.x * 256 + threadIdx.x) * 4;
    float4 v = *(const float4*)(in + i);
    uint32_t l0, l1;
    uint32_t h0 = pack2(v.x, v.y, l0);
    uint32_t h1 = pack2(v.z, v.w, l1);
    *(uint2*)(oh + i) = make_uint2(h0, h1);
    *(uint2*)(ol + i) = make_uint2(l0, l1);
}

// ---------------------------------------------------------------------------
// LayerNorm -> bf16 hi/lo split output
// ---------------------------------------------------------------------------
__global__ void ln_split_kernel(const float* __restrict__ in,
                                const float* __restrict__ g,
                                const float* __restrict__ b,
                                __nv_bfloat16* __restrict__ oh,
                                __nv_bfloat16* __restrict__ ol) {
    const int s = blockIdx.x;
    const int tid = threadIdx.x;
    const float* row = in + (size_t)s * H_;
    __shared__ float red[256];

    float v[8];
    float lsum = 0.f;
#pragma unroll
    for (int i = 0; i < 8; i++) { v[i] = row[tid + i * 256]; lsum += v[i]; }
    red[tid] = lsum; __syncthreads();
    for (int o = 128; o > 0; o >>= 1) {
        if (tid < o) red[tid] += red[tid + o];
        __syncthreads();
    }
    const float mean = red[0] * (1.f / H_);
    __syncthreads();

    float lvar = 0.f;
#pragma unroll
    for (int i = 0; i < 8; i++) { float d = v[i] - mean; lvar += d * d; }
    red[tid] = lvar; __syncthreads();
    for (int o = 128; o > 0; o >>= 1) {
        if (tid < o) red[tid] += red[tid + o];
        __syncthreads();
    }
    const float rstd = rsqrtf(red[0] * (1.f / H_) + EPS_);

#pragma unroll
    for (int i = 0; i < 8; i++) {
        int c = tid + i * 256;
        float val = (v[i] - mean) * rstd * g[c] + b[c];
        __nv_bfloat16 hh, ll;
        split1(val, hh, ll);
        oh[(size_t)s * H_ + c] = hh;
        ol[(size_t)s * H_ + c] = ll;
    }
}

// ---------------------------------------------------------------------------
// bf16x3 tensor-core GEMM, cp.async double-buffered.
//   A: Ah/Al [M][K] bf16 row-major, B: Bh/Bl [N][K] bf16 row-major.
//   CTA tile 128x128 (m=blockIdx.x, n=blockIdx.y), BK=64.
//   EPI: 0 = store fp32 C (+bias), 1 = gelu -> split bf16 Ch/Cl (+bias),
//        2 = accumulate into fp32 C (+bias).
// ---------------------------------------------------------------------------
#define GBF_SMEM (2 * 65536)

template <int EPI>
__global__ void __launch_bounds__(256, 1) gemm_bf(
    const __nv_bfloat16* __restrict__ Ah, const __nv_bfloat16* __restrict__ Al,
    const __nv_bfloat16* __restrict__ Bh, const __nv_bfloat16* __restrict__ Bl,
    const float* __restrict__ bias,
    float* __restrict__ C,
    __nv_bfloat16* __restrict__ Ch, __nv_bfloat16* __restrict__ Cl,
    int ldc, int K) {

    extern __shared__ char smem[];
    const uint32_t sb = smem_u32(smem);
    const int tid  = threadIdx.x;
    const int lane = tid & 31;
    const int wid  = tid >> 5;
    const int wm   = wid & 3;
    const int wn   = wid >> 2;
    const int row0 = blockIdx.x * 128;
    const int n0   = blockIdx.y * 128;

    float acc[2][8][4];
#pragma unroll
    for (int i = 0; i < 2; i++)
#pragma unroll
        for (int j = 0; j < 8; j++)
#pragma unroll
            for (int e = 0; e < 4; e++) acc[i][j][e] = 0.f;

    // per-thread staging coordinates (4 x 16B per tile, 4 tiles)
    const int nch = K >> 6;

    for (int c = 0; c <= nch; c++) {
        if (c < nch) {
            const uint32_t bufo = (uint32_t)(c & 1) * 65536;
            const int k0 = c << 6;
#pragma unroll
            for (int i = 0; i < 4; i++) {
                int idx = tid + i * 256;
                int r  = idx >> 3;
                int cc = (idx & 7) * 8;       // element offset in k
                uint32_t soff = swz((uint32_t)(r * 128 + cc * 2));
                size_t goA = (size_t)(row0 + r) * K + k0 + cc;
                size_t goB = (size_t)(n0 + r) * K + k0 + cc;
                cpa16(sb + bufo + soff,         Ah + goA);
                cpa16(sb + bufo + 16384 + soff, Al + goA);
                cpa16(sb + bufo + 32768 + soff, Bh + goB);
                cpa16(sb + bufo + 49152 + soff, Bl + goB);
            }
            asm volatile("cp.async.commit_group;" ::: "memory");
        }
        if (c >= 1) {
            if (c < nch) asm volatile("cp.async.wait_group 1;" ::: "memory");
            else         asm volatile("cp.async.wait_group 0;" ::: "memory");
            __syncthreads();

            const uint32_t bufo = (uint32_t)((c - 1) & 1) * 65536;
            const uint32_t sAh = sb + bufo;
            const uint32_t sAl = sAh + 16384;
            const uint32_t sBh = sAh + 32768;
            const uint32_t sBl = sAh + 49152;

#pragma unroll
            for (int ks = 0; ks < 4; ks++) {
                const int kk = ks * 16;
                uint32_t ah[2][4], al[2][4];
                {
                    const uint32_t arow = (uint32_t)(wm * 32 + (lane & 15));
                    const uint32_t acol = (uint32_t)(kk + (lane >> 4) * 8);
#pragma unroll
                    for (int mi = 0; mi < 2; mi++) {
                        uint32_t off = swz((arow + mi * 16) * 128 + acol * 2);
                        ldsm4(ah[mi], sAh + off);
                        ldsm4(al[mi], sAl + off);
                    }
                }
                const uint32_t brow = (uint32_t)(wn * 64 + ((lane >> 4) & 1) * 8 + (lane & 7));
                const uint32_t bcol = (uint32_t)(kk + ((lane >> 3) & 1) * 8);
#pragma unroll
                for (int ng = 0; ng < 4; ng++) {
                    uint32_t bh[4], bl[4];
                    uint32_t off = swz((brow + ng * 16) * 128 + bcol * 2);
                    ldsm4(bh, sBh + off);
                    ldsm4(bl, sBl + off);
#pragma unroll
                    for (int mi = 0; mi < 2; mi++) {
#pragma unroll
                        for (int half = 0; half < 2; half++) {
                            const int nt = ng * 2 + half;
                            mma16816(acc[mi][nt], ah[mi], bh + half * 2);
                            mma16816(acc[mi][nt], ah[mi], bl + half * 2);
                            mma16816(acc[mi][nt], al[mi], bh + half * 2);
                        }
                    }
                }
            }
            __syncthreads();
        }
    }

    // ---- epilogue ----
    const int g = lane >> 2;
    const int t = lane & 3;
#pragma unroll
    for (int mi = 0; mi < 2; mi++) {
        const int r = row0 + wm * 32 + mi * 16 + g;
#pragma unroll
        for (int nt = 0; nt < 8; nt++) {
            const int col = n0 + wn * 64 + nt * 8 + 2 * t;
            float2 v0 = make_float2(acc[mi][nt][0], acc[mi][nt][1]);
            float2 v1 = make_float2(acc[mi][nt][2], acc[mi][nt][3]);
            if (bias) {
                float2 bv = *(const float2*)(bias + col);
                v0.x += bv.x; v0.y += bv.y;
                v1.x += bv.x; v1.y += bv.y;
            }
            if (EPI == 1) {
                v0.x = gelu_f(v0.x); v0.y = gelu_f(v0.y);
                v1.x = gelu_f(v1.x); v1.y = gelu_f(v1.y);
                uint32_t l0, l1;
                uint32_t h0 = pack2(v0.x, v0.y, l0);
                uint32_t h1 = pack2(v1.x, v1.y, l1);
                *(uint32_t*)(Ch + (size_t)r * ldc + col) = h0;
                *(uint32_t*)(Cl + (size_t)r * ldc + col) = l0;
                *(uint32_t*)(Ch + (size_t)(r + 8) * ldc + col) = h1;
                *(uint32_t*)(Cl + (size_t)(r + 8) * ldc + col) = l1;
            } else {
                float* p0 = C + (size_t)r * ldc + col;
                float* p1 = C + (size_t)(r + 8) * ldc + col;
                if (EPI == 2) {
                    float2 o0 = *(const float2*)p0;
                    float2 o1 = *(const float2*)p1;
                    v0.x += o0.x; v0.y += o0.y;
                    v1.x += o1.x; v1.y += o1.y;
                }
                *(float2*)p0 = v0;
                *(float2*)p1 = v1;
            }
        }
    }
}

// ---------------------------------------------------------------------------
// Embedding gather
// ---------------------------------------------------------------------------
__global__ void embed_kernel(const int* __restrict__ x,
                             const float* __restrict__ embed,
                             float* __restrict__ h) {
    int s = blockIdx.y;
    int c = blockIdx.x * 256 + threadIdx.x;
    h[(size_t)s * H_ + c] = embed[(size_t)x[s] * H_ + c];
}

// ---------------------------------------------------------------------------
// Rotary (in-place on qkv)
// ---------------------------------------------------------------------------
__global__ void rotary_kernel(float* __restrict__ qkv) {
    int idx = blockIdx.x * 256 + threadIdx.x;
    int i = idx & 15;
    int n = (idx >> 4) & 15;
    int s = idx >> 8;
    float inv = expf(-(float)i * 0.575646273248511f);
    float ang = (float)s * inv;
    float sn, cs;
    sincosf(ang, &sn, &cs);
    float* p = qkv + (size_t)s * (3 * H_) + n * (3 * HD_);
    float a = p[i], c2 = p[i + 16];
    p[i]      = a * cs - c2 * sn;
    p[i + 16] = c2 * cs + a * sn;
    float* pk = p + HD_;
    a = pk[i]; c2 = pk[i + 16];
    pk[i]      = a * cs - c2 * sn;
    pk[i + 16] = c2 * cs + a * sn;
}

// ---------------------------------------------------------------------------
// Causal softmax (one block per (q, head)); zeroes k>q.
// ---------------------------------------------------------------------------
__global__ void softmax_kernel(float* __restrict__ scores) {
    const int q = blockIdx.x;
    const int n = blockIdx.y;
    float* row = scores + ((size_t)n * S_ + q) * (size_t)S_;
    const int len = q + 1;
    const int tid = threadIdx.x;
    __shared__ float red[256];

    float mx = -3.4e38f;
    for (int i = tid; i < len; i += 256) mx = fmaxf(mx, row[i]);
    red[tid] = mx; __syncthreads();
    for (int o = 128; o > 0; o >>= 1) {
        if (tid < o) red[tid] = fmaxf(red[tid], red[tid + o]);
        __syncthreads();
    }
    mx = red[0]; __syncthreads();

    float sum = 0.f;
    for (int i = tid; i < len; i += 256) {
        float e = expf(row[i] - mx);
        row[i] = e;
        sum += e;
    }
    red[tid] = sum; __syncthreads();
    for (int o = 128; o > 0; o >>= 1) {
        if (tid < o) red[tid] += red[tid + o];
        __syncthreads();
    }
    const float inv = 1.f / red[0];
    for (int i = tid; i < len; i += 256) row[i] *= inv;
    for (int i = len + tid; i < S_; i += 256) row[i] = 0.f;
}

// ---------------------------------------------------------------------------
// fp32 SIMT GEMM (attention scores/ctx)
// ---------------------------------------------------------------------------
template <bool TRANSB, int EPI, bool CAUSAL>
__global__ void __launch_bounds__(256, 2) gemm128(
    const float* __restrict__ A, int lda, long long sA,
    const float* __restrict__ B, int ldb, long long sB,
    const float* __restrict__ bias,
    float* __restrict__ C, int ldc, long long sC,
    int K, float alpha) {

    A += (size_t)blockIdx.z * sA;
    B += (size_t)blockIdx.z * sB;
    C += (size_t)blockIdx.z * sC;

    const int row0 = blockIdx.y * 128;
    const int col0 = blockIdx.x * 128;
    if (CAUSAL && col0 > row0 + 127) return;

    __shared__ float As[8][128];
    __shared__ float Bs[8][128];

    const int tid = threadIdx.x;
    const int tx = tid & 15;
    const int ty = tid >> 4;

    float acc[8][8];
#pragma unroll
    for (int i = 0; i < 8; i++)
#pragma unroll
        for (int j = 0; j < 8; j++) acc[i][j] = 0.f;

    const int lr = tid >> 1;
    const int lk = (tid & 1) * 4;
    const int bk = tid >> 5;
    const int bc = (tid & 31) * 4;

    const float* Aptr = A + (size_t)(row0 + lr) * lda + lk;
    const float* Bptr = TRANSB ? (B + (size_t)(col0 + lr) * ldb + lk)
                               : (B + (size_t)bk * ldb + col0 + bc);

    for (int k0 = 0; k0 < K; k0 += 8) {
        float4 av = *(const float4*)(Aptr + k0);
        As[lk + 0][lr] = av.x;
        As[lk + 1][lr] = av.y;
        As[lk + 2][lr] = av.z;
        As[lk + 3][lr] = av.w;
        if (TRANSB) {
            float4 bv = *(const float4*)(Bptr + k0);
            Bs[lk + 0][lr] = bv.x;
            Bs[lk + 1][lr] = bv.y;
            Bs[lk + 2][lr] = bv.z;
            Bs[lk + 3][lr] = bv.w;
        } else {
            float4 bv = *(const float4*)(Bptr + (size_t)k0 * ldb);
            *(float4*)&Bs[bk][bc] = bv;
        }
        __syncthreads();

#pragma unroll
        for (int kk = 0; kk < 8; kk++) {
            float a[8], b[8];
            *(float4*)(a)     = *(const float4*)&As[kk][ty * 8];
            *(float4*)(a + 4) = *(const float4*)&As[kk][ty * 8 + 4];
            *(float4*)(b)     = *(const float4*)&Bs[kk][tx * 8];
            *(float4*)(b + 4) = *(const float4*)&Bs[kk][tx * 8 + 4];
#pragma unroll
            for (int i = 0; i < 8; i++)
#pragma unroll
                for (int j = 0; j < 8; j++)
                    acc[i][j] = fmaf(a[i], b[j], acc[i][j]);
        }
        __syncthreads();
    }

#pragma unroll
    for (int i = 0; i < 8; i++) {
        const int r = row0 + ty * 8 + i;
        float* crow = C + (size_t)r * ldc + col0;
#pragma unroll
        for (int j = 0; j < 8; j++) {
            const int c = tx * 8 + j;
            float val = acc[i][j] * alpha;
            if (bias) val += bias[col0 + c];
            if (EPI == 2) crow[c] += val;
            else          crow[c] = val;
        }
    }
}

// ---------------------------------------------------------------------------
// Launcher
// ---------------------------------------------------------------------------
extern "C" void kernel_launch(void* const* d_in, const int* in_sizes, int n_in,
                              void* d_out, int out_size) {
    const int*   x        = (const int*)  d_in[0];
    const float* embed    = (const float*)d_in[1];
    const float* ln1_g    = (const float*)d_in[2];
    const float* ln1_b    = (const float*)d_in[3];
    const float* ln2_g    = (const float*)d_in[4];
    const float* ln2_b    = (const float*)d_in[5];
    const float* qkv_w    = (const float*)d_in[6];
    const float* qkv_b    = (const float*)d_in[7];
    const float* dense_w  = (const float*)d_in[8];
    const float* dense_b  = (const float*)d_in[9];
    const float* fc1_w    = (const float*)d_in[10];
    const float* fc1_b    = (const float*)d_in[11];
    const float* fc2_w    = (const float*)d_in[12];
    const float* fc2_b    = (const float*)d_in[13];
    const float* fln_g    = (const float*)d_in[14];
    const float* fln_b    = (const float*)d_in[15];
    const float* logits_w = (const float*)d_in[16];
    float* out = (float*)d_out;

    float *h, *qkv, *ctx, *scores;
    __nv_bfloat16 *a1h, *a1l, *a2h, *a2l, *fh, *fl, *wth, *wtl;
    cudaGetSymbolAddress((void**)&h,      g_h);
    cudaGetSymbolAddress((void**)&qkv,    g_qkv);
    cudaGetSymbolAddress((void**)&ctx,    g_ctx);
    cudaGetSymbolAddress((void**)&scores, g_scores);
    cudaGetSymbolAddress((void**)&a1h,    g_a1h);
    cudaGetSymbolAddress((void**)&a1l,    g_a1l);
    cudaGetSymbolAddress((void**)&a2h,    g_a2h);
    cudaGetSymbolAddress((void**)&a2l,    g_a2l);
    cudaGetSymbolAddress((void**)&fh,     g_fh);
    cudaGetSymbolAddress((void**)&fl,     g_fl);
    cudaGetSymbolAddress((void**)&wth,    g_wth);
    cudaGetSymbolAddress((void**)&wtl,    g_wtl);

    cudaFuncSetAttribute(gemm_bf<0>, cudaFuncAttributeMaxDynamicSharedMemorySize, GBF_SMEM);
    cudaFuncSetAttribute(gemm_bf<1>, cudaFuncAttributeMaxDynamicSharedMemorySize, GBF_SMEM);
    cudaFuncSetAttribute(gemm_bf<2>, cudaFuncAttributeMaxDynamicSharedMemorySize, GBF_SMEM);

    const float inv_sqrt_hd = 0.08838834764831845f;  // 1/sqrt(128)

    embed_kernel<<<dim3(H_ / 256, S_), 256>>>(x, embed, h);

    for (int l = 0; l < L_; l++) {
        // ln1 -> a1 (split)
        ln_split_kernel<<<S_, 256>>>(h, ln1_g + (size_t)l * H_, ln1_b + (size_t)l * H_,
                                     a1h, a1l);

        // qkv = ln1 @ qkv_w + qkv_b
        wsplit_kernel<<<dim3(H_ / 32, 3 * H_ / 32), 256>>>(
            qkv_w + (size_t)l * H_ * 3 * H_, H_, 3 * H_, wth, wtl);
        gemm_bf<0><<<dim3(S_ / 128, 3 * H_ / 128), 256, GBF_SMEM>>>(
            a1h, a1l, wth, wtl, qkv_b + (size_t)l * 3 * H_,
            qkv, nullptr, nullptr, 3 * H_, H_);

        rotary_kernel<<<(S_ * NH_ * 16) / 256, 256>>>(qkv);

        // scores = q @ k^T / sqrt(HD)  (fp32, causal skip)
        gemm128<true, 0, true><<<dim3(S_ / 128, S_ / 128, NH_), 256>>>(
            qkv, 3 * H_, 3 * HD_,
            qkv + HD_, 3 * H_, 3 * HD_,
            nullptr,
            scores, S_, (long long)S_ * S_, HD_, inv_sqrt_hd);

        softmax_kernel<<<dim3(S_, NH_), 256>>>(scores);

        // ctx = probs @ v  (fp32)
        gemm128<false, 0, false><<<dim3(HD_ / 128, S_ / 128, NH_), 256>>>(
            scores, S_, (long long)S_ * S_,
            qkv + 2 * HD_, 3 * H_, 3 * HD_,
            nullptr,
            ctx, H_, HD_, S_, 1.f);

        // ln2 -> a2 (reads pre-update h; must precede residual adds)
        ln_split_kernel<<<S_, 256>>>(h, ln2_g + (size_t)l * H_, ln2_b + (size_t)l * H_,
                                     a2h, a2l);

        // ctx split -> a1 (a1 free after qkv gemm)
        split_kernel<<<(S_ * H_) / 1024, 256>>>(ctx, a1h, a1l);

        // h += ctx @ dense_w + dense_b
        wsplit_kernel<<<dim3(H_ / 32, H_ / 32), 256>>>(
            dense_w + (size_t)l * H_ * H_, H_, H_, wth, wtl);
        gemm_bf<2><<<dim3(S_ / 128, H_ / 128), 256, GBF_SMEM>>>(
            a1h, a1l, wth, wtl, dense_b + (size_t)l * H_,
            h, nullptr, nullptr, H_, H_);

        // fc1 = gelu(ln2 @ fc1_w + fc1_b) -> fh/fl (split)
        wsplit_kernel<<<dim3(H_ / 32, FF_ / 32), 256>>>(
            fc1_w + (size_t)l * H_ * FF_, H_, FF_, wth, wtl);
        gemm_bf<1><<<dim3(S_ / 128, FF_ / 128), 256, GBF_SMEM>>>(
            a2h, a2l, wth, wtl, fc1_b + (size_t)l * FF_,
            nullptr, fh, fl, FF_, H_);

        // h += fc1 @ fc2_w + fc2_b
        wsplit_kernel<<<dim3(FF_ / 32, H_ / 32), 256>>>(
            fc2_w + (size_t)l * FF_ * H_, FF_, H_, wth, wtl);
        gemm_bf<2><<<dim3(S_ / 128, H_ / 128), 256, GBF_SMEM>>>(
            fh, fl, wth, wtl, fc2_b + (size_t)l * H_,
            h, nullptr, nullptr, H_, FF_);
    }

    // Final LN + logits GEMM
    ln_split_kernel<<<S_, 256>>>(h, fln_g, fln_b, a1h, a1l);
    wsplit_kernel<<<dim3(H_ / 32, V_ / 32), 256>>>(logits_w, H_, V_, wth, wtl);
    gemm_bf<0><<<dim3(S_ / 128, V_ / 128), 256, GBF_SMEM>>>(
        a1h, a1l, wth, wtl, nullptr, out, nullptr, nullptr, V_, H_);
}

// round 5
// speedup vs baseline: 3.2639x; 1.1976x over previous
#include <cuda_runtime.h>
#include <cuda_bf16.h>
#include <math.h>
#include <stdint.h>

// Problem constants
#define S_    2048
#define H_    2048
#define NH_   16
#define HD_   128
#define ROT_  32
#define FF_   8192
#define L_    2
#define V_    32000
#define EPS_  1e-5f

typedef __nv_bfloat16 bf16;

// ---------------------------------------------------------------------------
// Scratch (static device globals)
// ---------------------------------------------------------------------------
__device__ float g_h  [(size_t)S_ * H_];
__device__ float g_qkv[(size_t)S_ * 3 * H_];
__device__ float g_ctx[(size_t)S_ * H_];
__device__ float g_scores[(size_t)NH_ * S_ * S_];

__device__ bf16 g_a1h[(size_t)S_ * H_];
__device__ bf16 g_a1l[(size_t)S_ * H_];
__device__ bf16 g_a2h[(size_t)S_ * H_];
__device__ bf16 g_a2l[(size_t)S_ * H_];
__device__ bf16 g_fh [(size_t)S_ * FF_];
__device__ bf16 g_fl [(size_t)S_ * FF_];

__device__ bf16 g_qh [(size_t)S_ * 3 * H_];
__device__ bf16 g_ql [(size_t)S_ * 3 * H_];
__device__ bf16 g_vth[(size_t)NH_ * HD_ * S_];
__device__ bf16 g_vtl[(size_t)NH_ * HD_ * S_];
__device__ bf16 g_ph [(size_t)NH_ * S_ * S_];
__device__ bf16 g_pl [(size_t)NH_ * S_ * S_];

// transposed/split weight scratch (sized for largest: logits 32000x2048)
__device__ bf16 g_wth[(size_t)V_ * H_];
__device__ bf16 g_wtl[(size_t)V_ * H_];

// ---------------------------------------------------------------------------
// Helpers
// ---------------------------------------------------------------------------
__device__ __forceinline__ uint32_t smem_u32(const void* p) {
    uint32_t a;
    asm("{ .reg .u64 t; cvta.to.shared.u64 t, %1; cvt.u32.u64 %0, t; }"
        : "=r"(a) : "l"(p));
    return a;
}
__device__ __forceinline__ uint32_t swz(uint32_t off) {
    return off ^ ((off >> 3) & 0x70);
}
__device__ __forceinline__ float gelu_f(float x) {
    float t = tanhf(0.79788456f * x * (1.f + 0.044715f * x * x));
    return 0.5f * x * (1.f + t);
}
__device__ __forceinline__ uint32_t pack2(float x, float y, uint32_t& lo) {
    bf16 hx = __float2bfloat16_rn(x);
    bf16 hy = __float2bfloat16_rn(y);
    bf16 lx = __float2bfloat16_rn(x - __bfloat162float(hx));
    bf16 ly = __float2bfloat16_rn(y - __bfloat162float(hy));
    lo = (uint32_t)__bfloat16_as_ushort(lx) | ((uint32_t)__bfloat16_as_ushort(ly) << 16);
    return (uint32_t)__bfloat16_as_ushort(hx) | ((uint32_t)__bfloat16_as_ushort(hy) << 16);
}
__device__ __forceinline__ void split1(float x, bf16& h, bf16& l) {
    h = __float2bfloat16_rn(x);
    l = __float2bfloat16_rn(x - __bfloat162float(h));
}
__device__ __forceinline__ void ldsm4(uint32_t (&r)[4], uint32_t addr) {
    asm volatile("ldmatrix.sync.aligned.m8n8.x4.shared.b16 {%0,%1,%2,%3}, [%4];"
                 : "=r"(r[0]), "=r"(r[1]), "=r"(r[2]), "=r"(r[3]) : "r"(addr));
}
__device__ __forceinline__ void mma16816(float (&d)[4], const uint32_t (&a)[4],
                                         const uint32_t* b) {
    asm volatile(
        "mma.sync.aligned.m16n8k16.row.col.f32.bf16.bf16.f32 "
        "{%0,%1,%2,%3}, {%4,%5,%6,%7}, {%8,%9}, {%0,%1,%2,%3};"
        : "+f"(d[0]), "+f"(d[1]), "+f"(d[2]), "+f"(d[3])
        : "r"(a[0]), "r"(a[1]), "r"(a[2]), "r"(a[3]), "r"(b[0]), "r"(b[1]));
}
__device__ __forceinline__ void cpa16(uint32_t s, const void* g) {
    asm volatile("cp.async.cg.shared.global [%0], [%1], 16;" :: "r"(s), "l"(g));
}

// ---------------------------------------------------------------------------
// Transpose + split: W[Kd rows][N cols] fp32 (ldw) -> WTh/WTl[N][Kd] bf16
// (z batching: per-z input offset zin elements, output offset zout)
// ---------------------------------------------------------------------------
__global__ void wsplit_kernel(const float* __restrict__ W, int ldw, int Kd, int N,
                              long long zin, long long zout,
                              bf16* __restrict__ WTh, bf16* __restrict__ WTl) {
    W   += (size_t)blockIdx.z * zin;
    WTh += (size_t)blockIdx.z * zout;
    WTl += (size_t)blockIdx.z * zout;

    __shared__ float s[32][33];
    const int k0 = blockIdx.x * 32;
    const int n0 = blockIdx.y * 32;
    const int tid = threadIdx.x;
    const int r  = tid >> 3;
    const int c4 = (tid & 7) * 4;

    float4 v = *(const float4*)(W + (size_t)(k0 + r) * ldw + n0 + c4);
    s[r][c4 + 0] = v.x; s[r][c4 + 1] = v.y;
    s[r][c4 + 2] = v.z; s[r][c4 + 3] = v.w;
    __syncthreads();

    float x0 = s[c4 + 0][r], x1 = s[c4 + 1][r];
    float x2 = s[c4 + 2][r], x3 = s[c4 + 3][r];
    uint32_t l0, l1;
    uint32_t h0 = pack2(x0, x1, l0);
    uint32_t h1 = pack2(x2, x3, l1);
    size_t o = (size_t)(n0 + r) * Kd + k0 + c4;
    *(uint2*)(WTh + o) = make_uint2(h0, h1);
    *(uint2*)(WTl + o) = make_uint2(l0, l1);
}

// ---------------------------------------------------------------------------
// Elementwise fp32 -> bf16 hi/lo split
// ---------------------------------------------------------------------------
__global__ void split_kernel(const float* __restrict__ in,
                             bf16* __restrict__ oh,
                             bf16* __restrict__ ol) {
    int i = (blockIdx.x * 256 + threadIdx.x) * 4;
    float4 v = *(const float4*)(in + i);
    uint32_t l0, l1;
    uint32_t h0 = pack2(v.x, v.y, l0);
    uint32_t h1 = pack2(v.z, v.w, l1);
    *(uint2*)(oh + i) = make_uint2(h0, h1);
    *(uint2*)(ol + i) = make_uint2(l0, l1);
}

// ---------------------------------------------------------------------------
// LayerNorm -> bf16 hi/lo split output
// ---------------------------------------------------------------------------
__global__ void ln_split_kernel(const float* __restrict__ in,
                                const float* __restrict__ g,
                                const float* __restrict__ b,
                                bf16* __restrict__ oh,
                                bf16* __restrict__ ol) {
    const int s = blockIdx.x;
    const int tid = threadIdx.x;
    const float* row = in + (size_t)s * H_;
    __shared__ float red[256];

    float v[8];
    float lsum = 0.f;
#pragma unroll
    for (int i = 0; i < 8; i++) { v[i] = row[tid + i * 256]; lsum += v[i]; }
    red[tid] = lsum; __syncthreads();
    for (int o = 128; o > 0; o >>= 1) {
        if (tid < o) red[tid] += red[tid + o];
        __syncthreads();
    }
    const float mean = red[0] * (1.f / H_);
    __syncthreads();

    float lvar = 0.f;
#pragma unroll
    for (int i = 0; i < 8; i++) { float d = v[i] - mean; lvar += d * d; }
    red[tid] = lvar; __syncthreads();
    for (int o = 128; o > 0; o >>= 1) {
        if (tid < o) red[tid] += red[tid + o];
        __syncthreads();
    }
    const float rstd = rsqrtf(red[0] * (1.f / H_) + EPS_);

#pragma unroll
    for (int i = 0; i < 8; i++) {
        int c = tid + i * 256;
        float val = (v[i] - mean) * rstd * g[c] + b[c];
        bf16 hh, ll;
        split1(val, hh, ll);
        oh[(size_t)s * H_ + c] = hh;
        ol[(size_t)s * H_ + c] = ll;
    }
}

// ---------------------------------------------------------------------------
// Unified bf16x3 tensor-core GEMM, cp.async double-buffered.
//   A: Ah/Al [M][K] bf16 (lda), B: Bh/Bl [N][K] bf16 (ldb).
//   CTA tile 128 x BN (BN = 256: warps 2m x 4n each 64x64;
//                      BN = 128: warps 4m x 2n each 32x64). BK=64.
//   EPI: 0 = store fp32 (alpha*acc + bias), 1 = gelu -> split bf16 Ch/Cl,
//        2 = accumulate into fp32 C.
//   CAUS:  skip blocks with n0 > row0+127 (causal scores).
//   CAUSK: limit K chunks to row0+128 (probs@v with zeroed upper triangle).
//   blockIdx.z batching via element strides sA/sB/sC.
// ---------------------------------------------------------------------------
template <int EPI, int BN, bool CAUS, bool CAUSK>
__global__ void __launch_bounds__(256, 1) gemm_bf(
    const bf16* __restrict__ Ah, const bf16* __restrict__ Al, int lda, long long sA,
    const bf16* __restrict__ Bh, const bf16* __restrict__ Bl, int ldb, long long sB,
    const float* __restrict__ bias,
    float* __restrict__ C, bf16* __restrict__ Ch, bf16* __restrict__ Cl,
    int ldc, long long sC,
    int K, float alpha) {

    constexpr int MI  = (BN == 256) ? 4 : 2;      // m16 tiles per warp
    constexpr int BUF = 32768 + 2 * BN * 128;      // bytes per stage

    extern __shared__ char smem[];
    const uint32_t sb = smem_u32(smem);
    const int tid  = threadIdx.x;
    const int lane = tid & 31;
    const int wid  = tid >> 5;
    const int wm   = (BN == 256) ? (wid & 1) : (wid & 3);
    const int wn   = (BN == 256) ? (wid >> 1) : (wid >> 2);
    const int row0 = blockIdx.x * 128;
    const int n0   = blockIdx.y * BN;

    if (CAUS && n0 > row0 + 127) return;

    Ah += (size_t)blockIdx.z * sA;  Al += (size_t)blockIdx.z * sA;
    Bh += (size_t)blockIdx.z * sB;  Bl += (size_t)blockIdx.z * sB;
    if (C)  C  += (size_t)blockIdx.z * sC;
    if (Ch) { Ch += (size_t)blockIdx.z * sC; Cl += (size_t)blockIdx.z * sC; }

    float acc[MI][8][4];
#pragma unroll
    for (int i = 0; i < MI; i++)
#pragma unroll
        for (int j = 0; j < 8; j++)
#pragma unroll
            for (int e = 0; e < 4; e++) acc[i][j][e] = 0.f;

    const int nch = CAUSK ? ((row0 + 128) >> 6) : (K >> 6);

    for (int c = 0; c <= nch; c++) {
        if (c < nch) {
            const uint32_t bufo = (uint32_t)(c & 1) * BUF;
            const int k0 = c << 6;
            // A: 128 rows x 64 k (hi+lo)
#pragma unroll
            for (int i = 0; i < 4; i++) {
                int idx = tid + i * 256;
                int r  = idx >> 3;
                int cc = (idx & 7) * 8;
                uint32_t soff = swz((uint32_t)(r * 128 + cc * 2));
                size_t go = (size_t)(row0 + r) * lda + k0 + cc;
                cpa16(sb + bufo + soff,         Ah + go);
                cpa16(sb + bufo + 16384 + soff, Al + go);
            }
            // B: BN rows x 64 k (hi+lo)
#pragma unroll
            for (int i = 0; i < BN / 32; i++) {
                int idx = tid + i * 256;
                int r  = idx >> 3;
                int cc = (idx & 7) * 8;
                uint32_t soff = swz((uint32_t)(r * 128 + cc * 2));
                size_t go = (size_t)(n0 + r) * ldb + k0 + cc;
                cpa16(sb + bufo + 32768 + soff,            Bh + go);
                cpa16(sb + bufo + 32768 + BN * 128 + soff, Bl + go);
            }
            asm volatile("cp.async.commit_group;" ::: "memory");
        }
        if (c >= 1) {
            if (c < nch) asm volatile("cp.async.wait_group 1;" ::: "memory");
            else         asm volatile("cp.async.wait_group 0;" ::: "memory");
            __syncthreads();

            const uint32_t bufo = (uint32_t)((c - 1) & 1) * BUF;
            const uint32_t sAh = sb + bufo;
            const uint32_t sAl = sAh + 16384;
            const uint32_t sBh = sAh + 32768;
            const uint32_t sBl = sBh + BN * 128;

#pragma unroll
            for (int ks = 0; ks < 4; ks++) {
                const int kk = ks * 16;
                uint32_t ah[MI][4], al[MI][4];
                {
                    const uint32_t arow = (uint32_t)(wm * (MI * 16) + (lane & 15));
                    const uint32_t acol = (uint32_t)(kk + (lane >> 4) * 8);
#pragma unroll
                    for (int mi = 0; mi < MI; mi++) {
                        uint32_t off = swz((arow + mi * 16) * 128 + acol * 2);
                        ldsm4(ah[mi], sAh + off);
                        ldsm4(al[mi], sAl + off);
                    }
                }
                const uint32_t brow = (uint32_t)(wn * 64 + ((lane >> 4) & 1) * 8 + (lane & 7));
                const uint32_t bcol = (uint32_t)(kk + ((lane >> 3) & 1) * 8);
#pragma unroll
                for (int ng = 0; ng < 4; ng++) {
                    uint32_t bh[4], bl[4];
                    uint32_t off = swz((brow + ng * 16) * 128 + bcol * 2);
                    ldsm4(bh, sBh + off);
                    ldsm4(bl, sBl + off);
#pragma unroll
                    for (int mi = 0; mi < MI; mi++) {
#pragma unroll
                        for (int half = 0; half < 2; half++) {
                            const int nt = ng * 2 + half;
                            mma16816(acc[mi][nt], ah[mi], bh + half * 2);
                            mma16816(acc[mi][nt], ah[mi], bl + half * 2);
                            mma16816(acc[mi][nt], al[mi], bh + half * 2);
                        }
                    }
                }
            }
            __syncthreads();
        }
    }

    // ---- epilogue ----
    const int g = lane >> 2;
    const int t = lane & 3;
#pragma unroll
    for (int mi = 0; mi < MI; mi++) {
        const int r = row0 + wm * (MI * 16) + mi * 16 + g;
#pragma unroll
        for (int nt = 0; nt < 8; nt++) {
            const int col = n0 + wn * 64 + nt * 8 + 2 * t;
            float2 v0 = make_float2(acc[mi][nt][0] * alpha, acc[mi][nt][1] * alpha);
            float2 v1 = make_float2(acc[mi][nt][2] * alpha, acc[mi][nt][3] * alpha);
            if (bias) {
                float2 bv = *(const float2*)(bias + col);
                v0.x += bv.x; v0.y += bv.y;
                v1.x += bv.x; v1.y += bv.y;
            }
            if (EPI == 1) {
                v0.x = gelu_f(v0.x); v0.y = gelu_f(v0.y);
                v1.x = gelu_f(v1.x); v1.y = gelu_f(v1.y);
                uint32_t l0, l1;
                uint32_t h0 = pack2(v0.x, v0.y, l0);
                uint32_t h1 = pack2(v1.x, v1.y, l1);
                *(uint32_t*)(Ch + (size_t)r * ldc + col) = h0;
                *(uint32_t*)(Cl + (size_t)r * ldc + col) = l0;
                *(uint32_t*)(Ch + (size_t)(r + 8) * ldc + col) = h1;
                *(uint32_t*)(Cl + (size_t)(r + 8) * ldc + col) = l1;
            } else {
                float* p0 = C + (size_t)r * ldc + col;
                float* p1 = C + (size_t)(r + 8) * ldc + col;
                if (EPI == 2) {
                    float2 o0 = *(const float2*)p0;
                    float2 o1 = *(const float2*)p1;
                    v0.x += o0.x; v0.y += o0.y;
                    v1.x += o1.x; v1.y += o1.y;
                }
                *(float2*)p0 = v0;
                *(float2*)p1 = v1;
            }
        }
    }
}

// ---------------------------------------------------------------------------
// Embedding gather
// ---------------------------------------------------------------------------
__global__ void embed_kernel(const int* __restrict__ x,
                             const float* __restrict__ embed,
                             float* __restrict__ h) {
    int s = blockIdx.y;
    int c = blockIdx.x * 256 + threadIdx.x;
    h[(size_t)s * H_ + c] = embed[(size_t)x[s] * H_ + c];
}

// ---------------------------------------------------------------------------
// Rotary (in-place on qkv)
// ---------------------------------------------------------------------------
__global__ void rotary_kernel(float* __restrict__ qkv) {
    int idx = blockIdx.x * 256 + threadIdx.x;
    int i = idx & 15;
    int n = (idx >> 4) & 15;
    int s = idx >> 8;
    float inv = expf(-(float)i * 0.575646273248511f);
    float ang = (float)s * inv;
    float sn, cs;
    sincosf(ang, &sn, &cs);
    float* p = qkv + (size_t)s * (3 * H_) + n * (3 * HD_);
    float a = p[i], c2 = p[i + 16];
    p[i]      = a * cs - c2 * sn;
    p[i + 16] = c2 * cs + a * sn;
    float* pk = p + HD_;
    a = pk[i]; c2 = pk[i + 16];
    pk[i]      = a * cs - c2 * sn;
    pk[i + 16] = c2 * cs + a * sn;
}

// ---------------------------------------------------------------------------
// Causal softmax; emits probs as bf16 hi/lo, zeroes k>q.
// ---------------------------------------------------------------------------
__global__ void softmax_split_kernel(float* __restrict__ scores,
                                     bf16* __restrict__ ph,
                                     bf16* __restrict__ pl) {
    const int q = blockIdx.x;
    const int n = blockIdx.y;
    const size_t base = ((size_t)n * S_ + q) * (size_t)S_;
    float* row = scores + base;
    bf16* phr = ph + base;
    bf16* plr = pl + base;
    const int len = q + 1;
    const int tid = threadIdx.x;
    __shared__ float red[256];

    float mx = -3.4e38f;
    for (int i = tid; i < len; i += 256) mx = fmaxf(mx, row[i]);
    red[tid] = mx; __syncthreads();
    for (int o = 128; o > 0; o >>= 1) {
        if (tid < o) red[tid] = fmaxf(red[tid], red[tid + o]);
        __syncthreads();
    }
    mx = red[0]; __syncthreads();

    float sum = 0.f;
    for (int i = tid; i < len; i += 256) {
        float e = expf(row[i] - mx);
        row[i] = e;
        sum += e;
    }
    red[tid] = sum; __syncthreads();
    for (int o = 128; o > 0; o >>= 1) {
        if (tid < o) red[tid] += red[tid + o];
        __syncthreads();
    }
    const float inv = 1.f / red[0];
    for (int i = tid; i < len; i += 256) {
        bf16 hh, ll;
        split1(row[i] * inv, hh, ll);
        phr[i] = hh;
        plr[i] = ll;
    }
    const bf16 z = __float2bfloat16_rn(0.f);
    for (int i = len + tid; i < S_; i += 256) { phr[i] = z; plr[i] = z; }
}

// ---------------------------------------------------------------------------
// Launcher
// ---------------------------------------------------------------------------
#define SM_256 (2 * (32768 + 2 * 256 * 128))
#define SM_128 (2 * (32768 + 2 * 128 * 128))

extern "C" void kernel_launch(void* const* d_in, const int* in_sizes, int n_in,
                              void* d_out, int out_size) {
    const int*   x        = (const int*)  d_in[0];
    const float* embed    = (const float*)d_in[1];
    const float* ln1_g    = (const float*)d_in[2];
    const float* ln1_b    = (const float*)d_in[3];
    const float* ln2_g    = (const float*)d_in[4];
    const float* ln2_b    = (const float*)d_in[5];
    const float* qkv_w    = (const float*)d_in[6];
    const float* qkv_b    = (const float*)d_in[7];
    const float* dense_w  = (const float*)d_in[8];
    const float* dense_b  = (const float*)d_in[9];
    const float* fc1_w    = (const float*)d_in[10];
    const float* fc1_b    = (const float*)d_in[11];
    const float* fc2_w    = (const float*)d_in[12];
    const float* fc2_b    = (const float*)d_in[13];
    const float* fln_g    = (const float*)d_in[14];
    const float* fln_b    = (const float*)d_in[15];
    const float* logits_w = (const float*)d_in[16];
    float* out = (float*)d_out;

    float *h, *qkv, *ctx, *scores;
    bf16 *a1h, *a1l, *a2h, *a2l, *fh, *fl, *wth, *wtl;
    bf16 *qh, *ql, *vth, *vtl, *ph, *pl;
    cudaGetSymbolAddress((void**)&h,      g_h);
    cudaGetSymbolAddress((void**)&qkv,    g_qkv);
    cudaGetSymbolAddress((void**)&ctx,    g_ctx);
    cudaGetSymbolAddress((void**)&scores, g_scores);
    cudaGetSymbolAddress((void**)&a1h,    g_a1h);
    cudaGetSymbolAddress((void**)&a1l,    g_a1l);
    cudaGetSymbolAddress((void**)&a2h,    g_a2h);
    cudaGetSymbolAddress((void**)&a2l,    g_a2l);
    cudaGetSymbolAddress((void**)&fh,     g_fh);
    cudaGetSymbolAddress((void**)&fl,     g_fl);
    cudaGetSymbolAddress((void**)&wth,    g_wth);
    cudaGetSymbolAddress((void**)&wtl,    g_wtl);
    cudaGetSymbolAddress((void**)&qh,     g_qh);
    cudaGetSymbolAddress((void**)&ql,     g_ql);
    cudaGetSymbolAddress((void**)&vth,    g_vth);
    cudaGetSymbolAddress((void**)&vtl,    g_vtl);
    cudaGetSymbolAddress((void**)&ph,     g_ph);
    cudaGetSymbolAddress((void**)&pl,     g_pl);

    cudaFuncSetAttribute((const void*)gemm_bf<0, 256, false, false>,
                         cudaFuncAttributeMaxDynamicSharedMemorySize, SM_256);
    cudaFuncSetAttribute((const void*)gemm_bf<1, 256, false, false>,
                         cudaFuncAttributeMaxDynamicSharedMemorySize, SM_256);
    cudaFuncSetAttribute((const void*)gemm_bf<2, 256, false, false>,
                         cudaFuncAttributeMaxDynamicSharedMemorySize, SM_256);
    cudaFuncSetAttribute((const void*)gemm_bf<0, 256, true, false>,
                         cudaFuncAttributeMaxDynamicSharedMemorySize, SM_256);
    cudaFuncSetAttribute((const void*)gemm_bf<0, 128, false, true>,
                         cudaFuncAttributeMaxDynamicSharedMemorySize, SM_128);

    const float inv_sqrt_hd = 0.08838834764831845f;  // 1/sqrt(128)

    embed_kernel<<<dim3(H_ / 256, S_), 256>>>(x, embed, h);

    for (int l = 0; l < L_; l++) {
        // ln1 -> a1 (split)
        ln_split_kernel<<<S_, 256>>>(h, ln1_g + (size_t)l * H_, ln1_b + (size_t)l * H_,
                                     a1h, a1l);

        // qkv = ln1 @ qkv_w + qkv_b
        wsplit_kernel<<<dim3(H_ / 32, 3 * H_ / 32, 1), 256>>>(
            qkv_w + (size_t)l * H_ * 3 * H_, 3 * H_, H_, 3 * H_, 0, 0, wth, wtl);
        gemm_bf<0, 256, false, false><<<dim3(S_ / 128, 3 * H_ / 256, 1), 256, SM_256>>>(
            a1h, a1l, H_, 0, wth, wtl, H_, 0, qkv_b + (size_t)l * 3 * H_,
            qkv, nullptr, nullptr, 3 * H_, 0, H_, 1.f);

        rotary_kernel<<<(S_ * NH_ * 16) / 256, 256>>>(qkv);

        // split q,k (whole qkv buffer; v part unused but harmless)
        split_kernel<<<(S_ * 3 * H_) / 1024, 256>>>(qkv, qh, ql);

        // v^T split per head: vth[n][d][s] = v[s][n*384+256+d]
        wsplit_kernel<<<dim3(S_ / 32, HD_ / 32, NH_), 256>>>(
            qkv + 2 * HD_, 3 * H_, S_, HD_, 3 * HD_, (long long)HD_ * S_, vth, vtl);

        // scores = q @ k^T * 1/sqrt(HD)  (bf16x3 MMA, causal block-skip)
        gemm_bf<0, 256, true, false><<<dim3(S_ / 128, S_ / 256, NH_), 256, SM_256>>>(
            qh, ql, 3 * H_, 3 * HD_,
            qh + HD_, ql + HD_, 3 * H_, 3 * HD_,
            nullptr, scores, nullptr, nullptr, S_, (long long)S_ * S_,
            HD_, inv_sqrt_hd);

        softmax_split_kernel<<<dim3(S_, NH_), 256>>>(scores, ph, pl);

        // ctx = probs @ v  (bf16x3 MMA, causal K-limit)
        gemm_bf<0, 128, false, true><<<dim3(S_ / 128, 1, NH_), 256, SM_128>>>(
            ph, pl, S_, (long long)S_ * S_,
            vth, vtl, S_, (long long)HD_ * S_,
            nullptr, ctx, nullptr, nullptr, H_, HD_,
            S_, 1.f);

        // ln2 -> a2 (reads pre-update h; must precede residual adds)
        ln_split_kernel<<<S_, 256>>>(h, ln2_g + (size_t)l * H_, ln2_b + (size_t)l * H_,
                                     a2h, a2l);

        // ctx split -> a1 (a1 free after qkv gemm)
        split_kernel<<<(S_ * H_) / 1024, 256>>>(ctx, a1h, a1l);

        // h += ctx @ dense_w + dense_b
        wsplit_kernel<<<dim3(H_ / 32, H_ / 32, 1), 256>>>(
            dense_w + (size_t)l * H_ * H_, H_, H_, H_, 0, 0, wth, wtl);
        gemm_bf<2, 256, false, false><<<dim3(S_ / 128, H_ / 256, 1), 256, SM_256>>>(
            a1h, a1l, H_, 0, wth, wtl, H_, 0, dense_b + (size_t)l * H_,
            h, nullptr, nullptr, H_, 0, H_, 1.f);

        // fc1 = gelu(ln2 @ fc1_w + fc1_b) -> fh/fl (split)
        wsplit_kernel<<<dim3(H_ / 32, FF_ / 32, 1), 256>>>(
            fc1_w + (size_t)l * H_ * FF_, FF_, H_, FF_, 0, 0, wth, wtl);
        gemm_bf<1, 256, false, false><<<dim3(S_ / 128, FF_ / 256, 1), 256, SM_256>>>(
            a2h, a2l, H_, 0, wth, wtl, H_, 0, fc1_b + (size_t)l * FF_,
            nullptr, fh, fl, FF_, 0, H_, 1.f);

        // h += fc1 @ fc2_w + fc2_b
        wsplit_kernel<<<dim3(FF_ / 32, H_ / 32, 1), 256>>>(
            fc2_w + (size_t)l * FF_ * H_, H_, FF_, H_, 0, 0, wth, wtl);
        gemm_bf<2, 256, false, false><<<dim3(S_ / 128, H_ / 256, 1), 256, SM_256>>>(
            fh, fl, FF_, 0, wth, wtl, FF_, 0, fc2_b + (size_t)l * H_,
            h, nullptr, nullptr, H_, 0, FF_, 1.f);
    }

    // Final LN + logits GEMM
    ln_split_kernel<<<S_, 256>>>(h, fln_g, fln_b, a1h, a1l);
    wsplit_kernel<<<dim3(H_ / 32, V_ / 32, 1), 256>>>(
        logits_w, V_, H_, V_, 0, 0, wth, wtl);
    gemm_bf<0, 256, false, false><<<dim3(S_ / 128, V_ / 256, 1), 256, SM_256>>>(
        a1h, a1l, H_, 0, wth, wtl, H_, 0, nullptr,
        out, nullptr, nullptr, V_, 0, H_, 1.f);
}

// round 6
// speedup vs baseline: 3.5754x; 1.0954x over previous
#include <cuda_runtime.h>
#include <cuda_bf16.h>
#include <math.h>
#include <stdint.h>

// Problem constants
#define S_    2048
#define H_    2048
#define NH_   16
#define HD_   128
#define ROT_  32
#define FF_   8192
#define L_    2
#define V_    32000
#define EPS_  1e-5f

typedef __nv_bfloat16 bf16;

// ---------------------------------------------------------------------------
// Scratch (static device globals)
// ---------------------------------------------------------------------------
__device__ float g_h  [(size_t)S_ * H_];
__device__ float g_qkv[(size_t)S_ * 3 * H_];
__device__ float g_mlp[(size_t)S_ * H_];
__device__ float g_scores[(size_t)NH_ * S_ * S_];

__device__ bf16 g_a1h[(size_t)S_ * H_];
__device__ bf16 g_a1l[(size_t)S_ * H_];
__device__ bf16 g_a2h[(size_t)S_ * H_];
__device__ bf16 g_a2l[(size_t)S_ * H_];
__device__ bf16 g_fh [(size_t)S_ * FF_];
__device__ bf16 g_fl [(size_t)S_ * FF_];

__device__ bf16 g_qh [(size_t)S_ * 3 * H_];
__device__ bf16 g_ql [(size_t)S_ * 3 * H_];
__device__ bf16 g_vth[(size_t)NH_ * HD_ * S_];
__device__ bf16 g_vtl[(size_t)NH_ * HD_ * S_];
__device__ bf16 g_ph [(size_t)NH_ * S_ * S_];
__device__ bf16 g_pl [(size_t)NH_ * S_ * S_];

// per-GEMM transposed/split weights
__device__ bf16 g_wqh [(size_t)L_ * H_ * 3 * H_];
__device__ bf16 g_wql [(size_t)L_ * H_ * 3 * H_];
__device__ bf16 g_wdh [(size_t)L_ * H_ * H_];
__device__ bf16 g_wdl [(size_t)L_ * H_ * H_];
__device__ bf16 g_wf1h[(size_t)L_ * H_ * FF_];
__device__ bf16 g_wf1l[(size_t)L_ * H_ * FF_];
__device__ bf16 g_wf2h[(size_t)L_ * FF_ * H_];
__device__ bf16 g_wf2l[(size_t)L_ * FF_ * H_];
__device__ bf16 g_wlh [(size_t)V_ * H_];
__device__ bf16 g_wll [(size_t)V_ * H_];

// ---------------------------------------------------------------------------
// Helpers
// ---------------------------------------------------------------------------
__device__ __forceinline__ uint32_t smem_u32(const void* p) {
    uint32_t a;
    asm("{ .reg .u64 t; cvta.to.shared.u64 t, %1; cvt.u32.u64 %0, t; }"
        : "=r"(a) : "l"(p));
    return a;
}
__device__ __forceinline__ uint32_t swz(uint32_t off) {
    return off ^ ((off >> 3) & 0x70);
}
__device__ __forceinline__ float gelu_f(float x) {
    float t = tanhf(0.79788456f * x * (1.f + 0.044715f * x * x));
    return 0.5f * x * (1.f + t);
}
__device__ __forceinline__ uint32_t pack2(float x, float y, uint32_t& lo) {
    bf16 hx = __float2bfloat16_rn(x);
    bf16 hy = __float2bfloat16_rn(y);
    bf16 lx = __float2bfloat16_rn(x - __bfloat162float(hx));
    bf16 ly = __float2bfloat16_rn(y - __bfloat162float(hy));
    lo = (uint32_t)__bfloat16_as_ushort(lx) | ((uint32_t)__bfloat16_as_ushort(ly) << 16);
    return (uint32_t)__bfloat16_as_ushort(hx) | ((uint32_t)__bfloat16_as_ushort(hy) << 16);
}
__device__ __forceinline__ void split1(float x, bf16& h, bf16& l) {
    h = __float2bfloat16_rn(x);
    l = __float2bfloat16_rn(x - __bfloat162float(h));
}
__device__ __forceinline__ void ldsm4(uint32_t (&r)[4], uint32_t addr) {
    asm volatile("ldmatrix.sync.aligned.m8n8.x4.shared.b16 {%0,%1,%2,%3}, [%4];"
                 : "=r"(r[0]), "=r"(r[1]), "=r"(r[2]), "=r"(r[3]) : "r"(addr));
}
__device__ __forceinline__ void mma16816(float (&d)[4], const uint32_t (&a)[4],
                                         const uint32_t* b) {
    asm volatile(
        "mma.sync.aligned.m16n8k16.row.col.f32.bf16.bf16.f32 "
        "{%0,%1,%2,%3}, {%4,%5,%6,%7}, {%8,%9}, {%0,%1,%2,%3};"
        : "+f"(d[0]), "+f"(d[1]), "+f"(d[2]), "+f"(d[3])
        : "r"(a[0]), "r"(a[1]), "r"(a[2]), "r"(a[3]), "r"(b[0]), "r"(b[1]));
}
__device__ __forceinline__ void cpa16(uint32_t s, const void* g) {
    asm volatile("cp.async.cg.shared.global [%0], [%1], 16;" :: "r"(s), "l"(g));
}

// ---------------------------------------------------------------------------
// Transpose + split: W[Kd rows][N cols] fp32 (ldw) -> WTh/WTl[N][Kd] bf16
// ---------------------------------------------------------------------------
__global__ void wsplit_kernel(const float* __restrict__ W, int ldw, int Kd, int N,
                              long long zin, long long zout,
                              bf16* __restrict__ WTh, bf16* __restrict__ WTl) {
    W   += (size_t)blockIdx.z * zin;
    WTh += (size_t)blockIdx.z * zout;
    WTl += (size_t)blockIdx.z * zout;

    __shared__ float s[32][33];
    const int k0 = blockIdx.x * 32;
    const int n0 = blockIdx.y * 32;
    const int tid = threadIdx.x;
    const int r  = tid >> 3;
    const int c4 = (tid & 7) * 4;

    float4 v = *(const float4*)(W + (size_t)(k0 + r) * ldw + n0 + c4);
    s[r][c4 + 0] = v.x; s[r][c4 + 1] = v.y;
    s[r][c4 + 2] = v.z; s[r][c4 + 3] = v.w;
    __syncthreads();

    float x0 = s[c4 + 0][r], x1 = s[c4 + 1][r];
    float x2 = s[c4 + 2][r], x3 = s[c4 + 3][r];
    uint32_t l0, l1;
    uint32_t h0 = pack2(x0, x1, l0);
    uint32_t h1 = pack2(x2, x3, l1);
    size_t o = (size_t)(n0 + r) * Kd + k0 + c4;
    *(uint2*)(WTh + o) = make_uint2(h0, h1);
    *(uint2*)(WTl + o) = make_uint2(l0, l1);
}

// ---------------------------------------------------------------------------
// Elementwise fp32 -> bf16 hi/lo split
// ---------------------------------------------------------------------------
__global__ void split_kernel(const float* __restrict__ in,
                             bf16* __restrict__ oh,
                             bf16* __restrict__ ol) {
    int i = (blockIdx.x * 256 + threadIdx.x) * 4;
    float4 v = *(const float4*)(in + i);
    uint32_t l0, l1;
    uint32_t h0 = pack2(v.x, v.y, l0);
    uint32_t h1 = pack2(v.z, v.w, l1);
    *(uint2*)(oh + i) = make_uint2(h0, h1);
    *(uint2*)(ol + i) = make_uint2(l0, l1);
}

// h += m
__global__ void add_kernel(float* __restrict__ h, const float* __restrict__ m) {
    int i = (blockIdx.x * 256 + threadIdx.x) * 4;
    float4 a = *(const float4*)(h + i);
    float4 b = *(const float4*)(m + i);
    a.x += b.x; a.y += b.y; a.z += b.z; a.w += b.w;
    *(float4*)(h + i) = a;
}

// ---------------------------------------------------------------------------
// LayerNorm -> bf16 hi/lo split output
// ---------------------------------------------------------------------------
__global__ void ln_split_kernel(const float* __restrict__ in,
                                const float* __restrict__ g,
                                const float* __restrict__ b,
                                bf16* __restrict__ oh,
                                bf16* __restrict__ ol) {
    const int s = blockIdx.x;
    const int tid = threadIdx.x;
    const float* row = in + (size_t)s * H_;
    __shared__ float red[256];

    float v[8];
    float lsum = 0.f;
#pragma unroll
    for (int i = 0; i < 8; i++) { v[i] = row[tid + i * 256]; lsum += v[i]; }
    red[tid] = lsum; __syncthreads();
    for (int o = 128; o > 0; o >>= 1) {
        if (tid < o) red[tid] += red[tid + o];
        __syncthreads();
    }
    const float mean = red[0] * (1.f / H_);
    __syncthreads();

    float lvar = 0.f;
#pragma unroll
    for (int i = 0; i < 8; i++) { float d = v[i] - mean; lvar += d * d; }
    red[tid] = lvar; __syncthreads();
    for (int o = 128; o > 0; o >>= 1) {
        if (tid < o) red[tid] += red[tid + o];
        __syncthreads();
    }
    const float rstd = rsqrtf(red[0] * (1.f / H_) + EPS_);

#pragma unroll
    for (int i = 0; i < 8; i++) {
        int c = tid + i * 256;
        float val = (v[i] - mean) * rstd * g[c] + b[c];
        bf16 hh, ll;
        split1(val, hh, ll);
        oh[(size_t)s * H_ + c] = hh;
        ol[(size_t)s * H_ + c] = ll;
    }
}

// ---------------------------------------------------------------------------
// Unified bf16x3 tensor-core GEMM, cp.async double-buffered (same core as R5).
//   EPI: 0 = fp32 store, 1 = gelu->split bf16, 2 = fp32 accumulate,
//        3 = split bf16 (no gelu).
// ---------------------------------------------------------------------------
template <int EPI, int BN, bool CAUS, bool CAUSK>
__global__ void __launch_bounds__(256, 1) gemm_bf(
    const bf16* __restrict__ Ah, const bf16* __restrict__ Al, int lda, long long sA,
    const bf16* __restrict__ Bh, const bf16* __restrict__ Bl, int ldb, long long sB,
    const float* __restrict__ bias,
    float* __restrict__ C, bf16* __restrict__ Ch, bf16* __restrict__ Cl,
    int ldc, long long sC,
    int K, float alpha) {

    constexpr int MI  = (BN == 256) ? 4 : 2;
    constexpr int BUF = 32768 + 2 * BN * 128;

    extern __shared__ char smem[];
    const uint32_t sb = smem_u32(smem);
    const int tid  = threadIdx.x;
    const int lane = tid & 31;
    const int wid  = tid >> 5;
    const int wm   = (BN == 256) ? (wid & 1) : (wid & 3);
    const int wn   = (BN == 256) ? (wid >> 1) : (wid >> 2);
    const int row0 = blockIdx.x * 128;
    const int n0   = blockIdx.y * BN;

    if (CAUS && n0 > row0 + 127) return;

    Ah += (size_t)blockIdx.z * sA;  Al += (size_t)blockIdx.z * sA;
    Bh += (size_t)blockIdx.z * sB;  Bl += (size_t)blockIdx.z * sB;
    if (C)  C  += (size_t)blockIdx.z * sC;
    if (Ch) { Ch += (size_t)blockIdx.z * sC; Cl += (size_t)blockIdx.z * sC; }

    float acc[MI][8][4];
#pragma unroll
    for (int i = 0; i < MI; i++)
#pragma unroll
        for (int j = 0; j < 8; j++)
#pragma unroll
            for (int e = 0; e < 4; e++) acc[i][j][e] = 0.f;

    const int nch = CAUSK ? ((row0 + 128) >> 6) : (K >> 6);

    for (int c = 0; c <= nch; c++) {
        if (c < nch) {
            const uint32_t bufo = (uint32_t)(c & 1) * BUF;
            const int k0 = c << 6;
#pragma unroll
            for (int i = 0; i < 4; i++) {
                int idx = tid + i * 256;
                int r  = idx >> 3;
                int cc = (idx & 7) * 8;
                uint32_t soff = swz((uint32_t)(r * 128 + cc * 2));
                size_t go = (size_t)(row0 + r) * lda + k0 + cc;
                cpa16(sb + bufo + soff,         Ah + go);
                cpa16(sb + bufo + 16384 + soff, Al + go);
            }
#pragma unroll
            for (int i = 0; i < BN / 32; i++) {
                int idx = tid + i * 256;
                int r  = idx >> 3;
                int cc = (idx & 7) * 8;
                uint32_t soff = swz((uint32_t)(r * 128 + cc * 2));
                size_t go = (size_t)(n0 + r) * ldb + k0 + cc;
                cpa16(sb + bufo + 32768 + soff,            Bh + go);
                cpa16(sb + bufo + 32768 + BN * 128 + soff, Bl + go);
            }
            asm volatile("cp.async.commit_group;" ::: "memory");
        }
        if (c >= 1) {
            if (c < nch) asm volatile("cp.async.wait_group 1;" ::: "memory");
            else         asm volatile("cp.async.wait_group 0;" ::: "memory");
            __syncthreads();

            const uint32_t bufo = (uint32_t)((c - 1) & 1) * BUF;
            const uint32_t sAh = sb + bufo;
            const uint32_t sAl = sAh + 16384;
            const uint32_t sBh = sAh + 32768;
            const uint32_t sBl = sBh + BN * 128;

#pragma unroll
            for (int ks = 0; ks < 4; ks++) {
                const int kk = ks * 16;
                uint32_t ah[MI][4], al[MI][4];
                {
                    const uint32_t arow = (uint32_t)(wm * (MI * 16) + (lane & 15));
                    const uint32_t acol = (uint32_t)(kk + (lane >> 4) * 8);
#pragma unroll
                    for (int mi = 0; mi < MI; mi++) {
                        uint32_t off = swz((arow + mi * 16) * 128 + acol * 2);
                        ldsm4(ah[mi], sAh + off);
                        ldsm4(al[mi], sAl + off);
                    }
                }
                const uint32_t brow = (uint32_t)(wn * 64 + ((lane >> 4) & 1) * 8 + (lane & 7));
                const uint32_t bcol = (uint32_t)(kk + ((lane >> 3) & 1) * 8);
#pragma unroll
                for (int ng = 0; ng < 4; ng++) {
                    uint32_t bh[4], bl[4];
                    uint32_t off = swz((brow + ng * 16) * 128 + bcol * 2);
                    ldsm4(bh, sBh + off);
                    ldsm4(bl, sBl + off);
#pragma unroll
                    for (int mi = 0; mi < MI; mi++) {
#pragma unroll
                        for (int half = 0; half < 2; half++) {
                            const int nt = ng * 2 + half;
                            mma16816(acc[mi][nt], ah[mi], bh + half * 2);
                            mma16816(acc[mi][nt], ah[mi], bl + half * 2);
                            mma16816(acc[mi][nt], al[mi], bh + half * 2);
                        }
                    }
                }
            }
            __syncthreads();
        }
    }

    // ---- epilogue ----
    const int g = lane >> 2;
    const int t = lane & 3;
#pragma unroll
    for (int mi = 0; mi < MI; mi++) {
        const int r = row0 + wm * (MI * 16) + mi * 16 + g;
#pragma unroll
        for (int nt = 0; nt < 8; nt++) {
            const int col = n0 + wn * 64 + nt * 8 + 2 * t;
            float2 v0 = make_float2(acc[mi][nt][0] * alpha, acc[mi][nt][1] * alpha);
            float2 v1 = make_float2(acc[mi][nt][2] * alpha, acc[mi][nt][3] * alpha);
            if (bias) {
                float2 bv = *(const float2*)(bias + col);
                v0.x += bv.x; v0.y += bv.y;
                v1.x += bv.x; v1.y += bv.y;
            }
            if (EPI == 1 || EPI == 3) {
                if (EPI == 1) {
                    v0.x = gelu_f(v0.x); v0.y = gelu_f(v0.y);
                    v1.x = gelu_f(v1.x); v1.y = gelu_f(v1.y);
                }
                uint32_t l0, l1;
                uint32_t h0 = pack2(v0.x, v0.y, l0);
                uint32_t h1 = pack2(v1.x, v1.y, l1);
                *(uint32_t*)(Ch + (size_t)r * ldc + col) = h0;
                *(uint32_t*)(Cl + (size_t)r * ldc + col) = l0;
                *(uint32_t*)(Ch + (size_t)(r + 8) * ldc + col) = h1;
                *(uint32_t*)(Cl + (size_t)(r + 8) * ldc + col) = l1;
            } else {
                float* p0 = C + (size_t)r * ldc + col;
                float* p1 = C + (size_t)(r + 8) * ldc + col;
                if (EPI == 2) {
                    float2 o0 = *(const float2*)p0;
                    float2 o1 = *(const float2*)p1;
                    v0.x += o0.x; v0.y += o0.y;
                    v1.x += o1.x; v1.y += o1.y;
                }
                *(float2*)p0 = v0;
                *(float2*)p1 = v1;
            }
        }
    }
}

// ---------------------------------------------------------------------------
// Embedding gather
// ---------------------------------------------------------------------------
__global__ void embed_kernel(const int* __restrict__ x,
                             const float* __restrict__ embed,
                             float* __restrict__ h) {
    int s = blockIdx.y;
    int c = blockIdx.x * 256 + threadIdx.x;
    h[(size_t)s * H_ + c] = embed[(size_t)x[s] * H_ + c];
}

// ---------------------------------------------------------------------------
// Rotary (in-place on qkv)
// ---------------------------------------------------------------------------
__global__ void rotary_kernel(float* __restrict__ qkv) {
    int idx = blockIdx.x * 256 + threadIdx.x;
    int i = idx & 15;
    int n = (idx >> 4) & 15;
    int s = idx >> 8;
    float inv = expf(-(float)i * 0.575646273248511f);
    float ang = (float)s * inv;
    float sn, cs;
    sincosf(ang, &sn, &cs);
    float* p = qkv + (size_t)s * (3 * H_) + n * (3 * HD_);
    float a = p[i], c2 = p[i + 16];
    p[i]      = a * cs - c2 * sn;
    p[i + 16] = c2 * cs + a * sn;
    float* pk = p + HD_;
    a = pk[i]; c2 = pk[i + 16];
    pk[i]      = a * cs - c2 * sn;
    pk[i + 16] = c2 * cs + a * sn;
}

// ---------------------------------------------------------------------------
// Causal softmax; emits probs as bf16 hi/lo, zeroes k>q.
// ---------------------------------------------------------------------------
__global__ void softmax_split_kernel(float* __restrict__ scores,
                                     bf16* __restrict__ ph,
                                     bf16* __restrict__ pl) {
    const int q = blockIdx.x;
    const int n = blockIdx.y;
    const size_t base = ((size_t)n * S_ + q) * (size_t)S_;
    float* row = scores + base;
    bf16* phr = ph + base;
    bf16* plr = pl + base;
    const int len = q + 1;
    const int tid = threadIdx.x;
    __shared__ float red[256];

    float mx = -3.4e38f;
    for (int i = tid; i < len; i += 256) mx = fmaxf(mx, row[i]);
    red[tid] = mx; __syncthreads();
    for (int o = 128; o > 0; o >>= 1) {
        if (tid < o) red[tid] = fmaxf(red[tid], red[tid + o]);
        __syncthreads();
    }
    mx = red[0]; __syncthreads();

    float sum = 0.f;
    for (int i = tid; i < len; i += 256) {
        float e = expf(row[i] - mx);
        row[i] = e;
        sum += e;
    }
    red[tid] = sum; __syncthreads();
    for (int o = 128; o > 0; o >>= 1) {
        if (tid < o) red[tid] += red[tid + o];
        __syncthreads();
    }
    const float inv = 1.f / red[0];
    for (int i = tid; i < len; i += 256) {
        bf16 hh, ll;
        split1(row[i] * inv, hh, ll);
        phr[i] = hh;
        plr[i] = ll;
    }
    const bf16 z = __float2bfloat16_rn(0.f);
    for (int i = len + tid; i < S_; i += 256) { phr[i] = z; plr[i] = z; }
}

// ---------------------------------------------------------------------------
// Launcher with 3-stream fork/join (capture-safe: full join before return)
// ---------------------------------------------------------------------------
#define SM_256 (2 * (32768 + 2 * 256 * 128))
#define SM_128 (2 * (32768 + 2 * 128 * 128))

extern "C" void kernel_launch(void* const* d_in, const int* in_sizes, int n_in,
                              void* d_out, int out_size) {
    const int*   x        = (const int*)  d_in[0];
    const float* embed    = (const float*)d_in[1];
    const float* ln1_g    = (const float*)d_in[2];
    const float* ln1_b    = (const float*)d_in[3];
    const float* ln2_g    = (const float*)d_in[4];
    const float* ln2_b    = (const float*)d_in[5];
    const float* qkv_w    = (const float*)d_in[6];
    const float* qkv_b    = (const float*)d_in[7];
    const float* dense_w  = (const float*)d_in[8];
    const float* dense_b  = (const float*)d_in[9];
    const float* fc1_w    = (const float*)d_in[10];
    const float* fc1_b    = (const float*)d_in[11];
    const float* fc2_w    = (const float*)d_in[12];
    const float* fc2_b    = (const float*)d_in[13];
    const float* fln_g    = (const float*)d_in[14];
    const float* fln_b    = (const float*)d_in[15];
    const float* logits_w = (const float*)d_in[16];
    float* out = (float*)d_out;

    float *h, *qkv, *mlp, *scores;
    bf16 *a1h, *a1l, *a2h, *a2l, *fh, *fl;
    bf16 *qh, *ql, *vth, *vtl, *ph, *pl;
    bf16 *wqh, *wql, *wdh, *wdl, *wf1h, *wf1l, *wf2h, *wf2l, *wlh, *wll;
    cudaGetSymbolAddress((void**)&h,      g_h);
    cudaGetSymbolAddress((void**)&qkv,    g_qkv);
    cudaGetSymbolAddress((void**)&mlp,    g_mlp);
    cudaGetSymbolAddress((void**)&scores, g_scores);
    cudaGetSymbolAddress((void**)&a1h,    g_a1h);
    cudaGetSymbolAddress((void**)&a1l,    g_a1l);
    cudaGetSymbolAddress((void**)&a2h,    g_a2h);
    cudaGetSymbolAddress((void**)&a2l,    g_a2l);
    cudaGetSymbolAddress((void**)&fh,     g_fh);
    cudaGetSymbolAddress((void**)&fl,     g_fl);
    cudaGetSymbolAddress((void**)&qh,     g_qh);
    cudaGetSymbolAddress((void**)&ql,     g_ql);
    cudaGetSymbolAddress((void**)&vth,    g_vth);
    cudaGetSymbolAddress((void**)&vtl,    g_vtl);
    cudaGetSymbolAddress((void**)&ph,     g_ph);
    cudaGetSymbolAddress((void**)&pl,     g_pl);
    cudaGetSymbolAddress((void**)&wqh,    g_wqh);
    cudaGetSymbolAddress((void**)&wql,    g_wql);
    cudaGetSymbolAddress((void**)&wdh,    g_wdh);
    cudaGetSymbolAddress((void**)&wdl,    g_wdl);
    cudaGetSymbolAddress((void**)&wf1h,   g_wf1h);
    cudaGetSymbolAddress((void**)&wf1l,   g_wf1l);
    cudaGetSymbolAddress((void**)&wf2h,   g_wf2h);
    cudaGetSymbolAddress((void**)&wf2l,   g_wf2l);
    cudaGetSymbolAddress((void**)&wlh,    g_wlh);
    cudaGetSymbolAddress((void**)&wll,    g_wll);

    cudaFuncSetAttribute((const void*)gemm_bf<0, 256, false, false>,
                         cudaFuncAttributeMaxDynamicSharedMemorySize, SM_256);
    cudaFuncSetAttribute((const void*)gemm_bf<1, 256, false, false>,
                         cudaFuncAttributeMaxDynamicSharedMemorySize, SM_256);
    cudaFuncSetAttribute((const void*)gemm_bf<2, 256, false, false>,
                         cudaFuncAttributeMaxDynamicSharedMemorySize, SM_256);
    cudaFuncSetAttribute((const void*)gemm_bf<0, 256, true, false>,
                         cudaFuncAttributeMaxDynamicSharedMemorySize, SM_256);
    cudaFuncSetAttribute((const void*)gemm_bf<3, 128, false, true>,
                         cudaFuncAttributeMaxDynamicSharedMemorySize, SM_128);

    // streams/events created once (first call is the non-captured correctness run)
    static cudaStream_t sW = 0, sM = 0;
    static cudaEvent_t evFork, evW[5], evLn2[L_], evMlp[L_];
    if (!sW) {
        cudaStreamCreateWithFlags(&sW, cudaStreamNonBlocking);
        cudaStreamCreateWithFlags(&sM, cudaStreamNonBlocking);
        cudaEventCreateWithFlags(&evFork, cudaEventDisableTiming);
        for (int i = 0; i < 5; i++) cudaEventCreateWithFlags(&evW[i], cudaEventDisableTiming);
        for (int i = 0; i < L_; i++) {
            cudaEventCreateWithFlags(&evLn2[i], cudaEventDisableTiming);
            cudaEventCreateWithFlags(&evMlp[i], cudaEventDisableTiming);
        }
    }

    const float inv_sqrt_hd = 0.08838834764831845f;  // 1/sqrt(128)

    // ---- fork ----
    cudaEventRecord(evFork, 0);
    cudaStreamWaitEvent(sW, evFork, 0);
    cudaStreamWaitEvent(sM, evFork, 0);

    // ---- weight prep on sW (z batches both layers) ----
    wsplit_kernel<<<dim3(H_ / 32, 3 * H_ / 32, L_), 256, 0, sW>>>(
        qkv_w, 3 * H_, H_, 3 * H_, (long long)H_ * 3 * H_, (long long)H_ * 3 * H_, wqh, wql);
    cudaEventRecord(evW[0], sW);
    wsplit_kernel<<<dim3(H_ / 32, FF_ / 32, L_), 256, 0, sW>>>(
        fc1_w, FF_, H_, FF_, (long long)H_ * FF_, (long long)H_ * FF_, wf1h, wf1l);
    cudaEventRecord(evW[1], sW);
    wsplit_kernel<<<dim3(FF_ / 32, H_ / 32, L_), 256, 0, sW>>>(
        fc2_w, H_, FF_, H_, (long long)FF_ * H_, (long long)FF_ * H_, wf2h, wf2l);
    cudaEventRecord(evW[2], sW);
    wsplit_kernel<<<dim3(H_ / 32, H_ / 32, L_), 256, 0, sW>>>(
        dense_w, H_, H_, H_, (long long)H_ * H_, (long long)H_ * H_, wdh, wdl);
    cudaEventRecord(evW[3], sW);
    wsplit_kernel<<<dim3(H_ / 32, V_ / 32, 1), 256, 0, sW>>>(
        logits_w, V_, H_, V_, 0, 0, wlh, wll);
    cudaEventRecord(evW[4], sW);

    // ---- main path ----
    embed_kernel<<<dim3(H_ / 256, S_), 256>>>(x, embed, h);

    for (int l = 0; l < L_; l++) {
        // both LN read pre-update h
        ln_split_kernel<<<S_, 256>>>(h, ln1_g + (size_t)l * H_, ln1_b + (size_t)l * H_,
                                     a1h, a1l);
        ln_split_kernel<<<S_, 256>>>(h, ln2_g + (size_t)l * H_, ln2_b + (size_t)l * H_,
                                     a2h, a2l);
        cudaEventRecord(evLn2[l], 0);

        // ---- MLP branch on sM ----
        cudaStreamWaitEvent(sM, evLn2[l], 0);
        cudaStreamWaitEvent(sM, evW[1], 0);
        gemm_bf<1, 256, false, false><<<dim3(S_ / 128, FF_ / 256, 1), 256, SM_256, sM>>>(
            a2h, a2l, H_, 0, wf1h + (size_t)l * H_ * FF_, wf1l + (size_t)l * H_ * FF_, H_, 0,
            fc1_b + (size_t)l * FF_, nullptr, fh, fl, FF_, 0, H_, 1.f);
        cudaStreamWaitEvent(sM, evW[2], 0);
        gemm_bf<0, 256, false, false><<<dim3(S_ / 128, H_ / 256, 1), 256, SM_256, sM>>>(
            fh, fl, FF_, 0, wf2h + (size_t)l * FF_ * H_, wf2l + (size_t)l * FF_ * H_, FF_, 0,
            fc2_b + (size_t)l * H_, mlp, nullptr, nullptr, H_, 0, FF_, 1.f);
        cudaEventRecord(evMlp[l], sM);

        // ---- attention branch on main ----
        cudaStreamWaitEvent(0, evW[0], 0);
        gemm_bf<0, 256, false, false><<<dim3(S_ / 128, 3 * H_ / 256, 1), 256, SM_256>>>(
            a1h, a1l, H_, 0, wqh + (size_t)l * H_ * 3 * H_, wql + (size_t)l * H_ * 3 * H_, H_, 0,
            qkv_b + (size_t)l * 3 * H_, qkv, nullptr, nullptr, 3 * H_, 0, H_, 1.f);

        rotary_kernel<<<(S_ * NH_ * 16) / 256, 256>>>(qkv);
        split_kernel<<<(S_ * 3 * H_) / 1024, 256>>>(qkv, qh, ql);
        wsplit_kernel<<<dim3(S_ / 32, HD_ / 32, NH_), 256>>>(
            qkv + 2 * HD_, 3 * H_, S_, HD_, 3 * HD_, (long long)HD_ * S_, vth, vtl);

        gemm_bf<0, 256, true, false><<<dim3(S_ / 128, S_ / 256, NH_), 256, SM_256>>>(
            qh, ql, 3 * H_, 3 * HD_,
            qh + HD_, ql + HD_, 3 * H_, 3 * HD_,
            nullptr, scores, nullptr, nullptr, S_, (long long)S_ * S_,
            HD_, inv_sqrt_hd);

        softmax_split_kernel<<<dim3(S_, NH_), 256>>>(scores, ph, pl);

        // ctx = probs @ v, epilogue splits straight into a1h/a1l (bf16)
        gemm_bf<3, 128, false, true><<<dim3(S_ / 128, 1, NH_), 256, SM_128>>>(
            ph, pl, S_, (long long)S_ * S_,
            vth, vtl, S_, (long long)HD_ * S_,
            nullptr, nullptr, a1h, a1l, H_, HD_,
            S_, 1.f);

        // h += ctx @ dense_w + dense_b
        cudaStreamWaitEvent(0, evW[3], 0);
        gemm_bf<2, 256, false, false><<<dim3(S_ / 128, H_ / 256, 1), 256, SM_256>>>(
            a1h, a1l, H_, 0, wdh + (size_t)l * H_ * H_, wdl + (size_t)l * H_ * H_, H_, 0,
            dense_b + (size_t)l * H_, h, nullptr, nullptr, H_, 0, H_, 1.f);

        // join MLP, h += mlp
        cudaStreamWaitEvent(0, evMlp[l], 0);
        add_kernel<<<(S_ * H_) / 1024, 256>>>(h, mlp);
    }

    // Final LN + logits GEMM (joins sW via evW[4])
    ln_split_kernel<<<S_, 256>>>(h, fln_g, fln_b, a1h, a1l);
    cudaStreamWaitEvent(0, evW[4], 0);
    gemm_bf<0, 256, false, false><<<dim3(S_ / 128, V_ / 256, 1), 256, SM_256>>>(
        a1h, a1l, H_, 0, wlh, wll, H_, 0, nullptr,
        out, nullptr, nullptr, V_, 0, H_, 1.f);
}

// round 7
// speedup vs baseline: 4.4631x; 1.2483x over previous
#include <cuda_runtime.h>
#include <cuda_bf16.h>
#include <cuda_fp16.h>
#include <math.h>
#include <stdint.h>

// Problem constants
#define S_    2048
#define H_    2048
#define NH_   16
#define HD_   128
#define ROT_  32
#define FF_   8192
#define L_    2
#define V_    32000
#define EPS_  1e-5f

typedef __nv_bfloat16 bf16;

// ---------------------------------------------------------------------------
// Scratch (static device globals)
// ---------------------------------------------------------------------------
__device__ float g_h  [(size_t)S_ * H_];
__device__ float g_qkv[(size_t)S_ * 3 * H_];
__device__ float g_mlp[(size_t)S_ * H_];
__device__ float g_scores[(size_t)NH_ * S_ * S_];

__device__ bf16 g_a1h[(size_t)S_ * H_];
__device__ bf16 g_a1l[(size_t)S_ * H_];
__device__ bf16 g_a2h[(size_t)S_ * H_];
__device__ bf16 g_a2l[(size_t)S_ * H_];
__device__ bf16 g_fh [(size_t)S_ * FF_];
__device__ bf16 g_fl [(size_t)S_ * FF_];

__device__ bf16 g_qh [(size_t)S_ * 3 * H_];
__device__ bf16 g_ql [(size_t)S_ * 3 * H_];
__device__ bf16 g_vth[(size_t)NH_ * HD_ * S_];
__device__ bf16 g_vtl[(size_t)NH_ * HD_ * S_];
__device__ bf16 g_ph [(size_t)NH_ * S_ * S_];
__device__ bf16 g_pl [(size_t)NH_ * S_ * S_];

// per-GEMM transposed/split weights (bf16 hi/lo)
__device__ bf16 g_wqh [(size_t)L_ * H_ * 3 * H_];
__device__ bf16 g_wql [(size_t)L_ * H_ * 3 * H_];
__device__ bf16 g_wdh [(size_t)L_ * H_ * H_];
__device__ bf16 g_wdl [(size_t)L_ * H_ * H_];
__device__ bf16 g_wf1h[(size_t)L_ * H_ * FF_];
__device__ bf16 g_wf1l[(size_t)L_ * H_ * FF_];
__device__ bf16 g_wf2h[(size_t)L_ * FF_ * H_];
__device__ bf16 g_wf2l[(size_t)L_ * FF_ * H_];

// fp16 single-pass path for the final logits GEMM
__device__ __half g_af [(size_t)S_ * H_];
__device__ __half g_wlf[(size_t)V_ * H_];

// ---------------------------------------------------------------------------
// Helpers
// ---------------------------------------------------------------------------
__device__ __forceinline__ uint32_t smem_u32(const void* p) {
    uint32_t a;
    asm("{ .reg .u64 t; cvta.to.shared.u64 t, %1; cvt.u32.u64 %0, t; }"
        : "=r"(a) : "l"(p));
    return a;
}
__device__ __forceinline__ uint32_t swz(uint32_t off) {
    return off ^ ((off >> 3) & 0x70);
}
__device__ __forceinline__ float gelu_f(float x) {
    float t = tanhf(0.79788456f * x * (1.f + 0.044715f * x * x));
    return 0.5f * x * (1.f + t);
}
__device__ __forceinline__ uint32_t pack2(float x, float y, uint32_t& lo) {
    bf16 hx = __float2bfloat16_rn(x);
    bf16 hy = __float2bfloat16_rn(y);
    bf16 lx = __float2bfloat16_rn(x - __bfloat162float(hx));
    bf16 ly = __float2bfloat16_rn(y - __bfloat162float(hy));
    lo = (uint32_t)__bfloat16_as_ushort(lx) | ((uint32_t)__bfloat16_as_ushort(ly) << 16);
    return (uint32_t)__bfloat16_as_ushort(hx) | ((uint32_t)__bfloat16_as_ushort(hy) << 16);
}
__device__ __forceinline__ void split1(float x, bf16& h, bf16& l) {
    h = __float2bfloat16_rn(x);
    l = __float2bfloat16_rn(x - __bfloat162float(h));
}
__device__ __forceinline__ void ldsm4(uint32_t (&r)[4], uint32_t addr) {
    asm volatile("ldmatrix.sync.aligned.m8n8.x4.shared.b16 {%0,%1,%2,%3}, [%4];"
                 : "=r"(r[0]), "=r"(r[1]), "=r"(r[2]), "=r"(r[3]) : "r"(addr));
}
__device__ __forceinline__ void mma16816(float (&d)[4], const uint32_t (&a)[4],
                                         const uint32_t* b) {
    asm volatile(
        "mma.sync.aligned.m16n8k16.row.col.f32.bf16.bf16.f32 "
        "{%0,%1,%2,%3}, {%4,%5,%6,%7}, {%8,%9}, {%0,%1,%2,%3};"
        : "+f"(d[0]), "+f"(d[1]), "+f"(d[2]), "+f"(d[3])
        : "r"(a[0]), "r"(a[1]), "r"(a[2]), "r"(a[3]), "r"(b[0]), "r"(b[1]));
}
__device__ __forceinline__ void mma16816h(float (&d)[4], const uint32_t (&a)[4],
                                          const uint32_t* b) {
    asm volatile(
        "mma.sync.aligned.m16n8k16.row.col.f32.f16.f16.f32 "
        "{%0,%1,%2,%3}, {%4,%5,%6,%7}, {%8,%9}, {%0,%1,%2,%3};"
        : "+f"(d[0]), "+f"(d[1]), "+f"(d[2]), "+f"(d[3])
        : "r"(a[0]), "r"(a[1]), "r"(a[2]), "r"(a[3]), "r"(b[0]), "r"(b[1]));
}
__device__ __forceinline__ void cpa16(uint32_t s, const void* g) {
    asm volatile("cp.async.cg.shared.global [%0], [%1], 16;" :: "r"(s), "l"(g));
}

// ---------------------------------------------------------------------------
// Transpose + split: W[Kd rows][N cols] fp32 (ldw) -> WTh/WTl[N][Kd] bf16
// ---------------------------------------------------------------------------
__global__ void wsplit_kernel(const float* __restrict__ W, int ldw, int Kd, int N,
                              long long zin, long long zout,
                              bf16* __restrict__ WTh, bf16* __restrict__ WTl) {
    W   += (size_t)blockIdx.z * zin;
    WTh += (size_t)blockIdx.z * zout;
    WTl += (size_t)blockIdx.z * zout;

    __shared__ float s[32][33];
    const int k0 = blockIdx.x * 32;
    const int n0 = blockIdx.y * 32;
    const int tid = threadIdx.x;
    const int r  = tid >> 3;
    const int c4 = (tid & 7) * 4;

    float4 v = *(const float4*)(W + (size_t)(k0 + r) * ldw + n0 + c4);
    s[r][c4 + 0] = v.x; s[r][c4 + 1] = v.y;
    s[r][c4 + 2] = v.z; s[r][c4 + 3] = v.w;
    __syncthreads();

    float x0 = s[c4 + 0][r], x1 = s[c4 + 1][r];
    float x2 = s[c4 + 2][r], x3 = s[c4 + 3][r];
    uint32_t l0, l1;
    uint32_t h0 = pack2(x0, x1, l0);
    uint32_t h1 = pack2(x2, x3, l1);
    size_t o = (size_t)(n0 + r) * Kd + k0 + c4;
    *(uint2*)(WTh + o) = make_uint2(h0, h1);
    *(uint2*)(WTl + o) = make_uint2(l0, l1);
}

// Transpose to fp16 (single): W[Kd][N] fp32 -> WT[N][Kd] half
__global__ void wsplitf_kernel(const float* __restrict__ W, int ldw, int Kd, int N,
                               __half* __restrict__ WT) {
    __shared__ float s[32][33];
    const int k0 = blockIdx.x * 32;
    const int n0 = blockIdx.y * 32;
    const int tid = threadIdx.x;
    const int r  = tid >> 3;
    const int c4 = (tid & 7) * 4;

    float4 v = *(const float4*)(W + (size_t)(k0 + r) * ldw + n0 + c4);
    s[r][c4 + 0] = v.x; s[r][c4 + 1] = v.y;
    s[r][c4 + 2] = v.z; s[r][c4 + 3] = v.w;
    __syncthreads();

    __half2 p0 = __floats2half2_rn(s[c4 + 0][r], s[c4 + 1][r]);
    __half2 p1 = __floats2half2_rn(s[c4 + 2][r], s[c4 + 3][r]);
    size_t o = (size_t)(n0 + r) * Kd + k0 + c4;
    *(__half2*)(WT + o)     = p0;
    *(__half2*)(WT + o + 2) = p1;
}

// ---------------------------------------------------------------------------
// Elementwise fp32 -> bf16 hi/lo split
// ---------------------------------------------------------------------------
__global__ void split_kernel(const float* __restrict__ in,
                             bf16* __restrict__ oh,
                             bf16* __restrict__ ol) {
    int i = (blockIdx.x * 256 + threadIdx.x) * 4;
    float4 v = *(const float4*)(in + i);
    uint32_t l0, l1;
    uint32_t h0 = pack2(v.x, v.y, l0);
    uint32_t h1 = pack2(v.z, v.w, l1);
    *(uint2*)(oh + i) = make_uint2(h0, h1);
    *(uint2*)(ol + i) = make_uint2(l0, l1);
}

// h += m
__global__ void add_kernel(float* __restrict__ h, const float* __restrict__ m) {
    int i = (blockIdx.x * 256 + threadIdx.x) * 4;
    float4 a = *(const float4*)(h + i);
    float4 b = *(const float4*)(m + i);
    a.x += b.x; a.y += b.y; a.z += b.z; a.w += b.w;
    *(float4*)(h + i) = a;
}

// ---------------------------------------------------------------------------
// LayerNorm -> bf16 hi/lo split output
// ---------------------------------------------------------------------------
__global__ void ln_split_kernel(const float* __restrict__ in,
                                const float* __restrict__ g,
                                const float* __restrict__ b,
                                bf16* __restrict__ oh,
                                bf16* __restrict__ ol) {
    const int s = blockIdx.x;
    const int tid = threadIdx.x;
    const float* row = in + (size_t)s * H_;
    __shared__ float red[256];

    float v[8];
    float lsum = 0.f;
#pragma unroll
    for (int i = 0; i < 8; i++) { v[i] = row[tid + i * 256]; lsum += v[i]; }
    red[tid] = lsum; __syncthreads();
    for (int o = 128; o > 0; o >>= 1) {
        if (tid < o) red[tid] += red[tid + o];
        __syncthreads();
    }
    const float mean = red[0] * (1.f / H_);
    __syncthreads();

    float lvar = 0.f;
#pragma unroll
    for (int i = 0; i < 8; i++) { float d = v[i] - mean; lvar += d * d; }
    red[tid] = lvar; __syncthreads();
    for (int o = 128; o > 0; o >>= 1) {
        if (tid < o) red[tid] += red[tid + o];
        __syncthreads();
    }
    const float rstd = rsqrtf(red[0] * (1.f / H_) + EPS_);

#pragma unroll
    for (int i = 0; i < 8; i++) {
        int c = tid + i * 256;
        float val = (v[i] - mean) * rstd * g[c] + b[c];
        bf16 hh, ll;
        split1(val, hh, ll);
        oh[(size_t)s * H_ + c] = hh;
        ol[(size_t)s * H_ + c] = ll;
    }
}

// LayerNorm -> fp16 output (for the final logits GEMM)
__global__ void ln_splitf_kernel(const float* __restrict__ in,
                                 const float* __restrict__ g,
                                 const float* __restrict__ b,
                                 __half* __restrict__ o16) {
    const int s = blockIdx.x;
    const int tid = threadIdx.x;
    const float* row = in + (size_t)s * H_;
    __shared__ float red[256];

    float v[8];
    float lsum = 0.f;
#pragma unroll
    for (int i = 0; i < 8; i++) { v[i] = row[tid + i * 256]; lsum += v[i]; }
    red[tid] = lsum; __syncthreads();
    for (int o = 128; o > 0; o >>= 1) {
        if (tid < o) red[tid] += red[tid + o];
        __syncthreads();
    }
    const float mean = red[0] * (1.f / H_);
    __syncthreads();

    float lvar = 0.f;
#pragma unroll
    for (int i = 0; i < 8; i++) { float d = v[i] - mean; lvar += d * d; }
    red[tid] = lvar; __syncthreads();
    for (int o = 128; o > 0; o >>= 1) {
        if (tid < o) red[tid] += red[tid + o];
        __syncthreads();
    }
    const float rstd = rsqrtf(red[0] * (1.f / H_) + EPS_);

#pragma unroll
    for (int i = 0; i < 8; i++) {
        int c = tid + i * 256;
        float val = (v[i] - mean) * rstd * g[c] + b[c];
        o16[(size_t)s * H_ + c] = __float2half_rn(val);
    }
}

// ---------------------------------------------------------------------------
// Unified bf16x3 tensor-core GEMM, cp.async double-buffered.
//   EPI: 0 = fp32 store, 1 = gelu->split bf16, 2 = fp32 accumulate,
//        3 = split bf16 (no gelu).
// ---------------------------------------------------------------------------
template <int EPI, int BN, bool CAUS, bool CAUSK>
__global__ void __launch_bounds__(256, 1) gemm_bf(
    const bf16* __restrict__ Ah, const bf16* __restrict__ Al, int lda, long long sA,
    const bf16* __restrict__ Bh, const bf16* __restrict__ Bl, int ldb, long long sB,
    const float* __restrict__ bias,
    float* __restrict__ C, bf16* __restrict__ Ch, bf16* __restrict__ Cl,
    int ldc, long long sC,
    int K, float alpha) {

    constexpr int MI  = (BN == 256) ? 4 : 2;
    constexpr int BUF = 32768 + 2 * BN * 128;

    extern __shared__ char smem[];
    const uint32_t sb = smem_u32(smem);
    const int tid  = threadIdx.x;
    const int lane = tid & 31;
    const int wid  = tid >> 5;
    const int wm   = (BN == 256) ? (wid & 1) : (wid & 3);
    const int wn   = (BN == 256) ? (wid >> 1) : (wid >> 2);
    const int row0 = blockIdx.x * 128;
    const int n0   = blockIdx.y * BN;

    if (CAUS && n0 > row0 + 127) return;

    Ah += (size_t)blockIdx.z * sA;  Al += (size_t)blockIdx.z * sA;
    Bh += (size_t)blockIdx.z * sB;  Bl += (size_t)blockIdx.z * sB;
    if (C)  C  += (size_t)blockIdx.z * sC;
    if (Ch) { Ch += (size_t)blockIdx.z * sC; Cl += (size_t)blockIdx.z * sC; }

    float acc[MI][8][4];
#pragma unroll
    for (int i = 0; i < MI; i++)
#pragma unroll
        for (int j = 0; j < 8; j++)
#pragma unroll
            for (int e = 0; e < 4; e++) acc[i][j][e] = 0.f;

    const int nch = CAUSK ? ((row0 + 128) >> 6) : (K >> 6);

    for (int c = 0; c <= nch; c++) {
        if (c < nch) {
            const uint32_t bufo = (uint32_t)(c & 1) * BUF;
            const int k0 = c << 6;
#pragma unroll
            for (int i = 0; i < 4; i++) {
                int idx = tid + i * 256;
                int r  = idx >> 3;
                int cc = (idx & 7) * 8;
                uint32_t soff = swz((uint32_t)(r * 128 + cc * 2));
                size_t go = (size_t)(row0 + r) * lda + k0 + cc;
                cpa16(sb + bufo + soff,         Ah + go);
                cpa16(sb + bufo + 16384 + soff, Al + go);
            }
#pragma unroll
            for (int i = 0; i < BN / 32; i++) {
                int idx = tid + i * 256;
                int r  = idx >> 3;
                int cc = (idx & 7) * 8;
                uint32_t soff = swz((uint32_t)(r * 128 + cc * 2));
                size_t go = (size_t)(n0 + r) * ldb + k0 + cc;
                cpa16(sb + bufo + 32768 + soff,            Bh + go);
                cpa16(sb + bufo + 32768 + BN * 128 + soff, Bl + go);
            }
            asm volatile("cp.async.commit_group;" ::: "memory");
        }
        if (c >= 1) {
            if (c < nch) asm volatile("cp.async.wait_group 1;" ::: "memory");
            else         asm volatile("cp.async.wait_group 0;" ::: "memory");
            __syncthreads();

            const uint32_t bufo = (uint32_t)((c - 1) & 1) * BUF;
            const uint32_t sAh = sb + bufo;
            const uint32_t sAl = sAh + 16384;
            const uint32_t sBh = sAh + 32768;
            const uint32_t sBl = sBh + BN * 128;

#pragma unroll
            for (int ks = 0; ks < 4; ks++) {
                const int kk = ks * 16;
                uint32_t ah[MI][4], al[MI][4];
                {
                    const uint32_t arow = (uint32_t)(wm * (MI * 16) + (lane & 15));
                    const uint32_t acol = (uint32_t)(kk + (lane >> 4) * 8);
#pragma unroll
                    for (int mi = 0; mi < MI; mi++) {
                        uint32_t off = swz((arow + mi * 16) * 128 + acol * 2);
                        ldsm4(ah[mi], sAh + off);
                        ldsm4(al[mi], sAl + off);
                    }
                }
                const uint32_t brow = (uint32_t)(wn * 64 + ((lane >> 4) & 1) * 8 + (lane & 7));
                const uint32_t bcol = (uint32_t)(kk + ((lane >> 3) & 1) * 8);
#pragma unroll
                for (int ng = 0; ng < 4; ng++) {
                    uint32_t bh[4], bl[4];
                    uint32_t off = swz((brow + ng * 16) * 128 + bcol * 2);
                    ldsm4(bh, sBh + off);
                    ldsm4(bl, sBl + off);
#pragma unroll
                    for (int mi = 0; mi < MI; mi++) {
#pragma unroll
                        for (int half = 0; half < 2; half++) {
                            const int nt = ng * 2 + half;
                            mma16816(acc[mi][nt], ah[mi], bh + half * 2);
                            mma16816(acc[mi][nt], ah[mi], bl + half * 2);
                            mma16816(acc[mi][nt], al[mi], bh + half * 2);
                        }
                    }
                }
            }
            __syncthreads();
        }
    }

    // ---- epilogue ----
    const int g = lane >> 2;
    const int t = lane & 3;
#pragma unroll
    for (int mi = 0; mi < MI; mi++) {
        const int r = row0 + wm * (MI * 16) + mi * 16 + g;
#pragma unroll
        for (int nt = 0; nt < 8; nt++) {
            const int col = n0 + wn * 64 + nt * 8 + 2 * t;
            float2 v0 = make_float2(acc[mi][nt][0] * alpha, acc[mi][nt][1] * alpha);
            float2 v1 = make_float2(acc[mi][nt][2] * alpha, acc[mi][nt][3] * alpha);
            if (bias) {
                float2 bv = *(const float2*)(bias + col);
                v0.x += bv.x; v0.y += bv.y;
                v1.x += bv.x; v1.y += bv.y;
            }
            if (EPI == 1 || EPI == 3) {
                if (EPI == 1) {
                    v0.x = gelu_f(v0.x); v0.y = gelu_f(v0.y);
                    v1.x = gelu_f(v1.x); v1.y = gelu_f(v1.y);
                }
                uint32_t l0, l1;
                uint32_t h0 = pack2(v0.x, v0.y, l0);
                uint32_t h1 = pack2(v1.x, v1.y, l1);
                *(uint32_t*)(Ch + (size_t)r * ldc + col) = h0;
                *(uint32_t*)(Cl + (size_t)r * ldc + col) = l0;
                *(uint32_t*)(Ch + (size_t)(r + 8) * ldc + col) = h1;
                *(uint32_t*)(Cl + (size_t)(r + 8) * ldc + col) = l1;
            } else {
                float* p0 = C + (size_t)r * ldc + col;
                float* p1 = C + (size_t)(r + 8) * ldc + col;
                if (EPI == 2) {
                    float2 o0 = *(const float2*)p0;
                    float2 o1 = *(const float2*)p1;
                    v0.x += o0.x; v0.y += o0.y;
                    v1.x += o1.x; v1.y += o1.y;
                }
                *(float2*)p0 = v0;
                *(float2*)p1 = v1;
            }
        }
    }
}

// ---------------------------------------------------------------------------
// Single-pass fp16 GEMM (logits): C[M,N] = A[M,K]h @ B[N,K]h^T, fp32 store.
// CTA 128x256, warps 2m x 4n, BK=64, double-buffered cp.async.
// ---------------------------------------------------------------------------
#define SM_F16 (2 * (16384 + 256 * 128))

__global__ void __launch_bounds__(256, 1) gemm_f16(
    const __half* __restrict__ A, int lda,
    const __half* __restrict__ B, int ldb,
    float* __restrict__ C, int ldc, int K) {

    constexpr int BUF = 16384 + 256 * 128;

    extern __shared__ char smem[];
    const uint32_t sb = smem_u32(smem);
    const int tid  = threadIdx.x;
    const int lane = tid & 31;
    const int wid  = tid >> 5;
    const int wm   = wid & 1;
    const int wn   = wid >> 1;
    const int row0 = blockIdx.x * 128;
    const int n0   = blockIdx.y * 256;

    float acc[4][8][4];
#pragma unroll
    for (int i = 0; i < 4; i++)
#pragma unroll
        for (int j = 0; j < 8; j++)
#pragma unroll
            for (int e = 0; e < 4; e++) acc[i][j][e] = 0.f;

    const int nch = K >> 6;

    for (int c = 0; c <= nch; c++) {
        if (c < nch) {
            const uint32_t bufo = (uint32_t)(c & 1) * BUF;
            const int k0 = c << 6;
#pragma unroll
            for (int i = 0; i < 4; i++) {
                int idx = tid + i * 256;
                int r  = idx >> 3;
                int cc = (idx & 7) * 8;
                uint32_t soff = swz((uint32_t)(r * 128 + cc * 2));
                cpa16(sb + bufo + soff, A + (size_t)(row0 + r) * lda + k0 + cc);
            }
#pragma unroll
            for (int i = 0; i < 8; i++) {
                int idx = tid + i * 256;
                int r  = idx >> 3;
                int cc = (idx & 7) * 8;
                uint32_t soff = swz((uint32_t)(r * 128 + cc * 2));
                cpa16(sb + bufo + 16384 + soff, B + (size_t)(n0 + r) * ldb + k0 + cc);
            }
            asm volatile("cp.async.commit_group;" ::: "memory");
        }
        if (c >= 1) {
            if (c < nch) asm volatile("cp.async.wait_group 1;" ::: "memory");
            else         asm volatile("cp.async.wait_group 0;" ::: "memory");
            __syncthreads();

            const uint32_t bufo = (uint32_t)((c - 1) & 1) * BUF;
            const uint32_t sA = sb + bufo;
            const uint32_t sB = sA + 16384;

#pragma unroll
            for (int ks = 0; ks < 4; ks++) {
                const int kk = ks * 16;
                uint32_t ah[4][4];
                {
                    const uint32_t arow = (uint32_t)(wm * 64 + (lane & 15));
                    const uint32_t acol = (uint32_t)(kk + (lane >> 4) * 8);
#pragma unroll
                    for (int mi = 0; mi < 4; mi++) {
                        uint32_t off = swz((arow + mi * 16) * 128 + acol * 2);
                        ldsm4(ah[mi], sA + off);
                    }
                }
                const uint32_t brow = (uint32_t)(wn * 64 + ((lane >> 4) & 1) * 8 + (lane & 7));
                const uint32_t bcol = (uint32_t)(kk + ((lane >> 3) & 1) * 8);
#pragma unroll
                for (int ng = 0; ng < 4; ng++) {
                    uint32_t bh[4];
                    uint32_t off = swz((brow + ng * 16) * 128 + bcol * 2);
                    ldsm4(bh, sB + off);
#pragma unroll
                    for (int mi = 0; mi < 4; mi++) {
#pragma unroll
                        for (int half = 0; half < 2; half++) {
                            mma16816h(acc[mi][ng * 2 + half], ah[mi], bh + half * 2);
                        }
                    }
                }
            }
            __syncthreads();
        }
    }

    const int g = lane >> 2;
    const int t = lane & 3;
#pragma unroll
    for (int mi = 0; mi < 4; mi++) {
        const int r = row0 + wm * 64 + mi * 16 + g;
#pragma unroll
        for (int nt = 0; nt < 8; nt++) {
            const int col = n0 + wn * 64 + nt * 8 + 2 * t;
            *(float2*)(C + (size_t)r * ldc + col) =
                make_float2(acc[mi][nt][0], acc[mi][nt][1]);
            *(float2*)(C + (size_t)(r + 8) * ldc + col) =
                make_float2(acc[mi][nt][2], acc[mi][nt][3]);
        }
    }
}

// ---------------------------------------------------------------------------
// Embedding gather
// ---------------------------------------------------------------------------
__global__ void embed_kernel(const int* __restrict__ x,
                             const float* __restrict__ embed,
                             float* __restrict__ h) {
    int s = blockIdx.y;
    int c = blockIdx.x * 256 + threadIdx.x;
    h[(size_t)s * H_ + c] = embed[(size_t)x[s] * H_ + c];
}

// ---------------------------------------------------------------------------
// Rotary (in-place on qkv)
// ---------------------------------------------------------------------------
__global__ void rotary_kernel(float* __restrict__ qkv) {
    int idx = blockIdx.x * 256 + threadIdx.x;
    int i = idx & 15;
    int n = (idx >> 4) & 15;
    int s = idx >> 8;
    float inv = expf(-(float)i * 0.575646273248511f);
    float ang = (float)s * inv;
    float sn, cs;
    sincosf(ang, &sn, &cs);
    float* p = qkv + (size_t)s * (3 * H_) + n * (3 * HD_);
    float a = p[i], c2 = p[i + 16];
    p[i]      = a * cs - c2 * sn;
    p[i + 16] = c2 * cs + a * sn;
    float* pk = p + HD_;
    a = pk[i]; c2 = pk[i + 16];
    pk[i]      = a * cs - c2 * sn;
    pk[i + 16] = c2 * cs + a * sn;
}

// ---------------------------------------------------------------------------
// Causal softmax; emits probs as bf16 hi/lo, zeroes k>q.
// ---------------------------------------------------------------------------
__global__ void softmax_split_kernel(float* __restrict__ scores,
                                     bf16* __restrict__ ph,
                                     bf16* __restrict__ pl) {
    const int q = blockIdx.x;
    const int n = blockIdx.y;
    const size_t base = ((size_t)n * S_ + q) * (size_t)S_;
    float* row = scores + base;
    bf16* phr = ph + base;
    bf16* plr = pl + base;
    const int len = q + 1;
    const int tid = threadIdx.x;
    __shared__ float red[256];

    float mx = -3.4e38f;
    for (int i = tid; i < len; i += 256) mx = fmaxf(mx, row[i]);
    red[tid] = mx; __syncthreads();
    for (int o = 128; o > 0; o >>= 1) {
        if (tid < o) red[tid] = fmaxf(red[tid], red[tid + o]);
        __syncthreads();
    }
    mx = red[0]; __syncthreads();

    float sum = 0.f;
    for (int i = tid; i < len; i += 256) {
        float e = expf(row[i] - mx);
        row[i] = e;
        sum += e;
    }
    red[tid] = sum; __syncthreads();
    for (int o = 128; o > 0; o >>= 1) {
        if (tid < o) red[tid] += red[tid + o];
        __syncthreads();
    }
    const float inv = 1.f / red[0];
    for (int i = tid; i < len; i += 256) {
        bf16 hh, ll;
        split1(row[i] * inv, hh, ll);
        phr[i] = hh;
        plr[i] = ll;
    }
    const bf16 z = __float2bfloat16_rn(0.f);
    for (int i = len + tid; i < S_; i += 256) { phr[i] = z; plr[i] = z; }
}

// ---------------------------------------------------------------------------
// Launcher with 3-stream fork/join (capture-safe: full join before return)
// ---------------------------------------------------------------------------
#define SM_256 (2 * (32768 + 2 * 256 * 128))
#define SM_128 (2 * (32768 + 2 * 128 * 128))

extern "C" void kernel_launch(void* const* d_in, const int* in_sizes, int n_in,
                              void* d_out, int out_size) {
    const int*   x        = (const int*)  d_in[0];
    const float* embed    = (const float*)d_in[1];
    const float* ln1_g    = (const float*)d_in[2];
    const float* ln1_b    = (const float*)d_in[3];
    const float* ln2_g    = (const float*)d_in[4];
    const float* ln2_b    = (const float*)d_in[5];
    const float* qkv_w    = (const float*)d_in[6];
    const float* qkv_b    = (const float*)d_in[7];
    const float* dense_w  = (const float*)d_in[8];
    const float* dense_b  = (const float*)d_in[9];
    const float* fc1_w    = (const float*)d_in[10];
    const float* fc1_b    = (const float*)d_in[11];
    const float* fc2_w    = (const float*)d_in[12];
    const float* fc2_b    = (const float*)d_in[13];
    const float* fln_g    = (const float*)d_in[14];
    const float* fln_b    = (const float*)d_in[15];
    const float* logits_w = (const float*)d_in[16];
    float* out = (float*)d_out;

    float *h, *qkv, *mlp, *scores;
    bf16 *a1h, *a1l, *a2h, *a2l, *fh, *fl;
    bf16 *qh, *ql, *vth, *vtl, *ph, *pl;
    bf16 *wqh, *wql, *wdh, *wdl, *wf1h, *wf1l, *wf2h, *wf2l;
    __half *af, *wlf;
    cudaGetSymbolAddress((void**)&h,      g_h);
    cudaGetSymbolAddress((void**)&qkv,    g_qkv);
    cudaGetSymbolAddress((void**)&mlp,    g_mlp);
    cudaGetSymbolAddress((void**)&scores, g_scores);
    cudaGetSymbolAddress((void**)&a1h,    g_a1h);
    cudaGetSymbolAddress((void**)&a1l,    g_a1l);
    cudaGetSymbolAddress((void**)&a2h,    g_a2h);
    cudaGetSymbolAddress((void**)&a2l,    g_a2l);
    cudaGetSymbolAddress((void**)&fh,     g_fh);
    cudaGetSymbolAddress((void**)&fl,     g_fl);
    cudaGetSymbolAddress((void**)&qh,     g_qh);
    cudaGetSymbolAddress((void**)&ql,     g_ql);
    cudaGetSymbolAddress((void**)&vth,    g_vth);
    cudaGetSymbolAddress((void**)&vtl,    g_vtl);
    cudaGetSymbolAddress((void**)&ph,     g_ph);
    cudaGetSymbolAddress((void**)&pl,     g_pl);
    cudaGetSymbolAddress((void**)&wqh,    g_wqh);
    cudaGetSymbolAddress((void**)&wql,    g_wql);
    cudaGetSymbolAddress((void**)&wdh,    g_wdh);
    cudaGetSymbolAddress((void**)&wdl,    g_wdl);
    cudaGetSymbolAddress((void**)&wf1h,   g_wf1h);
    cudaGetSymbolAddress((void**)&wf1l,   g_wf1l);
    cudaGetSymbolAddress((void**)&wf2h,   g_wf2h);
    cudaGetSymbolAddress((void**)&wf2l,   g_wf2l);
    cudaGetSymbolAddress((void**)&af,     g_af);
    cudaGetSymbolAddress((void**)&wlf,    g_wlf);

    cudaFuncSetAttribute((const void*)gemm_bf<0, 256, false, false>,
                         cudaFuncAttributeMaxDynamicSharedMemorySize, SM_256);
    cudaFuncSetAttribute((const void*)gemm_bf<1, 256, false, false>,
                         cudaFuncAttributeMaxDynamicSharedMemorySize, SM_256);
    cudaFuncSetAttribute((const void*)gemm_bf<2, 256, false, false>,
                         cudaFuncAttributeMaxDynamicSharedMemorySize, SM_256);
    cudaFuncSetAttribute((const void*)gemm_bf<0, 256, true, false>,
                         cudaFuncAttributeMaxDynamicSharedMemorySize, SM_256);
    cudaFuncSetAttribute((const void*)gemm_bf<3, 128, false, true>,
                         cudaFuncAttributeMaxDynamicSharedMemorySize, SM_128);
    cudaFuncSetAttribute((const void*)gemm_f16,
                         cudaFuncAttributeMaxDynamicSharedMemorySize, SM_F16);

    // streams/events created once (first call is the non-captured correctness run)
    static cudaStream_t sW = 0, sM = 0;
    static cudaEvent_t evFork, evW[5], evLn2[L_], evMlp[L_];
    if (!sW) {
        cudaStreamCreateWithFlags(&sW, cudaStreamNonBlocking);
        cudaStreamCreateWithFlags(&sM, cudaStreamNonBlocking);
        cudaEventCreateWithFlags(&evFork, cudaEventDisableTiming);
        for (int i = 0; i < 5; i++) cudaEventCreateWithFlags(&evW[i], cudaEventDisableTiming);
        for (int i = 0; i < L_; i++) {
            cudaEventCreateWithFlags(&evLn2[i], cudaEventDisableTiming);
            cudaEventCreateWithFlags(&evMlp[i], cudaEventDisableTiming);
        }
    }

    const float inv_sqrt_hd = 0.08838834764831845f;  // 1/sqrt(128)

    // ---- fork ----
    cudaEventRecord(evFork, 0);
    cudaStreamWaitEvent(sW, evFork, 0);
    cudaStreamWaitEvent(sM, evFork, 0);

    // ---- weight prep on sW (z batches both layers) ----
    wsplit_kernel<<<dim3(H_ / 32, 3 * H_ / 32, L_), 256, 0, sW>>>(
        qkv_w, 3 * H_, H_, 3 * H_, (long long)H_ * 3 * H_, (long long)H_ * 3 * H_, wqh, wql);
    cudaEventRecord(evW[0], sW);
    wsplit_kernel<<<dim3(H_ / 32, FF_ / 32, L_), 256, 0, sW>>>(
        fc1_w, FF_, H_, FF_, (long long)H_ * FF_, (long long)H_ * FF_, wf1h, wf1l);
    cudaEventRecord(evW[1], sW);
    wsplit_kernel<<<dim3(FF_ / 32, H_ / 32, L_), 256, 0, sW>>>(
        fc2_w, H_, FF_, H_, (long long)FF_ * H_, (long long)FF_ * H_, wf2h, wf2l);
    cudaEventRecord(evW[2], sW);
    wsplit_kernel<<<dim3(H_ / 32, H_ / 32, L_), 256, 0, sW>>>(
        dense_w, H_, H_, H_, (long long)H_ * H_, (long long)H_ * H_, wdh, wdl);
    cudaEventRecord(evW[3], sW);
    wsplitf_kernel<<<dim3(H_ / 32, V_ / 32, 1), 256, 0, sW>>>(
        logits_w, V_, H_, V_, wlf);
    cudaEventRecord(evW[4], sW);

    // ---- main path ----
    embed_kernel<<<dim3(H_ / 256, S_), 256>>>(x, embed, h);

    for (int l = 0; l < L_; l++) {
        // both LN read pre-update h
        ln_split_kernel<<<S_, 256>>>(h, ln1_g + (size_t)l * H_, ln1_b + (size_t)l * H_,
                                     a1h, a1l);
        ln_split_kernel<<<S_, 256>>>(h, ln2_g + (size_t)l * H_, ln2_b + (size_t)l * H_,
                                     a2h, a2l);
        cudaEventRecord(evLn2[l], 0);

        // ---- MLP branch on sM ----
        cudaStreamWaitEvent(sM, evLn2[l], 0);
        cudaStreamWaitEvent(sM, evW[1], 0);
        gemm_bf<1, 256, false, false><<<dim3(S_ / 128, FF_ / 256, 1), 256, SM_256, sM>>>(
            a2h, a2l, H_, 0, wf1h + (size_t)l * H_ * FF_, wf1l + (size_t)l * H_ * FF_, H_, 0,
            fc1_b + (size_t)l * FF_, nullptr, fh, fl, FF_, 0, H_, 1.f);
        cudaStreamWaitEvent(sM, evW[2], 0);
        gemm_bf<0, 256, false, false><<<dim3(S_ / 128, H_ / 256, 1), 256, SM_256, sM>>>(
            fh, fl, FF_, 0, wf2h + (size_t)l * FF_ * H_, wf2l + (size_t)l * FF_ * H_, FF_, 0,
            fc2_b + (size_t)l * H_, mlp, nullptr, nullptr, H_, 0, FF_, 1.f);
        cudaEventRecord(evMlp[l], sM);

        // ---- attention branch on main ----
        cudaStreamWaitEvent(0, evW[0], 0);
        gemm_bf<0, 256, false, false><<<dim3(S_ / 128, 3 * H_ / 256, 1), 256, SM_256>>>(
            a1h, a1l, H_, 0, wqh + (size_t)l * H_ * 3 * H_, wql + (size_t)l * H_ * 3 * H_, H_, 0,
            qkv_b + (size_t)l * 3 * H_, qkv, nullptr, nullptr, 3 * H_, 0, H_, 1.f);

        rotary_kernel<<<(S_ * NH_ * 16) / 256, 256>>>(qkv);
        split_kernel<<<(S_ * 3 * H_) / 1024, 256>>>(qkv, qh, ql);
        wsplit_kernel<<<dim3(S_ / 32, HD_ / 32, NH_), 256>>>(
            qkv + 2 * HD_, 3 * H_, S_, HD_, 3 * HD_, (long long)HD_ * S_, vth, vtl);

        gemm_bf<0, 256, true, false><<<dim3(S_ / 128, S_ / 256, NH_), 256, SM_256>>>(
            qh, ql, 3 * H_, 3 * HD_,
            qh + HD_, ql + HD_, 3 * H_, 3 * HD_,
            nullptr, scores, nullptr, nullptr, S_, (long long)S_ * S_,
            HD_, inv_sqrt_hd);

        softmax_split_kernel<<<dim3(S_, NH_), 256>>>(scores, ph, pl);

        // ctx = probs @ v, epilogue splits straight into a1h/a1l (bf16)
        gemm_bf<3, 128, false, true><<<dim3(S_ / 128, 1, NH_), 256, SM_128>>>(
            ph, pl, S_, (long long)S_ * S_,
            vth, vtl, S_, (long long)HD_ * S_,
            nullptr, nullptr, a1h, a1l, H_, HD_,
            S_, 1.f);

        // h += ctx @ dense_w + dense_b
        cudaStreamWaitEvent(0, evW[3], 0);
        gemm_bf<2, 256, false, false><<<dim3(S_ / 128, H_ / 256, 1), 256, SM_256>>>(
            a1h, a1l, H_, 0, wdh + (size_t)l * H_ * H_, wdl + (size_t)l * H_ * H_, H_, 0,
            dense_b + (size_t)l * H_, h, nullptr, nullptr, H_, 0, H_, 1.f);

        // join MLP, h += mlp
        cudaStreamWaitEvent(0, evMlp[l], 0);
        add_kernel<<<(S_ * H_) / 1024, 256>>>(h, mlp);
    }

    // Final LN (fp16) + single-pass fp16 logits GEMM (joins sW via evW[4])
    ln_splitf_kernel<<<S_, 256>>>(h, fln_g, fln_b, af);
    cudaStreamWaitEvent(0, evW[4], 0);
    gemm_f16<<<dim3(S_ / 128, V_ / 256), 256, SM_F16>>>(
        af, H_, wlf, H_, out, V_, H_);
}

// round 8
// speedup vs baseline: 4.6922x; 1.0513x over previous
#include <cuda_runtime.h>
#include <cuda_bf16.h>
#include <cuda_fp16.h>
#include <math.h>
#include <stdint.h>

// Problem constants
#define S_    2048
#define H_    2048
#define NH_   16
#define HD_   128
#define ROT_  32
#define FF_   8192
#define L_    2
#define V_    32000
#define EPS_  1e-5f

typedef __nv_bfloat16 bf16;

// ---------------------------------------------------------------------------
// Scratch (static device globals)
// ---------------------------------------------------------------------------
__device__ float g_h  [(size_t)S_ * H_];
__device__ float g_qkv[(size_t)S_ * 3 * H_];
__device__ float g_mlp[(size_t)S_ * H_];
__device__ float g_scores[(size_t)NH_ * S_ * S_];

__device__ bf16 g_a1h[(size_t)S_ * H_];
__device__ bf16 g_a1l[(size_t)S_ * H_];
__device__ bf16 g_a2h[(size_t)S_ * H_];
__device__ bf16 g_a2l[(size_t)S_ * H_];
__device__ bf16 g_fh [(size_t)S_ * FF_];
__device__ bf16 g_fl [(size_t)S_ * FF_];

// fp16 attention buffers
__device__ __half g_qf [(size_t)S_ * 3 * H_];
__device__ __half g_vtf[(size_t)NH_ * HD_ * S_];
__device__ __half g_pf [(size_t)NH_ * S_ * S_];

// per-GEMM transposed/split weights (bf16 hi/lo)
__device__ bf16 g_wqh [(size_t)L_ * H_ * 3 * H_];
__device__ bf16 g_wql [(size_t)L_ * H_ * 3 * H_];
__device__ bf16 g_wdh [(size_t)L_ * H_ * H_];
__device__ bf16 g_wdl [(size_t)L_ * H_ * H_];
__device__ bf16 g_wf1h[(size_t)L_ * H_ * FF_];
__device__ bf16 g_wf1l[(size_t)L_ * H_ * FF_];
__device__ bf16 g_wf2h[(size_t)L_ * FF_ * H_];
__device__ bf16 g_wf2l[(size_t)L_ * FF_ * H_];

// fp16 single-pass path for the final logits GEMM
__device__ __half g_af [(size_t)S_ * H_];
__device__ __half g_wlf[(size_t)V_ * H_];

// ---------------------------------------------------------------------------
// Helpers
// ---------------------------------------------------------------------------
__device__ __forceinline__ uint32_t smem_u32(const void* p) {
    uint32_t a;
    asm("{ .reg .u64 t; cvta.to.shared.u64 t, %1; cvt.u32.u64 %0, t; }"
        : "=r"(a) : "l"(p));
    return a;
}
__device__ __forceinline__ uint32_t swz(uint32_t off) {
    return off ^ ((off >> 3) & 0x70);
}
__device__ __forceinline__ float gelu_f(float x) {
    float t = tanhf(0.79788456f * x * (1.f + 0.044715f * x * x));
    return 0.5f * x * (1.f + t);
}
__device__ __forceinline__ uint32_t pack2(float x, float y, uint32_t& lo) {
    bf16 hx = __float2bfloat16_rn(x);
    bf16 hy = __float2bfloat16_rn(y);
    bf16 lx = __float2bfloat16_rn(x - __bfloat162float(hx));
    bf16 ly = __float2bfloat16_rn(y - __bfloat162float(hy));
    lo = (uint32_t)__bfloat16_as_ushort(lx) | ((uint32_t)__bfloat16_as_ushort(ly) << 16);
    return (uint32_t)__bfloat16_as_ushort(hx) | ((uint32_t)__bfloat16_as_ushort(hy) << 16);
}
__device__ __forceinline__ void split1(float x, bf16& h, bf16& l) {
    h = __float2bfloat16_rn(x);
    l = __float2bfloat16_rn(x - __bfloat162float(h));
}
__device__ __forceinline__ void ldsm4(uint32_t (&r)[4], uint32_t addr) {
    asm volatile("ldmatrix.sync.aligned.m8n8.x4.shared.b16 {%0,%1,%2,%3}, [%4];"
                 : "=r"(r[0]), "=r"(r[1]), "=r"(r[2]), "=r"(r[3]) : "r"(addr));
}
__device__ __forceinline__ void mma16816(float (&d)[4], const uint32_t (&a)[4],
                                         const uint32_t* b) {
    asm volatile(
        "mma.sync.aligned.m16n8k16.row.col.f32.bf16.bf16.f32 "
        "{%0,%1,%2,%3}, {%4,%5,%6,%7}, {%8,%9}, {%0,%1,%2,%3};"
        : "+f"(d[0]), "+f"(d[1]), "+f"(d[2]), "+f"(d[3])
        : "r"(a[0]), "r"(a[1]), "r"(a[2]), "r"(a[3]), "r"(b[0]), "r"(b[1]));
}
__device__ __forceinline__ void mma16816h(float (&d)[4], const uint32_t (&a)[4],
                                          const uint32_t* b) {
    asm volatile(
        "mma.sync.aligned.m16n8k16.row.col.f32.f16.f16.f32 "
        "{%0,%1,%2,%3}, {%4,%5,%6,%7}, {%8,%9}, {%0,%1,%2,%3};"
        : "+f"(d[0]), "+f"(d[1]), "+f"(d[2]), "+f"(d[3])
        : "r"(a[0]), "r"(a[1]), "r"(a[2]), "r"(a[3]), "r"(b[0]), "r"(b[1]));
}
__device__ __forceinline__ void cpa16(uint32_t s, const void* g) {
    asm volatile("cp.async.cg.shared.global [%0], [%1], 16;" :: "r"(s), "l"(g));
}

// ---------------------------------------------------------------------------
// Transpose + split: W[Kd rows][N cols] fp32 (ldw) -> WTh/WTl[N][Kd] bf16
// ---------------------------------------------------------------------------
__global__ void wsplit_kernel(const float* __restrict__ W, int ldw, int Kd, int N,
                              long long zin, long long zout,
                              bf16* __restrict__ WTh, bf16* __restrict__ WTl) {
    W   += (size_t)blockIdx.z * zin;
    WTh += (size_t)blockIdx.z * zout;
    WTl += (size_t)blockIdx.z * zout;

    __shared__ float s[32][33];
    const int k0 = blockIdx.x * 32;
    const int n0 = blockIdx.y * 32;
    const int tid = threadIdx.x;
    const int r  = tid >> 3;
    const int c4 = (tid & 7) * 4;

    float4 v = *(const float4*)(W + (size_t)(k0 + r) * ldw + n0 + c4);
    s[r][c4 + 0] = v.x; s[r][c4 + 1] = v.y;
    s[r][c4 + 2] = v.z; s[r][c4 + 3] = v.w;
    __syncthreads();

    float x0 = s[c4 + 0][r], x1 = s[c4 + 1][r];
    float x2 = s[c4 + 2][r], x3 = s[c4 + 3][r];
    uint32_t l0, l1;
    uint32_t h0 = pack2(x0, x1, l0);
    uint32_t h1 = pack2(x2, x3, l1);
    size_t o = (size_t)(n0 + r) * Kd + k0 + c4;
    *(uint2*)(WTh + o) = make_uint2(h0, h1);
    *(uint2*)(WTl + o) = make_uint2(l0, l1);
}

// Transpose to fp16 (single): W[Kd][N] fp32 (ldw) -> WT[N][Kd] half, z-batched
__global__ void wsplitf_kernel(const float* __restrict__ W, int ldw, int Kd, int N,
                               long long zin, long long zout,
                               __half* __restrict__ WT) {
    W  += (size_t)blockIdx.z * zin;
    WT += (size_t)blockIdx.z * zout;

    __shared__ float s[32][33];
    const int k0 = blockIdx.x * 32;
    const int n0 = blockIdx.y * 32;
    const int tid = threadIdx.x;
    const int r  = tid >> 3;
    const int c4 = (tid & 7) * 4;

    float4 v = *(const float4*)(W + (size_t)(k0 + r) * ldw + n0 + c4);
    s[r][c4 + 0] = v.x; s[r][c4 + 1] = v.y;
    s[r][c4 + 2] = v.z; s[r][c4 + 3] = v.w;
    __syncthreads();

    __half2 p0 = __floats2half2_rn(s[c4 + 0][r], s[c4 + 1][r]);
    __half2 p1 = __floats2half2_rn(s[c4 + 2][r], s[c4 + 3][r]);
    size_t o = (size_t)(n0 + r) * Kd + k0 + c4;
    *(__half2*)(WT + o)     = p0;
    *(__half2*)(WT + o + 2) = p1;
}

// ---------------------------------------------------------------------------
// Elementwise fp32 -> fp16
// ---------------------------------------------------------------------------
__global__ void splitf_kernel(const float* __restrict__ in,
                              __half* __restrict__ o16) {
    int i = (blockIdx.x * 256 + threadIdx.x) * 4;
    float4 v = *(const float4*)(in + i);
    __half2 p0 = __floats2half2_rn(v.x, v.y);
    __half2 p1 = __floats2half2_rn(v.z, v.w);
    *(__half2*)(o16 + i)     = p0;
    *(__half2*)(o16 + i + 2) = p1;
}

// h += m
__global__ void add_kernel(float* __restrict__ h, const float* __restrict__ m) {
    int i = (blockIdx.x * 256 + threadIdx.x) * 4;
    float4 a = *(const float4*)(h + i);
    float4 b = *(const float4*)(m + i);
    a.x += b.x; a.y += b.y; a.z += b.z; a.w += b.w;
    *(float4*)(h + i) = a;
}

// ---------------------------------------------------------------------------
// LayerNorm -> bf16 hi/lo split output
// ---------------------------------------------------------------------------
__global__ void ln_split_kernel(const float* __restrict__ in,
                                const float* __restrict__ g,
                                const float* __restrict__ b,
                                bf16* __restrict__ oh,
                                bf16* __restrict__ ol) {
    const int s = blockIdx.x;
    const int tid = threadIdx.x;
    const float* row = in + (size_t)s * H_;
    __shared__ float red[256];

    float v[8];
    float lsum = 0.f;
#pragma unroll
    for (int i = 0; i < 8; i++) { v[i] = row[tid + i * 256]; lsum += v[i]; }
    red[tid] = lsum; __syncthreads();
    for (int o = 128; o > 0; o >>= 1) {
        if (tid < o) red[tid] += red[tid + o];
        __syncthreads();
    }
    const float mean = red[0] * (1.f / H_);
    __syncthreads();

    float lvar = 0.f;
#pragma unroll
    for (int i = 0; i < 8; i++) { float d = v[i] - mean; lvar += d * d; }
    red[tid] = lvar; __syncthreads();
    for (int o = 128; o > 0; o >>= 1) {
        if (tid < o) red[tid] += red[tid + o];
        __syncthreads();
    }
    const float rstd = rsqrtf(red[0] * (1.f / H_) + EPS_);

#pragma unroll
    for (int i = 0; i < 8; i++) {
        int c = tid + i * 256;
        float val = (v[i] - mean) * rstd * g[c] + b[c];
        bf16 hh, ll;
        split1(val, hh, ll);
        oh[(size_t)s * H_ + c] = hh;
        ol[(size_t)s * H_ + c] = ll;
    }
}

// LayerNorm -> fp16 output (for the final logits GEMM)
__global__ void ln_splitf_kernel(const float* __restrict__ in,
                                 const float* __restrict__ g,
                                 const float* __restrict__ b,
                                 __half* __restrict__ o16) {
    const int s = blockIdx.x;
    const int tid = threadIdx.x;
    const float* row = in + (size_t)s * H_;
    __shared__ float red[256];

    float v[8];
    float lsum = 0.f;
#pragma unroll
    for (int i = 0; i < 8; i++) { v[i] = row[tid + i * 256]; lsum += v[i]; }
    red[tid] = lsum; __syncthreads();
    for (int o = 128; o > 0; o >>= 1) {
        if (tid < o) red[tid] += red[tid + o];
        __syncthreads();
    }
    const float mean = red[0] * (1.f / H_);
    __syncthreads();

    float lvar = 0.f;
#pragma unroll
    for (int i = 0; i < 8; i++) { float d = v[i] - mean; lvar += d * d; }
    red[tid] = lvar; __syncthreads();
    for (int o = 128; o > 0; o >>= 1) {
        if (tid < o) red[tid] += red[tid + o];
        __syncthreads();
    }
    const float rstd = rsqrtf(red[0] * (1.f / H_) + EPS_);

#pragma unroll
    for (int i = 0; i < 8; i++) {
        int c = tid + i * 256;
        float val = (v[i] - mean) * rstd * g[c] + b[c];
        o16[(size_t)s * H_ + c] = __float2half_rn(val);
    }
}

// ---------------------------------------------------------------------------
// Unified bf16x3 tensor-core GEMM, cp.async double-buffered.
//   EPI: 0 = fp32 store, 1 = gelu->split bf16, 2 = fp32 accumulate,
//        3 = split bf16 (no gelu).
// ---------------------------------------------------------------------------
template <int EPI, int BN, bool CAUS, bool CAUSK>
__global__ void __launch_bounds__(256, 1) gemm_bf(
    const bf16* __restrict__ Ah, const bf16* __restrict__ Al, int lda, long long sA,
    const bf16* __restrict__ Bh, const bf16* __restrict__ Bl, int ldb, long long sB,
    const float* __restrict__ bias,
    float* __restrict__ C, bf16* __restrict__ Ch, bf16* __restrict__ Cl,
    int ldc, long long sC,
    int K, float alpha) {

    constexpr int MI  = (BN == 256) ? 4 : 2;
    constexpr int BUF = 32768 + 2 * BN * 128;

    extern __shared__ char smem[];
    const uint32_t sb = smem_u32(smem);
    const int tid  = threadIdx.x;
    const int lane = tid & 31;
    const int wid  = tid >> 5;
    const int wm   = (BN == 256) ? (wid & 1) : (wid & 3);
    const int wn   = (BN == 256) ? (wid >> 1) : (wid >> 2);
    const int row0 = blockIdx.x * 128;
    const int n0   = blockIdx.y * BN;

    if (CAUS && n0 > row0 + 127) return;

    Ah += (size_t)blockIdx.z * sA;  Al += (size_t)blockIdx.z * sA;
    Bh += (size_t)blockIdx.z * sB;  Bl += (size_t)blockIdx.z * sB;
    if (C)  C  += (size_t)blockIdx.z * sC;
    if (Ch) { Ch += (size_t)blockIdx.z * sC; Cl += (size_t)blockIdx.z * sC; }

    float acc[MI][8][4];
#pragma unroll
    for (int i = 0; i < MI; i++)
#pragma unroll
        for (int j = 0; j < 8; j++)
#pragma unroll
            for (int e = 0; e < 4; e++) acc[i][j][e] = 0.f;

    const int nch = CAUSK ? ((row0 + 128) >> 6) : (K >> 6);

    for (int c = 0; c <= nch; c++) {
        if (c < nch) {
            const uint32_t bufo = (uint32_t)(c & 1) * BUF;
            const int k0 = c << 6;
#pragma unroll
            for (int i = 0; i < 4; i++) {
                int idx = tid + i * 256;
                int r  = idx >> 3;
                int cc = (idx & 7) * 8;
                uint32_t soff = swz((uint32_t)(r * 128 + cc * 2));
                size_t go = (size_t)(row0 + r) * lda + k0 + cc;
                cpa16(sb + bufo + soff,         Ah + go);
                cpa16(sb + bufo + 16384 + soff, Al + go);
            }
#pragma unroll
            for (int i = 0; i < BN / 32; i++) {
                int idx = tid + i * 256;
                int r  = idx >> 3;
                int cc = (idx & 7) * 8;
                uint32_t soff = swz((uint32_t)(r * 128 + cc * 2));
                size_t go = (size_t)(n0 + r) * ldb + k0 + cc;
                cpa16(sb + bufo + 32768 + soff,            Bh + go);
                cpa16(sb + bufo + 32768 + BN * 128 + soff, Bl + go);
            }
            asm volatile("cp.async.commit_group;" ::: "memory");
        }
        if (c >= 1) {
            if (c < nch) asm volatile("cp.async.wait_group 1;" ::: "memory");
            else         asm volatile("cp.async.wait_group 0;" ::: "memory");
            __syncthreads();

            const uint32_t bufo = (uint32_t)((c - 1) & 1) * BUF;
            const uint32_t sAh = sb + bufo;
            const uint32_t sAl = sAh + 16384;
            const uint32_t sBh = sAh + 32768;
            const uint32_t sBl = sBh + BN * 128;

#pragma unroll
            for (int ks = 0; ks < 4; ks++) {
                const int kk = ks * 16;
                uint32_t ah[MI][4], al[MI][4];
                {
                    const uint32_t arow = (uint32_t)(wm * (MI * 16) + (lane & 15));
                    const uint32_t acol = (uint32_t)(kk + (lane >> 4) * 8);
#pragma unroll
                    for (int mi = 0; mi < MI; mi++) {
                        uint32_t off = swz((arow + mi * 16) * 128 + acol * 2);
                        ldsm4(ah[mi], sAh + off);
                        ldsm4(al[mi], sAl + off);
                    }
                }
                const uint32_t brow = (uint32_t)(wn * 64 + ((lane >> 4) & 1) * 8 + (lane & 7));
                const uint32_t bcol = (uint32_t)(kk + ((lane >> 3) & 1) * 8);
#pragma unroll
                for (int ng = 0; ng < 4; ng++) {
                    uint32_t bh[4], bl[4];
                    uint32_t off = swz((brow + ng * 16) * 128 + bcol * 2);
                    ldsm4(bh, sBh + off);
                    ldsm4(bl, sBl + off);
#pragma unroll
                    for (int mi = 0; mi < MI; mi++) {
#pragma unroll
                        for (int half = 0; half < 2; half++) {
                            const int nt = ng * 2 + half;
                            mma16816(acc[mi][nt], ah[mi], bh + half * 2);
                            mma16816(acc[mi][nt], ah[mi], bl + half * 2);
                            mma16816(acc[mi][nt], al[mi], bh + half * 2);
                        }
                    }
                }
            }
            __syncthreads();
        }
    }

    // ---- epilogue ----
    const int g = lane >> 2;
    const int t = lane & 3;
#pragma unroll
    for (int mi = 0; mi < MI; mi++) {
        const int r = row0 + wm * (MI * 16) + mi * 16 + g;
#pragma unroll
        for (int nt = 0; nt < 8; nt++) {
            const int col = n0 + wn * 64 + nt * 8 + 2 * t;
            float2 v0 = make_float2(acc[mi][nt][0] * alpha, acc[mi][nt][1] * alpha);
            float2 v1 = make_float2(acc[mi][nt][2] * alpha, acc[mi][nt][3] * alpha);
            if (bias) {
                float2 bv = *(const float2*)(bias + col);
                v0.x += bv.x; v0.y += bv.y;
                v1.x += bv.x; v1.y += bv.y;
            }
            if (EPI == 1 || EPI == 3) {
                if (EPI == 1) {
                    v0.x = gelu_f(v0.x); v0.y = gelu_f(v0.y);
                    v1.x = gelu_f(v1.x); v1.y = gelu_f(v1.y);
                }
                uint32_t l0, l1;
                uint32_t h0 = pack2(v0.x, v0.y, l0);
                uint32_t h1 = pack2(v1.x, v1.y, l1);
                *(uint32_t*)(Ch + (size_t)r * ldc + col) = h0;
                *(uint32_t*)(Cl + (size_t)r * ldc + col) = l0;
                *(uint32_t*)(Ch + (size_t)(r + 8) * ldc + col) = h1;
                *(uint32_t*)(Cl + (size_t)(r + 8) * ldc + col) = l1;
            } else {
                float* p0 = C + (size_t)r * ldc + col;
                float* p1 = C + (size_t)(r + 8) * ldc + col;
                if (EPI == 2) {
                    float2 o0 = *(const float2*)p0;
                    float2 o1 = *(const float2*)p1;
                    v0.x += o0.x; v0.y += o0.y;
                    v1.x += o1.x; v1.y += o1.y;
                }
                *(float2*)p0 = v0;
                *(float2*)p1 = v1;
            }
        }
    }
}

// ---------------------------------------------------------------------------
// Single-pass fp16 GEMM: C[M,N] = alpha * A[M,K] @ B[N,K]^T.
//   EPI: 0 = fp32 store, 3 = split bf16 hi/lo (for ctx -> dense).
//   CAUS/CAUSK as in gemm_bf. z-batched via sA/sB/sC.
// ---------------------------------------------------------------------------
template <int EPI, int BN, bool CAUS, bool CAUSK>
__global__ void __launch_bounds__(256, 1) gemm_hf(
    const __half* __restrict__ A, int lda, long long sA,
    const __half* __restrict__ B, int ldb, long long sB,
    float* __restrict__ C, bf16* __restrict__ Ch, bf16* __restrict__ Cl,
    int ldc, long long sC,
    int K, float alpha) {

    constexpr int MI  = (BN == 256) ? 4 : 2;
    constexpr int BUF = 16384 + BN * 128;

    extern __shared__ char smem[];
    const uint32_t sb = smem_u32(smem);
    const int tid  = threadIdx.x;
    const int lane = tid & 31;
    const int wid  = tid >> 5;
    const int wm   = (BN == 256) ? (wid & 1) : (wid & 3);
    const int wn   = (BN == 256) ? (wid >> 1) : (wid >> 2);
    const int row0 = blockIdx.x * 128;
    const int n0   = blockIdx.y * BN;

    if (CAUS && n0 > row0 + 127) return;

    A += (size_t)blockIdx.z * sA;
    B += (size_t)blockIdx.z * sB;
    if (C)  C  += (size_t)blockIdx.z * sC;
    if (Ch) { Ch += (size_t)blockIdx.z * sC; Cl += (size_t)blockIdx.z * sC; }

    float acc[MI][8][4];
#pragma unroll
    for (int i = 0; i < MI; i++)
#pragma unroll
        for (int j = 0; j < 8; j++)
#pragma unroll
            for (int e = 0; e < 4; e++) acc[i][j][e] = 0.f;

    const int nch = CAUSK ? ((row0 + 128) >> 6) : (K >> 6);

    for (int c = 0; c <= nch; c++) {
        if (c < nch) {
            const uint32_t bufo = (uint32_t)(c & 1) * BUF;
            const int k0 = c << 6;
#pragma unroll
            for (int i = 0; i < 4; i++) {
                int idx = tid + i * 256;
                int r  = idx >> 3;
                int cc = (idx & 7) * 8;
                uint32_t soff = swz((uint32_t)(r * 128 + cc * 2));
                cpa16(sb + bufo + soff, A + (size_t)(row0 + r) * lda + k0 + cc);
            }
#pragma unroll
            for (int i = 0; i < BN / 32; i++) {
                int idx = tid + i * 256;
                int r  = idx >> 3;
                int cc = (idx & 7) * 8;
                uint32_t soff = swz((uint32_t)(r * 128 + cc * 2));
                cpa16(sb + bufo + 16384 + soff, B + (size_t)(n0 + r) * ldb + k0 + cc);
            }
            asm volatile("cp.async.commit_group;" ::: "memory");
        }
        if (c >= 1) {
            if (c < nch) asm volatile("cp.async.wait_group 1;" ::: "memory");
            else         asm volatile("cp.async.wait_group 0;" ::: "memory");
            __syncthreads();

            const uint32_t bufo = (uint32_t)((c - 1) & 1) * BUF;
            const uint32_t sA16 = sb + bufo;
            const uint32_t sB16 = sA16 + 16384;

#pragma unroll
            for (int ks = 0; ks < 4; ks++) {
                const int kk = ks * 16;
                uint32_t ah[MI][4];
                {
                    const uint32_t arow = (uint32_t)(wm * (MI * 16) + (lane & 15));
                    const uint32_t acol = (uint32_t)(kk + (lane >> 4) * 8);
#pragma unroll
                    for (int mi = 0; mi < MI; mi++) {
                        uint32_t off = swz((arow + mi * 16) * 128 + acol * 2);
                        ldsm4(ah[mi], sA16 + off);
                    }
                }
                const uint32_t brow = (uint32_t)(wn * 64 + ((lane >> 4) & 1) * 8 + (lane & 7));
                const uint32_t bcol = (uint32_t)(kk + ((lane >> 3) & 1) * 8);
#pragma unroll
                for (int ng = 0; ng < 4; ng++) {
                    uint32_t bh[4];
                    uint32_t off = swz((brow + ng * 16) * 128 + bcol * 2);
                    ldsm4(bh, sB16 + off);
#pragma unroll
                    for (int mi = 0; mi < MI; mi++) {
#pragma unroll
                        for (int half = 0; half < 2; half++) {
                            mma16816h(acc[mi][ng * 2 + half], ah[mi], bh + half * 2);
                        }
                    }
                }
            }
            __syncthreads();
        }
    }

    const int g = lane >> 2;
    const int t = lane & 3;
#pragma unroll
    for (int mi = 0; mi < MI; mi++) {
        const int r = row0 + wm * (MI * 16) + mi * 16 + g;
#pragma unroll
        for (int nt = 0; nt < 8; nt++) {
            const int col = n0 + wn * 64 + nt * 8 + 2 * t;
            float2 v0 = make_float2(acc[mi][nt][0] * alpha, acc[mi][nt][1] * alpha);
            float2 v1 = make_float2(acc[mi][nt][2] * alpha, acc[mi][nt][3] * alpha);
            if (EPI == 3) {
                uint32_t l0, l1;
                uint32_t h0 = pack2(v0.x, v0.y, l0);
                uint32_t h1 = pack2(v1.x, v1.y, l1);
                *(uint32_t*)(Ch + (size_t)r * ldc + col) = h0;
                *(uint32_t*)(Cl + (size_t)r * ldc + col) = l0;
                *(uint32_t*)(Ch + (size_t)(r + 8) * ldc + col) = h1;
                *(uint32_t*)(Cl + (size_t)(r + 8) * ldc + col) = l1;
            } else {
                *(float2*)(C + (size_t)r * ldc + col)       = v0;
                *(float2*)(C + (size_t)(r + 8) * ldc + col) = v1;
            }
        }
    }
}

// ---------------------------------------------------------------------------
// Embedding gather
// ---------------------------------------------------------------------------
__global__ void embed_kernel(const int* __restrict__ x,
                             const float* __restrict__ embed,
                             float* __restrict__ h) {
    int s = blockIdx.y;
    int c = blockIdx.x * 256 + threadIdx.x;
    h[(size_t)s * H_ + c] = embed[(size_t)x[s] * H_ + c];
}

// ---------------------------------------------------------------------------
// Rotary (in-place on qkv)
// ---------------------------------------------------------------------------
__global__ void rotary_kernel(float* __restrict__ qkv) {
    int idx = blockIdx.x * 256 + threadIdx.x;
    int i = idx & 15;
    int n = (idx >> 4) & 15;
    int s = idx >> 8;
    float inv = expf(-(float)i * 0.575646273248511f);
    float ang = (float)s * inv;
    float sn, cs;
    sincosf(ang, &sn, &cs);
    float* p = qkv + (size_t)s * (3 * H_) + n * (3 * HD_);
    float a = p[i], c2 = p[i + 16];
    p[i]      = a * cs - c2 * sn;
    p[i + 16] = c2 * cs + a * sn;
    float* pk = p + HD_;
    a = pk[i]; c2 = pk[i + 16];
    pk[i]      = a * cs - c2 * sn;
    pk[i + 16] = c2 * cs + a * sn;
}

// ---------------------------------------------------------------------------
// Causal softmax; emits probs as fp16, zeroes k>q.
// ---------------------------------------------------------------------------
__global__ void softmax_f16_kernel(float* __restrict__ scores,
                                   __half* __restrict__ pf) {
    const int q = blockIdx.x;
    const int n = blockIdx.y;
    const size_t base = ((size_t)n * S_ + q) * (size_t)S_;
    float* row = scores + base;
    __half* pr = pf + base;
    const int len = q + 1;
    const int tid = threadIdx.x;
    __shared__ float red[256];

    float mx = -3.4e38f;
    for (int i = tid; i < len; i += 256) mx = fmaxf(mx, row[i]);
    red[tid] = mx; __syncthreads();
    for (int o = 128; o > 0; o >>= 1) {
        if (tid < o) red[tid] = fmaxf(red[tid], red[tid + o]);
        __syncthreads();
    }
    mx = red[0]; __syncthreads();

    float sum = 0.f;
    for (int i = tid; i < len; i += 256) {
        float e = expf(row[i] - mx);
        row[i] = e;
        sum += e;
    }
    red[tid] = sum; __syncthreads();
    for (int o = 128; o > 0; o >>= 1) {
        if (tid < o) red[tid] += red[tid + o];
        __syncthreads();
    }
    const float inv = 1.f / red[0];
    for (int i = tid; i < len; i += 256)
        pr[i] = __float2half_rn(row[i] * inv);
    const __half z = __float2half_rn(0.f);
    for (int i = len + tid; i < S_; i += 256) pr[i] = z;
}

// ---------------------------------------------------------------------------
// Launcher with 3-stream fork/join (capture-safe: full join before return)
// ---------------------------------------------------------------------------
#define SM_256 (2 * (32768 + 2 * 256 * 128))
#define SM_128 (2 * (32768 + 2 * 128 * 128))
#define SM_H256 (2 * (16384 + 256 * 128))
#define SM_H128 (2 * (16384 + 128 * 128))

extern "C" void kernel_launch(void* const* d_in, const int* in_sizes, int n_in,
                              void* d_out, int out_size) {
    const int*   x        = (const int*)  d_in[0];
    const float* embed    = (const float*)d_in[1];
    const float* ln1_g    = (const float*)d_in[2];
    const float* ln1_b    = (const float*)d_in[3];
    const float* ln2_g    = (const float*)d_in[4];
    const float* ln2_b    = (const float*)d_in[5];
    const float* qkv_w    = (const float*)d_in[6];
    const float* qkv_b    = (const float*)d_in[7];
    const float* dense_w  = (const float*)d_in[8];
    const float* dense_b  = (const float*)d_in[9];
    const float* fc1_w    = (const float*)d_in[10];
    const float* fc1_b    = (const float*)d_in[11];
    const float* fc2_w    = (const float*)d_in[12];
    const float* fc2_b    = (const float*)d_in[13];
    const float* fln_g    = (const float*)d_in[14];
    const float* fln_b    = (const float*)d_in[15];
    const float* logits_w = (const float*)d_in[16];
    float* out = (float*)d_out;

    float *h, *qkv, *mlp, *scores;
    bf16 *a1h, *a1l, *a2h, *a2l, *fh, *fl;
    bf16 *wqh, *wql, *wdh, *wdl, *wf1h, *wf1l, *wf2h, *wf2l;
    __half *qf, *vtf, *pf, *af, *wlf;
    cudaGetSymbolAddress((void**)&h,      g_h);
    cudaGetSymbolAddress((void**)&qkv,    g_qkv);
    cudaGetSymbolAddress((void**)&mlp,    g_mlp);
    cudaGetSymbolAddress((void**)&scores, g_scores);
    cudaGetSymbolAddress((void**)&a1h,    g_a1h);
    cudaGetSymbolAddress((void**)&a1l,    g_a1l);
    cudaGetSymbolAddress((void**)&a2h,    g_a2h);
    cudaGetSymbolAddress((void**)&a2l,    g_a2l);
    cudaGetSymbolAddress((void**)&fh,     g_fh);
    cudaGetSymbolAddress((void**)&fl,     g_fl);
    cudaGetSymbolAddress((void**)&qf,     g_qf);
    cudaGetSymbolAddress((void**)&vtf,    g_vtf);
    cudaGetSymbolAddress((void**)&pf,     g_pf);
    cudaGetSymbolAddress((void**)&wqh,    g_wqh);
    cudaGetSymbolAddress((void**)&wql,    g_wql);
    cudaGetSymbolAddress((void**)&wdh,    g_wdh);
    cudaGetSymbolAddress((void**)&wdl,    g_wdl);
    cudaGetSymbolAddress((void**)&wf1h,   g_wf1h);
    cudaGetSymbolAddress((void**)&wf1l,   g_wf1l);
    cudaGetSymbolAddress((void**)&wf2h,   g_wf2h);
    cudaGetSymbolAddress((void**)&wf2l,   g_wf2l);
    cudaGetSymbolAddress((void**)&af,     g_af);
    cudaGetSymbolAddress((void**)&wlf,    g_wlf);

    cudaFuncSetAttribute((const void*)gemm_bf<0, 256, false, false>,
                         cudaFuncAttributeMaxDynamicSharedMemorySize, SM_256);
    cudaFuncSetAttribute((const void*)gemm_bf<1, 256, false, false>,
                         cudaFuncAttributeMaxDynamicSharedMemorySize, SM_256);
    cudaFuncSetAttribute((const void*)gemm_bf<2, 256, false, false>,
                         cudaFuncAttributeMaxDynamicSharedMemorySize, SM_256);
    cudaFuncSetAttribute((const void*)gemm_hf<0, 256, true, false>,
                         cudaFuncAttributeMaxDynamicSharedMemorySize, SM_H256);
    cudaFuncSetAttribute((const void*)gemm_hf<3, 128, false, true>,
                         cudaFuncAttributeMaxDynamicSharedMemorySize, SM_H128);
    cudaFuncSetAttribute((const void*)gemm_hf<0, 256, false, false>,
                         cudaFuncAttributeMaxDynamicSharedMemorySize, SM_H256);

    // streams/events created once (first call is the non-captured correctness run)
    static cudaStream_t sW = 0, sM = 0;
    static cudaEvent_t evFork, evW[5], evLn2[L_], evMlp[L_];
    if (!sW) {
        cudaStreamCreateWithFlags(&sW, cudaStreamNonBlocking);
        cudaStreamCreateWithFlags(&sM, cudaStreamNonBlocking);
        cudaEventCreateWithFlags(&evFork, cudaEventDisableTiming);
        for (int i = 0; i < 5; i++) cudaEventCreateWithFlags(&evW[i], cudaEventDisableTiming);
        for (int i = 0; i < L_; i++) {
            cudaEventCreateWithFlags(&evLn2[i], cudaEventDisableTiming);
            cudaEventCreateWithFlags(&evMlp[i], cudaEventDisableTiming);
        }
    }

    const float inv_sqrt_hd = 0.08838834764831845f;  // 1/sqrt(128)

    // ---- fork ----
    cudaEventRecord(evFork, 0);
    cudaStreamWaitEvent(sW, evFork, 0);
    cudaStreamWaitEvent(sM, evFork, 0);

    // ---- weight prep on sW (z batches both layers) ----
    wsplit_kernel<<<dim3(H_ / 32, 3 * H_ / 32, L_), 256, 0, sW>>>(
        qkv_w, 3 * H_, H_, 3 * H_, (long long)H_ * 3 * H_, (long long)H_ * 3 * H_, wqh, wql);
    cudaEventRecord(evW[0], sW);
    wsplit_kernel<<<dim3(H_ / 32, FF_ / 32, L_), 256, 0, sW>>>(
        fc1_w, FF_, H_, FF_, (long long)H_ * FF_, (long long)H_ * FF_, wf1h, wf1l);
    cudaEventRecord(evW[1], sW);
    wsplit_kernel<<<dim3(FF_ / 32, H_ / 32, L_), 256, 0, sW>>>(
        fc2_w, H_, FF_, H_, (long long)FF_ * H_, (long long)FF_ * H_, wf2h, wf2l);
    cudaEventRecord(evW[2], sW);
    wsplit_kernel<<<dim3(H_ / 32, H_ / 32, L_), 256, 0, sW>>>(
        dense_w, H_, H_, H_, (long long)H_ * H_, (long long)H_ * H_, wdh, wdl);
    cudaEventRecord(evW[3], sW);
    wsplitf_kernel<<<dim3(H_ / 32, V_ / 32, 1), 256, 0, sW>>>(
        logits_w, V_, H_, V_, 0, 0, wlf);
    cudaEventRecord(evW[4], sW);

    // ---- main path ----
    embed_kernel<<<dim3(H_ / 256, S_), 256>>>(x, embed, h);

    for (int l = 0; l < L_; l++) {
        // both LN read pre-update h
        ln_split_kernel<<<S_, 256>>>(h, ln1_g + (size_t)l * H_, ln1_b + (size_t)l * H_,
                                     a1h, a1l);
        ln_split_kernel<<<S_, 256>>>(h, ln2_g + (size_t)l * H_, ln2_b + (size_t)l * H_,
                                     a2h, a2l);
        cudaEventRecord(evLn2[l], 0);

        // ---- MLP branch on sM ----
        cudaStreamWaitEvent(sM, evLn2[l], 0);
        cudaStreamWaitEvent(sM, evW[1], 0);
        gemm_bf<1, 256, false, false><<<dim3(S_ / 128, FF_ / 256, 1), 256, SM_256, sM>>>(
            a2h, a2l, H_, 0, wf1h + (size_t)l * H_ * FF_, wf1l + (size_t)l * H_ * FF_, H_, 0,
            fc1_b + (size_t)l * FF_, nullptr, fh, fl, FF_, 0, H_, 1.f);
        cudaStreamWaitEvent(sM, evW[2], 0);
        gemm_bf<0, 256, false, false><<<dim3(S_ / 128, H_ / 256, 1), 256, SM_256, sM>>>(
            fh, fl, FF_, 0, wf2h + (size_t)l * FF_ * H_, wf2l + (size_t)l * FF_ * H_, FF_, 0,
            fc2_b + (size_t)l * H_, mlp, nullptr, nullptr, H_, 0, FF_, 1.f);
        cudaEventRecord(evMlp[l], sM);

        // ---- attention branch on main ----
        cudaStreamWaitEvent(0, evW[0], 0);
        gemm_bf<0, 256, false, false><<<dim3(S_ / 128, 3 * H_ / 256, 1), 256, SM_256>>>(
            a1h, a1l, H_, 0, wqh + (size_t)l * H_ * 3 * H_, wql + (size_t)l * H_ * 3 * H_, H_, 0,
            qkv_b + (size_t)l * 3 * H_, qkv, nullptr, nullptr, 3 * H_, 0, H_, 1.f);

        rotary_kernel<<<(S_ * NH_ * 16) / 256, 256>>>(qkv);
        splitf_kernel<<<(S_ * 3 * H_) / 1024, 256>>>(qkv, qf);
        wsplitf_kernel<<<dim3(S_ / 32, HD_ / 32, NH_), 256>>>(
            qkv + 2 * HD_, 3 * H_, S_, HD_, 3 * HD_, (long long)HD_ * S_, vtf);

        // scores = q @ k^T * 1/sqrt(HD)  (fp16 single pass, causal block-skip)
        gemm_hf<0, 256, true, false><<<dim3(S_ / 128, S_ / 256, NH_), 256, SM_H256>>>(
            qf, 3 * H_, 3 * HD_,
            qf + HD_, 3 * H_, 3 * HD_,
            scores, nullptr, nullptr, S_, (long long)S_ * S_,
            HD_, inv_sqrt_hd);

        softmax_f16_kernel<<<dim3(S_, NH_), 256>>>(scores, pf);

        // ctx = probs @ v  (fp16 single pass, causal K-limit), split -> a1h/a1l
        gemm_hf<3, 128, false, true><<<dim3(S_ / 128, 1, NH_), 256, SM_H128>>>(
            pf, S_, (long long)S_ * S_,
            vtf, S_, (long long)HD_ * S_,
            nullptr, a1h, a1l, H_, HD_,
            S_, 1.f);

        // h += ctx @ dense_w + dense_b  (bf16x3)
        cudaStreamWaitEvent(0, evW[3], 0);
        gemm_bf<2, 256, false, false><<<dim3(S_ / 128, H_ / 256, 1), 256, SM_256>>>(
            a1h, a1l, H_, 0, wdh + (size_t)l * H_ * H_, wdl + (size_t)l * H_ * H_, H_, 0,
            dense_b + (size_t)l * H_, h, nullptr, nullptr, H_, 0, H_, 1.f);

        // join MLP, h += mlp
        cudaStreamWaitEvent(0, evMlp[l], 0);
        add_kernel<<<(S_ * H_) / 1024, 256>>>(h, mlp);
    }

    // Final LN (fp16) + single-pass fp16 logits GEMM (joins sW via evW[4])
    ln_splitf_kernel<<<S_, 256>>>(h, fln_g, fln_b, af);
    cudaStreamWaitEvent(0, evW[4], 0);
    gemm_hf<0, 256, false, false><<<dim3(S_ / 128, V_ / 256, 1), 256, SM_H256>>>(
        af, H_, 0, wlf, H_, 0, out, nullptr, nullptr, V_, 0, H_, 1.f);
}

// round 9
// speedup vs baseline: 5.8203x; 1.2404x over previous
#include <cuda_runtime.h>
#include <cuda_bf16.h>
#include <cuda_fp16.h>
#include <math.h>
#include <stdint.h>

// Problem constants
#define S_    2048
#define H_    2048
#define NH_   16
#define HD_   128
#define ROT_  32
#define FF_   8192
#define L_    2
#define V_    32000
#define EPS_  1e-5f

// ---------------------------------------------------------------------------
// Scratch (static device globals)
// ---------------------------------------------------------------------------
__device__ float g_h  [(size_t)S_ * H_];
__device__ float g_qkv[(size_t)S_ * 3 * H_];
__device__ float g_mlp[(size_t)S_ * H_];
__device__ float g_scores[(size_t)NH_ * S_ * S_];

// fp16 hi/lo activation buffers
__device__ __half g_a1h[(size_t)S_ * H_];
__device__ __half g_a1l[(size_t)S_ * H_];
__device__ __half g_a2h[(size_t)S_ * H_];
__device__ __half g_a2l[(size_t)S_ * H_];
__device__ __half g_fhh[(size_t)S_ * FF_];
__device__ __half g_fll[(size_t)S_ * FF_];

// fp16 attention buffers
__device__ __half g_qf [(size_t)S_ * 3 * H_];
__device__ __half g_vtf[(size_t)NH_ * HD_ * S_];
__device__ __half g_pf [(size_t)NH_ * S_ * S_];

// per-GEMM transposed fp16 weights
__device__ __half g_wq [(size_t)L_ * H_ * 3 * H_];
__device__ __half g_wd [(size_t)L_ * H_ * H_];
__device__ __half g_wf1[(size_t)L_ * H_ * FF_];
__device__ __half g_wf2[(size_t)L_ * FF_ * H_];
__device__ __half g_wlf[(size_t)V_ * H_];

// final-LN fp16 activations
__device__ __half g_af [(size_t)S_ * H_];

// ---------------------------------------------------------------------------
// Helpers
// ---------------------------------------------------------------------------
__device__ __forceinline__ uint32_t smem_u32(const void* p) {
    uint32_t a;
    asm("{ .reg .u64 t; cvta.to.shared.u64 t, %1; cvt.u32.u64 %0, t; }"
        : "=r"(a) : "l"(p));
    return a;
}
__device__ __forceinline__ uint32_t swz(uint32_t off) {
    return off ^ ((off >> 3) & 0x70);
}
__device__ __forceinline__ float gelu_f(float x) {
    float t = tanhf(0.79788456f * x * (1.f + 0.044715f * x * x));
    return 0.5f * x * (1.f + t);
}
// fp16 hi/lo split of a pair -> packed hi word + lo word
__device__ __forceinline__ uint32_t pack2h(float x, float y, uint32_t& lo) {
    __half hx = __float2half_rn(x);
    __half hy = __float2half_rn(y);
    __half lx = __float2half_rn(x - __half2float(hx));
    __half ly = __float2half_rn(y - __half2float(hy));
    lo = (uint32_t)__half_as_ushort(lx) | ((uint32_t)__half_as_ushort(ly) << 16);
    return (uint32_t)__half_as_ushort(hx) | ((uint32_t)__half_as_ushort(hy) << 16);
}
__device__ __forceinline__ void split1h(float x, __half& h, __half& l) {
    h = __float2half_rn(x);
    l = __float2half_rn(x - __half2float(h));
}
__device__ __forceinline__ void ldsm4(uint32_t (&r)[4], uint32_t addr) {
    asm volatile("ldmatrix.sync.aligned.m8n8.x4.shared.b16 {%0,%1,%2,%3}, [%4];"
                 : "=r"(r[0]), "=r"(r[1]), "=r"(r[2]), "=r"(r[3]) : "r"(addr));
}
__device__ __forceinline__ void mma16816h(float (&d)[4], const uint32_t (&a)[4],
                                          const uint32_t* b) {
    asm volatile(
        "mma.sync.aligned.m16n8k16.row.col.f32.f16.f16.f32 "
        "{%0,%1,%2,%3}, {%4,%5,%6,%7}, {%8,%9}, {%0,%1,%2,%3};"
        : "+f"(d[0]), "+f"(d[1]), "+f"(d[2]), "+f"(d[3])
        : "r"(a[0]), "r"(a[1]), "r"(a[2]), "r"(a[3]), "r"(b[0]), "r"(b[1]));
}
__device__ __forceinline__ void cpa16(uint32_t s, const void* g) {
    asm volatile("cp.async.cg.shared.global [%0], [%1], 16;" :: "r"(s), "l"(g));
}

// ---------------------------------------------------------------------------
// Transpose to fp16: W[Kd rows][N cols] fp32 (ldw) -> WT[N][Kd] half, z-batched
// ---------------------------------------------------------------------------
__global__ void wsplitf_kernel(const float* __restrict__ W, int ldw, int Kd, int N,
                               long long zin, long long zout,
                               __half* __restrict__ WT) {
    W  += (size_t)blockIdx.z * zin;
    WT += (size_t)blockIdx.z * zout;

    __shared__ float s[32][33];
    const int k0 = blockIdx.x * 32;
    const int n0 = blockIdx.y * 32;
    const int tid = threadIdx.x;
    const int r  = tid >> 3;
    const int c4 = (tid & 7) * 4;

    float4 v = *(const float4*)(W + (size_t)(k0 + r) * ldw + n0 + c4);
    s[r][c4 + 0] = v.x; s[r][c4 + 1] = v.y;
    s[r][c4 + 2] = v.z; s[r][c4 + 3] = v.w;
    __syncthreads();

    __half2 p0 = __floats2half2_rn(s[c4 + 0][r], s[c4 + 1][r]);
    __half2 p1 = __floats2half2_rn(s[c4 + 2][r], s[c4 + 3][r]);
    size_t o = (size_t)(n0 + r) * Kd + k0 + c4;
    *(__half2*)(WT + o)     = p0;
    *(__half2*)(WT + o + 2) = p1;
}

// ---------------------------------------------------------------------------
// Elementwise fp32 -> fp16
// ---------------------------------------------------------------------------
__global__ void splitf_kernel(const float* __restrict__ in,
                              __half* __restrict__ o16) {
    int i = (blockIdx.x * 256 + threadIdx.x) * 4;
    float4 v = *(const float4*)(in + i);
    *(__half2*)(o16 + i)     = __floats2half2_rn(v.x, v.y);
    *(__half2*)(o16 + i + 2) = __floats2half2_rn(v.z, v.w);
}

// h += m
__global__ void add_kernel(float* __restrict__ h, const float* __restrict__ m) {
    int i = (blockIdx.x * 256 + threadIdx.x) * 4;
    float4 a = *(const float4*)(h + i);
    float4 b = *(const float4*)(m + i);
    a.x += b.x; a.y += b.y; a.z += b.z; a.w += b.w;
    *(float4*)(h + i) = a;
}

// ---------------------------------------------------------------------------
// LayerNorm -> fp16 hi/lo split output
// ---------------------------------------------------------------------------
__global__ void ln_split2_kernel(const float* __restrict__ in,
                                 const float* __restrict__ g,
                                 const float* __restrict__ b,
                                 __half* __restrict__ oh,
                                 __half* __restrict__ ol) {
    const int s = blockIdx.x;
    const int tid = threadIdx.x;
    const float* row = in + (size_t)s * H_;
    __shared__ float red[256];

    float v[8];
    float lsum = 0.f;
#pragma unroll
    for (int i = 0; i < 8; i++) { v[i] = row[tid + i * 256]; lsum += v[i]; }
    red[tid] = lsum; __syncthreads();
    for (int o = 128; o > 0; o >>= 1) {
        if (tid < o) red[tid] += red[tid + o];
        __syncthreads();
    }
    const float mean = red[0] * (1.f / H_);
    __syncthreads();

    float lvar = 0.f;
#pragma unroll
    for (int i = 0; i < 8; i++) { float d = v[i] - mean; lvar += d * d; }
    red[tid] = lvar; __syncthreads();
    for (int o = 128; o > 0; o >>= 1) {
        if (tid < o) red[tid] += red[tid + o];
        __syncthreads();
    }
    const float rstd = rsqrtf(red[0] * (1.f / H_) + EPS_);

#pragma unroll
    for (int i = 0; i < 8; i++) {
        int c = tid + i * 256;
        float val = (v[i] - mean) * rstd * g[c] + b[c];
        __half hh, ll;
        split1h(val, hh, ll);
        oh[(size_t)s * H_ + c] = hh;
        ol[(size_t)s * H_ + c] = ll;
    }
}

// LayerNorm -> fp16 single output (final logits GEMM input)
__global__ void ln_splitf_kernel(const float* __restrict__ in,
                                 const float* __restrict__ g,
                                 const float* __restrict__ b,
                                 __half* __restrict__ o16) {
    const int s = blockIdx.x;
    const int tid = threadIdx.x;
    const float* row = in + (size_t)s * H_;
    __shared__ float red[256];

    float v[8];
    float lsum = 0.f;
#pragma unroll
    for (int i = 0; i < 8; i++) { v[i] = row[tid + i * 256]; lsum += v[i]; }
    red[tid] = lsum; __syncthreads();
    for (int o = 128; o > 0; o >>= 1) {
        if (tid < o) red[tid] += red[tid + o];
        __syncthreads();
    }
    const float mean = red[0] * (1.f / H_);
    __syncthreads();

    float lvar = 0.f;
#pragma unroll
    for (int i = 0; i < 8; i++) { float d = v[i] - mean; lvar += d * d; }
    red[tid] = lvar; __syncthreads();
    for (int o = 128; o > 0; o >>= 1) {
        if (tid < o) red[tid] += red[tid + o];
        __syncthreads();
    }
    const float rstd = rsqrtf(red[0] * (1.f / H_) + EPS_);

#pragma unroll
    for (int i = 0; i < 8; i++) {
        int c = tid + i * 256;
        float val = (v[i] - mean) * rstd * g[c] + b[c];
        o16[(size_t)s * H_ + c] = __float2half_rn(val);
    }
}

// ---------------------------------------------------------------------------
// 2-pass fp16 GEMM (dense path): C = (Ah+Al) @ W^T (+bias).
//   A: Ah/Al [M][K] fp16 hi/lo, W: [N][K] fp16.
//   EPI: 0 = fp32 store, 1 = gelu -> fp16 hi/lo, 2 = fp32 accumulate.
//   CTA 128 x 256, warps 2m x 4n, BK=64, double-buffered cp.async.
// ---------------------------------------------------------------------------
#define SM_G2 (2 * (32768 + 256 * 128))

template <int EPI>
__global__ void __launch_bounds__(256, 1) gemm2(
    const __half* __restrict__ Ah, const __half* __restrict__ Al, int lda,
    const __half* __restrict__ W, int ldb,
    const float* __restrict__ bias,
    float* __restrict__ C, __half* __restrict__ Ch, __half* __restrict__ Cl,
    int ldc, int K) {

    constexpr int BUF = 32768 + 256 * 128;

    extern __shared__ char smem[];
    const uint32_t sb = smem_u32(smem);
    const int tid  = threadIdx.x;
    const int lane = tid & 31;
    const int wid  = tid >> 5;
    const int wm   = wid & 1;
    const int wn   = wid >> 1;
    const int row0 = blockIdx.x * 128;
    const int n0   = blockIdx.y * 256;

    float acc[4][8][4];
#pragma unroll
    for (int i = 0; i < 4; i++)
#pragma unroll
        for (int j = 0; j < 8; j++)
#pragma unroll
            for (int e = 0; e < 4; e++) acc[i][j][e] = 0.f;

    const int nch = K >> 6;

    for (int c = 0; c <= nch; c++) {
        if (c < nch) {
            const uint32_t bufo = (uint32_t)(c & 1) * BUF;
            const int k0 = c << 6;
#pragma unroll
            for (int i = 0; i < 4; i++) {
                int idx = tid + i * 256;
                int r  = idx >> 3;
                int cc = (idx & 7) * 8;
                uint32_t soff = swz((uint32_t)(r * 128 + cc * 2));
                size_t go = (size_t)(row0 + r) * lda + k0 + cc;
                cpa16(sb + bufo + soff,         Ah + go);
                cpa16(sb + bufo + 16384 + soff, Al + go);
            }
#pragma unroll
            for (int i = 0; i < 8; i++) {
                int idx = tid + i * 256;
                int r  = idx >> 3;
                int cc = (idx & 7) * 8;
                uint32_t soff = swz((uint32_t)(r * 128 + cc * 2));
                cpa16(sb + bufo + 32768 + soff, W + (size_t)(n0 + r) * ldb + k0 + cc);
            }
            asm volatile("cp.async.commit_group;" ::: "memory");
        }
        if (c >= 1) {
            if (c < nch) asm volatile("cp.async.wait_group 1;" ::: "memory");
            else         asm volatile("cp.async.wait_group 0;" ::: "memory");
            __syncthreads();

            const uint32_t bufo = (uint32_t)((c - 1) & 1) * BUF;
            const uint32_t sAh = sb + bufo;
            const uint32_t sAl = sAh + 16384;
            const uint32_t sW  = sAh + 32768;

#pragma unroll
            for (int ks = 0; ks < 4; ks++) {
                const int kk = ks * 16;
                uint32_t ah[4][4], al[4][4];
                {
                    const uint32_t arow = (uint32_t)(wm * 64 + (lane & 15));
                    const uint32_t acol = (uint32_t)(kk + (lane >> 4) * 8);
#pragma unroll
                    for (int mi = 0; mi < 4; mi++) {
                        uint32_t off = swz((arow + mi * 16) * 128 + acol * 2);
                        ldsm4(ah[mi], sAh + off);
                        ldsm4(al[mi], sAl + off);
                    }
                }
                const uint32_t brow = (uint32_t)(wn * 64 + ((lane >> 4) & 1) * 8 + (lane & 7));
                const uint32_t bcol = (uint32_t)(kk + ((lane >> 3) & 1) * 8);
#pragma unroll
                for (int ng = 0; ng < 4; ng++) {
                    uint32_t bw[4];
                    uint32_t off = swz((brow + ng * 16) * 128 + bcol * 2);
                    ldsm4(bw, sW + off);
#pragma unroll
                    for (int mi = 0; mi < 4; mi++) {
#pragma unroll
                        for (int half = 0; half < 2; half++) {
                            const int nt = ng * 2 + half;
                            mma16816h(acc[mi][nt], ah[mi], bw + half * 2);
                            mma16816h(acc[mi][nt], al[mi], bw + half * 2);
                        }
                    }
                }
            }
            __syncthreads();
        }
    }

    // ---- epilogue ----
    const int g = lane >> 2;
    const int t = lane & 3;
#pragma unroll
    for (int mi = 0; mi < 4; mi++) {
        const int r = row0 + wm * 64 + mi * 16 + g;
#pragma unroll
        for (int nt = 0; nt < 8; nt++) {
            const int col = n0 + wn * 64 + nt * 8 + 2 * t;
            float2 v0 = make_float2(acc[mi][nt][0], acc[mi][nt][1]);
            float2 v1 = make_float2(acc[mi][nt][2], acc[mi][nt][3]);
            if (bias) {
                float2 bv = *(const float2*)(bias + col);
                v0.x += bv.x; v0.y += bv.y;
                v1.x += bv.x; v1.y += bv.y;
            }
            if (EPI == 1) {
                v0.x = gelu_f(v0.x); v0.y = gelu_f(v0.y);
                v1.x = gelu_f(v1.x); v1.y = gelu_f(v1.y);
                uint32_t l0, l1;
                uint32_t h0 = pack2h(v0.x, v0.y, l0);
                uint32_t h1 = pack2h(v1.x, v1.y, l1);
                *(uint32_t*)(Ch + (size_t)r * ldc + col) = h0;
                *(uint32_t*)(Cl + (size_t)r * ldc + col) = l0;
                *(uint32_t*)(Ch + (size_t)(r + 8) * ldc + col) = h1;
                *(uint32_t*)(Cl + (size_t)(r + 8) * ldc + col) = l1;
            } else {
                float* p0 = C + (size_t)r * ldc + col;
                float* p1 = C + (size_t)(r + 8) * ldc + col;
                if (EPI == 2) {
                    float2 o0 = *(const float2*)p0;
                    float2 o1 = *(const float2*)p1;
                    v0.x += o0.x; v0.y += o0.y;
                    v1.x += o1.x; v1.y += o1.y;
                }
                *(float2*)p0 = v0;
                *(float2*)p1 = v1;
            }
        }
    }
}

// ---------------------------------------------------------------------------
// Single-pass fp16 GEMM: C[M,N] = alpha * A[M,K] @ B[N,K]^T.
//   EPI: 0 = fp32 store, 3 = fp16 hi/lo split (ctx -> dense input).
//   CAUS/CAUSK causal block-skip / causal K-limit. z-batched via sA/sB/sC.
// ---------------------------------------------------------------------------
template <int EPI, int BN, bool CAUS, bool CAUSK>
__global__ void __launch_bounds__(256, 1) gemm_hf(
    const __half* __restrict__ A, int lda, long long sA,
    const __half* __restrict__ B, int ldb, long long sB,
    float* __restrict__ C, __half* __restrict__ Ch, __half* __restrict__ Cl,
    int ldc, long long sC,
    int K, float alpha) {

    constexpr int MI  = (BN == 256) ? 4 : 2;
    constexpr int BUF = 16384 + BN * 128;

    extern __shared__ char smem[];
    const uint32_t sb = smem_u32(smem);
    const int tid  = threadIdx.x;
    const int lane = tid & 31;
    const int wid  = tid >> 5;
    const int wm   = (BN == 256) ? (wid & 1) : (wid & 3);
    const int wn   = (BN == 256) ? (wid >> 1) : (wid >> 2);
    const int row0 = blockIdx.x * 128;
    const int n0   = blockIdx.y * BN;

    if (CAUS && n0 > row0 + 127) return;

    A += (size_t)blockIdx.z * sA;
    B += (size_t)blockIdx.z * sB;
    if (C)  C  += (size_t)blockIdx.z * sC;
    if (Ch) { Ch += (size_t)blockIdx.z * sC; Cl += (size_t)blockIdx.z * sC; }

    float acc[MI][8][4];
#pragma unroll
    for (int i = 0; i < MI; i++)
#pragma unroll
        for (int j = 0; j < 8; j++)
#pragma unroll
            for (int e = 0; e < 4; e++) acc[i][j][e] = 0.f;

    const int nch = CAUSK ? ((row0 + 128) >> 6) : (K >> 6);

    for (int c = 0; c <= nch; c++) {
        if (c < nch) {
            const uint32_t bufo = (uint32_t)(c & 1) * BUF;
            const int k0 = c << 6;
#pragma unroll
            for (int i = 0; i < 4; i++) {
                int idx = tid + i * 256;
                int r  = idx >> 3;
                int cc = (idx & 7) * 8;
                uint32_t soff = swz((uint32_t)(r * 128 + cc * 2));
                cpa16(sb + bufo + soff, A + (size_t)(row0 + r) * lda + k0 + cc);
            }
#pragma unroll
            for (int i = 0; i < BN / 32; i++) {
                int idx = tid + i * 256;
                int r  = idx >> 3;
                int cc = (idx & 7) * 8;
                uint32_t soff = swz((uint32_t)(r * 128 + cc * 2));
                cpa16(sb + bufo + 16384 + soff, B + (size_t)(n0 + r) * ldb + k0 + cc);
            }
            asm volatile("cp.async.commit_group;" ::: "memory");
        }
        if (c >= 1) {
            if (c < nch) asm volatile("cp.async.wait_group 1;" ::: "memory");
            else         asm volatile("cp.async.wait_group 0;" ::: "memory");
            __syncthreads();

            const uint32_t bufo = (uint32_t)((c - 1) & 1) * BUF;
            const uint32_t sA16 = sb + bufo;
            const uint32_t sB16 = sA16 + 16384;

#pragma unroll
            for (int ks = 0; ks < 4; ks++) {
                const int kk = ks * 16;
                uint32_t ah[MI][4];
                {
                    const uint32_t arow = (uint32_t)(wm * (MI * 16) + (lane & 15));
                    const uint32_t acol = (uint32_t)(kk + (lane >> 4) * 8);
#pragma unroll
                    for (int mi = 0; mi < MI; mi++) {
                        uint32_t off = swz((arow + mi * 16) * 128 + acol * 2);
                        ldsm4(ah[mi], sA16 + off);
                    }
                }
                const uint32_t brow = (uint32_t)(wn * 64 + ((lane >> 4) & 1) * 8 + (lane & 7));
                const uint32_t bcol = (uint32_t)(kk + ((lane >> 3) & 1) * 8);
#pragma unroll
                for (int ng = 0; ng < 4; ng++) {
                    uint32_t bh[4];
                    uint32_t off = swz((brow + ng * 16) * 128 + bcol * 2);
                    ldsm4(bh, sB16 + off);
#pragma unroll
                    for (int mi = 0; mi < MI; mi++) {
#pragma unroll
                        for (int half = 0; half < 2; half++) {
                            mma16816h(acc[mi][ng * 2 + half], ah[mi], bh + half * 2);
                        }
                    }
                }
            }
            __syncthreads();
        }
    }

    const int g = lane >> 2;
    const int t = lane & 3;
#pragma unroll
    for (int mi = 0; mi < MI; mi++) {
        const int r = row0 + wm * (MI * 16) + mi * 16 + g;
#pragma unroll
        for (int nt = 0; nt < 8; nt++) {
            const int col = n0 + wn * 64 + nt * 8 + 2 * t;
            float2 v0 = make_float2(acc[mi][nt][0] * alpha, acc[mi][nt][1] * alpha);
            float2 v1 = make_float2(acc[mi][nt][2] * alpha, acc[mi][nt][3] * alpha);
            if (EPI == 3) {
                uint32_t l0, l1;
                uint32_t h0 = pack2h(v0.x, v0.y, l0);
                uint32_t h1 = pack2h(v1.x, v1.y, l1);
                *(uint32_t*)(Ch + (size_t)r * ldc + col) = h0;
                *(uint32_t*)(Cl + (size_t)r * ldc + col) = l0;
                *(uint32_t*)(Ch + (size_t)(r + 8) * ldc + col) = h1;
                *(uint32_t*)(Cl + (size_t)(r + 8) * ldc + col) = l1;
            } else {
                *(float2*)(C + (size_t)r * ldc + col)       = v0;
                *(float2*)(C + (size_t)(r + 8) * ldc + col) = v1;
            }
        }
    }
}

// ---------------------------------------------------------------------------
// Embedding gather
// ---------------------------------------------------------------------------
__global__ void embed_kernel(const int* __restrict__ x,
                             const float* __restrict__ embed,
                             float* __restrict__ h) {
    int s = blockIdx.y;
    int c = blockIdx.x * 256 + threadIdx.x;
    h[(size_t)s * H_ + c] = embed[(size_t)x[s] * H_ + c];
}

// ---------------------------------------------------------------------------
// Rotary (in-place on qkv)
// ---------------------------------------------------------------------------
__global__ void rotary_kernel(float* __restrict__ qkv) {
    int idx = blockIdx.x * 256 + threadIdx.x;
    int i = idx & 15;
    int n = (idx >> 4) & 15;
    int s = idx >> 8;
    float inv = expf(-(float)i * 0.575646273248511f);
    float ang = (float)s * inv;
    float sn, cs;
    sincosf(ang, &sn, &cs);
    float* p = qkv + (size_t)s * (3 * H_) + n * (3 * HD_);
    float a = p[i], c2 = p[i + 16];
    p[i]      = a * cs - c2 * sn;
    p[i + 16] = c2 * cs + a * sn;
    float* pk = p + HD_;
    a = pk[i]; c2 = pk[i + 16];
    pk[i]      = a * cs - c2 * sn;
    pk[i + 16] = c2 * cs + a * sn;
}

// ---------------------------------------------------------------------------
// Causal softmax; emits probs as fp16, zeroes k>q.
// ---------------------------------------------------------------------------
__global__ void softmax_f16_kernel(float* __restrict__ scores,
                                   __half* __restrict__ pf) {
    const int q = blockIdx.x;
    const int n = blockIdx.y;
    const size_t base = ((size_t)n * S_ + q) * (size_t)S_;
    float* row = scores + base;
    __half* pr = pf + base;
    const int len = q + 1;
    const int tid = threadIdx.x;
    __shared__ float red[256];

    float mx = -3.4e38f;
    for (int i = tid; i < len; i += 256) mx = fmaxf(mx, row[i]);
    red[tid] = mx; __syncthreads();
    for (int o = 128; o > 0; o >>= 1) {
        if (tid < o) red[tid] = fmaxf(red[tid], red[tid + o]);
        __syncthreads();
    }
    mx = red[0]; __syncthreads();

    float sum = 0.f;
    for (int i = tid; i < len; i += 256) {
        float e = expf(row[i] - mx);
        row[i] = e;
        sum += e;
    }
    red[tid] = sum; __syncthreads();
    for (int o = 128; o > 0; o >>= 1) {
        if (tid < o) red[tid] += red[tid + o];
        __syncthreads();
    }
    const float inv = 1.f / red[0];
    for (int i = tid; i < len; i += 256)
        pr[i] = __float2half_rn(row[i] * inv);
    const __half z = __float2half_rn(0.f);
    for (int i = len + tid; i < S_; i += 256) pr[i] = z;
}

// ---------------------------------------------------------------------------
// Launcher with 3-stream fork/join (capture-safe: full join before return)
// ---------------------------------------------------------------------------
#define SM_H256 (2 * (16384 + 256 * 128))
#define SM_H128 (2 * (16384 + 128 * 128))

extern "C" void kernel_launch(void* const* d_in, const int* in_sizes, int n_in,
                              void* d_out, int out_size) {
    const int*   x        = (const int*)  d_in[0];
    const float* embed    = (const float*)d_in[1];
    const float* ln1_g    = (const float*)d_in[2];
    const float* ln1_b    = (const float*)d_in[3];
    const float* ln2_g    = (const float*)d_in[4];
    const float* ln2_b    = (const float*)d_in[5];
    const float* qkv_w    = (const float*)d_in[6];
    const float* qkv_b    = (const float*)d_in[7];
    const float* dense_w  = (const float*)d_in[8];
    const float* dense_b  = (const float*)d_in[9];
    const float* fc1_w    = (const float*)d_in[10];
    const float* fc1_b    = (const float*)d_in[11];
    const float* fc2_w    = (const float*)d_in[12];
    const float* fc2_b    = (const float*)d_in[13];
    const float* fln_g    = (const float*)d_in[14];
    const float* fln_b    = (const float*)d_in[15];
    const float* logits_w = (const float*)d_in[16];
    float* out = (float*)d_out;

    float *h, *qkv, *mlp, *scores;
    __half *a1h, *a1l, *a2h, *a2l, *fhh, *fll;
    __half *qf, *vtf, *pf, *af;
    __half *wq, *wd, *wf1, *wf2, *wlf;
    cudaGetSymbolAddress((void**)&h,      g_h);
    cudaGetSymbolAddress((void**)&qkv,    g_qkv);
    cudaGetSymbolAddress((void**)&mlp,    g_mlp);
    cudaGetSymbolAddress((void**)&scores, g_scores);
    cudaGetSymbolAddress((void**)&a1h,    g_a1h);
    cudaGetSymbolAddress((void**)&a1l,    g_a1l);
    cudaGetSymbolAddress((void**)&a2h,    g_a2h);
    cudaGetSymbolAddress((void**)&a2l,    g_a2l);
    cudaGetSymbolAddress((void**)&fhh,    g_fhh);
    cudaGetSymbolAddress((void**)&fll,    g_fll);
    cudaGetSymbolAddress((void**)&qf,     g_qf);
    cudaGetSymbolAddress((void**)&vtf,    g_vtf);
    cudaGetSymbolAddress((void**)&pf,     g_pf);
    cudaGetSymbolAddress((void**)&af,     g_af);
    cudaGetSymbolAddress((void**)&wq,     g_wq);
    cudaGetSymbolAddress((void**)&wd,     g_wd);
    cudaGetSymbolAddress((void**)&wf1,    g_wf1);
    cudaGetSymbolAddress((void**)&wf2,    g_wf2);
    cudaGetSymbolAddress((void**)&wlf,    g_wlf);

    cudaFuncSetAttribute((const void*)gemm2<0>,
                         cudaFuncAttributeMaxDynamicSharedMemorySize, SM_G2);
    cudaFuncSetAttribute((const void*)gemm2<1>,
                         cudaFuncAttributeMaxDynamicSharedMemorySize, SM_G2);
    cudaFuncSetAttribute((const void*)gemm2<2>,
                         cudaFuncAttributeMaxDynamicSharedMemorySize, SM_G2);
    cudaFuncSetAttribute((const void*)gemm_hf<0, 256, true, false>,
                         cudaFuncAttributeMaxDynamicSharedMemorySize, SM_H256);
    cudaFuncSetAttribute((const void*)gemm_hf<3, 128, false, true>,
                         cudaFuncAttributeMaxDynamicSharedMemorySize, SM_H128);
    cudaFuncSetAttribute((const void*)gemm_hf<0, 256, false, false>,
                         cudaFuncAttributeMaxDynamicSharedMemorySize, SM_H256);

    // streams/events created once (first call is the non-captured correctness run)
    static cudaStream_t sW = 0, sM = 0;
    static cudaEvent_t evFork, evW[5], evLn2[L_], evMlp[L_];
    if (!sW) {
        cudaStreamCreateWithFlags(&sW, cudaStreamNonBlocking);
        cudaStreamCreateWithFlags(&sM, cudaStreamNonBlocking);
        cudaEventCreateWithFlags(&evFork, cudaEventDisableTiming);
        for (int i = 0; i < 5; i++) cudaEventCreateWithFlags(&evW[i], cudaEventDisableTiming);
        for (int i = 0; i < L_; i++) {
            cudaEventCreateWithFlags(&evLn2[i], cudaEventDisableTiming);
            cudaEventCreateWithFlags(&evMlp[i], cudaEventDisableTiming);
        }
    }

    const float inv_sqrt_hd = 0.08838834764831845f;  // 1/sqrt(128)

    // ---- fork ----
    cudaEventRecord(evFork, 0);
    cudaStreamWaitEvent(sW, evFork, 0);
    cudaStreamWaitEvent(sM, evFork, 0);

    // ---- weight prep on sW (fp16, z batches both layers) ----
    wsplitf_kernel<<<dim3(H_ / 32, 3 * H_ / 32, L_), 256, 0, sW>>>(
        qkv_w, 3 * H_, H_, 3 * H_, (long long)H_ * 3 * H_, (long long)H_ * 3 * H_, wq);
    cudaEventRecord(evW[0], sW);
    wsplitf_kernel<<<dim3(H_ / 32, FF_ / 32, L_), 256, 0, sW>>>(
        fc1_w, FF_, H_, FF_, (long long)H_ * FF_, (long long)H_ * FF_, wf1);
    cudaEventRecord(evW[1], sW);
    wsplitf_kernel<<<dim3(FF_ / 32, H_ / 32, L_), 256, 0, sW>>>(
        fc2_w, H_, FF_, H_, (long long)FF_ * H_, (long long)FF_ * H_, wf2);
    cudaEventRecord(evW[2], sW);
    wsplitf_kernel<<<dim3(H_ / 32, H_ / 32, L_), 256, 0, sW>>>(
        dense_w, H_, H_, H_, (long long)H_ * H_, (long long)H_ * H_, wd);
    cudaEventRecord(evW[3], sW);
    wsplitf_kernel<<<dim3(H_ / 32, V_ / 32, 1), 256, 0, sW>>>(
        logits_w, V_, H_, V_, 0, 0, wlf);
    cudaEventRecord(evW[4], sW);

    // ---- main path ----
    embed_kernel<<<dim3(H_ / 256, S_), 256>>>(x, embed, h);

    for (int l = 0; l < L_; l++) {
        // both LN read pre-update h
        ln_split2_kernel<<<S_, 256>>>(h, ln1_g + (size_t)l * H_, ln1_b + (size_t)l * H_,
                                      a1h, a1l);
        ln_split2_kernel<<<S_, 256>>>(h, ln2_g + (size_t)l * H_, ln2_b + (size_t)l * H_,
                                      a2h, a2l);
        cudaEventRecord(evLn2[l], 0);

        // ---- MLP branch on sM ----
        cudaStreamWaitEvent(sM, evLn2[l], 0);
        cudaStreamWaitEvent(sM, evW[1], 0);
        gemm2<1><<<dim3(S_ / 128, FF_ / 256), 256, SM_G2, sM>>>(
            a2h, a2l, H_, wf1 + (size_t)l * H_ * FF_, H_,
            fc1_b + (size_t)l * FF_, nullptr, fhh, fll, FF_, H_);
        cudaStreamWaitEvent(sM, evW[2], 0);
        gemm2<0><<<dim3(S_ / 128, H_ / 256), 256, SM_G2, sM>>>(
            fhh, fll, FF_, wf2 + (size_t)l * FF_ * H_, FF_,
            fc2_b + (size_t)l * H_, mlp, nullptr, nullptr, H_, FF_);
        cudaEventRecord(evMlp[l], sM);

        // ---- attention branch on main ----
        cudaStreamWaitEvent(0, evW[0], 0);
        gemm2<0><<<dim3(S_ / 128, 3 * H_ / 256), 256, SM_G2>>>(
            a1h, a1l, H_, wq + (size_t)l * H_ * 3 * H_, H_,
            qkv_b + (size_t)l * 3 * H_, qkv, nullptr, nullptr, 3 * H_, H_);

        rotary_kernel<<<(S_ * NH_ * 16) / 256, 256>>>(qkv);
        splitf_kernel<<<(S_ * 3 * H_) / 1024, 256>>>(qkv, qf);
        wsplitf_kernel<<<dim3(S_ / 32, HD_ / 32, NH_), 256>>>(
            qkv + 2 * HD_, 3 * H_, S_, HD_, 3 * HD_, (long long)HD_ * S_, vtf);

        // scores = q @ k^T * 1/sqrt(HD)  (fp16, causal block-skip)
        gemm_hf<0, 256, true, false><<<dim3(S_ / 128, S_ / 256, NH_), 256, SM_H256>>>(
            qf, 3 * H_, 3 * HD_,
            qf + HD_, 3 * H_, 3 * HD_,
            scores, nullptr, nullptr, S_, (long long)S_ * S_,
            HD_, inv_sqrt_hd);

        softmax_f16_kernel<<<dim3(S_, NH_), 256>>>(scores, pf);

        // ctx = probs @ v  (fp16, causal K-limit), split -> a1h/a1l (fp16 hi/lo)
        gemm_hf<3, 128, false, true><<<dim3(S_ / 128, 1, NH_), 256, SM_H128>>>(
            pf, S_, (long long)S_ * S_,
            vtf, S_, (long long)HD_ * S_,
            nullptr, a1h, a1l, H_, HD_,
            S_, 1.f);

        // h += ctx @ dense_w + dense_b  (2-pass fp16)
        cudaStreamWaitEvent(0, evW[3], 0);
        gemm2<2><<<dim3(S_ / 128, H_ / 256), 256, SM_G2>>>(
            a1h, a1l, H_, wd + (size_t)l * H_ * H_, H_,
            dense_b + (size_t)l * H_, h, nullptr, nullptr, H_, H_);

        // join MLP, h += mlp
        cudaStreamWaitEvent(0, evMlp[l], 0);
        add_kernel<<<(S_ * H_) / 1024, 256>>>(h, mlp);
    }

    // Final LN (fp16) + single-pass fp16 logits GEMM (joins sW via evW[4])
    ln_splitf_kernel<<<S_, 256>>>(h, fln_g, fln_b, af);
    cudaStreamWaitEvent(0, evW[4], 0);
    gemm_hf<0, 256, false, false><<<dim3(S_ / 128, V_ / 256, 1), 256, SM_H256>>>(
        af, H_, 0, wlf, H_, 0, out, nullptr, nullptr, V_, 0, H_, 1.f);
}

// round 10
// speedup vs baseline: 7.8787x; 1.3537x over previous
#include <cuda_runtime.h>
#include <cuda_fp16.h>
#include <math.h>
#include <stdint.h>

// Problem constants
#define S_    2048
#define H_    2048
#define NH_   16
#define HD_   128
#define ROT_  32
#define FF_   8192
#define L_    2
#define V_    32000
#define EPS_  1e-5f

// ---------------------------------------------------------------------------
// Scratch (static device globals)
// ---------------------------------------------------------------------------
__device__ float g_h  [(size_t)S_ * H_];
__device__ float g_mlp[(size_t)S_ * H_];
__device__ float g_scores[(size_t)NH_ * S_ * S_];

// fp16 activations
__device__ __half g_a1f[(size_t)S_ * H_];
__device__ __half g_a2f[(size_t)S_ * H_];
__device__ __half g_ff [(size_t)S_ * FF_];
__device__ __half g_qf [(size_t)S_ * 3 * H_];
__device__ __half g_vtf[(size_t)NH_ * HD_ * S_];
__device__ __half g_pf [(size_t)NH_ * S_ * S_];
__device__ __half g_ctxf[(size_t)S_ * H_];
__device__ __half g_af [(size_t)S_ * H_];

// per-GEMM transposed fp16 weights
__device__ __half g_wq [(size_t)L_ * H_ * 3 * H_];
__device__ __half g_wd [(size_t)L_ * H_ * H_];
__device__ __half g_wf1[(size_t)L_ * H_ * FF_];
__device__ __half g_wf2[(size_t)L_ * FF_ * H_];
__device__ __half g_wlf[(size_t)V_ * H_];

// ---------------------------------------------------------------------------
// Helpers
// ---------------------------------------------------------------------------
__device__ __forceinline__ uint32_t smem_u32(const void* p) {
    uint32_t a;
    asm("{ .reg .u64 t; cvta.to.shared.u64 t, %1; cvt.u32.u64 %0, t; }"
        : "=r"(a) : "l"(p));
    return a;
}
__device__ __forceinline__ uint32_t swz(uint32_t off) {
    return off ^ ((off >> 3) & 0x70);
}
__device__ __forceinline__ float gelu_f(float x) {
    float t = tanhf(0.79788456f * x * (1.f + 0.044715f * x * x));
    return 0.5f * x * (1.f + t);
}
__device__ __forceinline__ void ldsm4(uint32_t (&r)[4], uint32_t addr) {
    asm volatile("ldmatrix.sync.aligned.m8n8.x4.shared.b16 {%0,%1,%2,%3}, [%4];"
                 : "=r"(r[0]), "=r"(r[1]), "=r"(r[2]), "=r"(r[3]) : "r"(addr));
}
__device__ __forceinline__ void mma16816h(float (&d)[4], const uint32_t (&a)[4],
                                          const uint32_t* b) {
    asm volatile(
        "mma.sync.aligned.m16n8k16.row.col.f32.f16.f16.f32 "
        "{%0,%1,%2,%3}, {%4,%5,%6,%7}, {%8,%9}, {%0,%1,%2,%3};"
        : "+f"(d[0]), "+f"(d[1]), "+f"(d[2]), "+f"(d[3])
        : "r"(a[0]), "r"(a[1]), "r"(a[2]), "r"(a[3]), "r"(b[0]), "r"(b[1]));
}
__device__ __forceinline__ void cpa16(uint32_t s, const void* g) {
    asm volatile("cp.async.cg.shared.global [%0], [%1], 16;" :: "r"(s), "l"(g));
}

// ---------------------------------------------------------------------------
// Transpose fp32 -> fp16: W[Kd rows][N cols] (ldw) -> WT[N][Kd], z-batched
// ---------------------------------------------------------------------------
__global__ void wsplitf_kernel(const float* __restrict__ W, int ldw, int Kd, int N,
                               long long zin, long long zout,
                               __half* __restrict__ WT) {
    W  += (size_t)blockIdx.z * zin;
    WT += (size_t)blockIdx.z * zout;

    __shared__ float s[32][33];
    const int k0 = blockIdx.x * 32;
    const int n0 = blockIdx.y * 32;
    const int tid = threadIdx.x;
    const int r  = tid >> 3;
    const int c4 = (tid & 7) * 4;

    float4 v = *(const float4*)(W + (size_t)(k0 + r) * ldw + n0 + c4);
    s[r][c4 + 0] = v.x; s[r][c4 + 1] = v.y;
    s[r][c4 + 2] = v.z; s[r][c4 + 3] = v.w;
    __syncthreads();

    __half2 p0 = __floats2half2_rn(s[c4 + 0][r], s[c4 + 1][r]);
    __half2 p1 = __floats2half2_rn(s[c4 + 2][r], s[c4 + 3][r]);
    size_t o = (size_t)(n0 + r) * Kd + k0 + c4;
    *(__half2*)(WT + o)     = p0;
    *(__half2*)(WT + o + 2) = p1;
}

// Transpose fp16 -> fp16 (v heads): V[Kd rows][...] (ldv) -> VT[N][Kd], z-batched
__global__ void vtranf_kernel(const __half* __restrict__ V, int ldv, int Kd, int N,
                              long long zin, long long zout,
                              __half* __restrict__ VT) {
    V  += (size_t)blockIdx.z * zin;
    VT += (size_t)blockIdx.z * zout;

    __shared__ __half s[32][40];
    const int k0 = blockIdx.x * 32;   // row (s) tile
    const int n0 = blockIdx.y * 32;   // col (d) tile
    const int tid = threadIdx.x;
    const int r  = tid >> 3;
    const int c4 = (tid & 7) * 4;

    uint2 v = *(const uint2*)(V + (size_t)(k0 + r) * ldv + n0 + c4);
    *(uint32_t*)&s[r][c4]     = v.x;
    *(uint32_t*)&s[r][c4 + 2] = v.y;
    __syncthreads();

    __half o0 = s[c4 + 0][r], o1 = s[c4 + 1][r];
    __half o2 = s[c4 + 2][r], o3 = s[c4 + 3][r];
    size_t o = (size_t)(n0 + r) * Kd + k0 + c4;
    VT[o + 0] = o0; VT[o + 1] = o1; VT[o + 2] = o2; VT[o + 3] = o3;
}

// h += m
__global__ void add_kernel(float* __restrict__ h, const float* __restrict__ m) {
    int i = (blockIdx.x * 256 + threadIdx.x) * 4;
    float4 a = *(const float4*)(h + i);
    float4 b = *(const float4*)(m + i);
    a.x += b.x; a.y += b.y; a.z += b.z; a.w += b.w;
    *(float4*)(h + i) = a;
}

// ---------------------------------------------------------------------------
// LayerNorm -> fp16 output
// ---------------------------------------------------------------------------
__global__ void ln_f16_kernel(const float* __restrict__ in,
                              const float* __restrict__ g,
                              const float* __restrict__ b,
                              __half* __restrict__ o16) {
    const int s = blockIdx.x;
    const int tid = threadIdx.x;
    const float* row = in + (size_t)s * H_;
    __shared__ float red[256];

    float v[8];
    float lsum = 0.f;
#pragma unroll
    for (int i = 0; i < 8; i++) { v[i] = row[tid + i * 256]; lsum += v[i]; }
    red[tid] = lsum; __syncthreads();
    for (int o = 128; o > 0; o >>= 1) {
        if (tid < o) red[tid] += red[tid + o];
        __syncthreads();
    }
    const float mean = red[0] * (1.f / H_);
    __syncthreads();

    float lvar = 0.f;
#pragma unroll
    for (int i = 0; i < 8; i++) { float d = v[i] - mean; lvar += d * d; }
    red[tid] = lvar; __syncthreads();
    for (int o = 128; o > 0; o >>= 1) {
        if (tid < o) red[tid] += red[tid + o];
        __syncthreads();
    }
    const float rstd = rsqrtf(red[0] * (1.f / H_) + EPS_);

#pragma unroll
    for (int i = 0; i < 8; i++) {
        int c = tid + i * 256;
        float val = (v[i] - mean) * rstd * g[c] + b[c];
        o16[(size_t)s * H_ + c] = __float2half_rn(val);
    }
}

// ---------------------------------------------------------------------------
// Rotary, in-place on fp16 qkv buffer
// ---------------------------------------------------------------------------
__global__ void rotaryf_kernel(__half* __restrict__ qf) {
    int idx = blockIdx.x * 256 + threadIdx.x;
    int i = idx & 15;
    int n = (idx >> 4) & 15;
    int s = idx >> 8;
    float inv = expf(-(float)i * 0.575646273248511f);
    float ang = (float)s * inv;
    float sn, cs;
    sincosf(ang, &sn, &cs);
    __half* p = qf + (size_t)s * (3 * H_) + n * (3 * HD_);
    float a = __half2float(p[i]), c2 = __half2float(p[i + 16]);
    p[i]      = __float2half_rn(a * cs - c2 * sn);
    p[i + 16] = __float2half_rn(c2 * cs + a * sn);
    __half* pk = p + HD_;
    a = __half2float(pk[i]); c2 = __half2float(pk[i + 16]);
    pk[i]      = __float2half_rn(a * cs - c2 * sn);
    pk[i + 16] = __float2half_rn(c2 * cs + a * sn);
}

// ---------------------------------------------------------------------------
// Causal softmax; emits probs as fp16, zeroes k>q.
// ---------------------------------------------------------------------------
__global__ void softmax_f16_kernel(float* __restrict__ scores,
                                   __half* __restrict__ pf) {
    const int q = blockIdx.x;
    const int n = blockIdx.y;
    const size_t base = ((size_t)n * S_ + q) * (size_t)S_;
    float* row = scores + base;
    __half* pr = pf + base;
    const int len = q + 1;
    const int tid = threadIdx.x;
    __shared__ float red[256];

    float mx = -3.4e38f;
    for (int i = tid; i < len; i += 256) mx = fmaxf(mx, row[i]);
    red[tid] = mx; __syncthreads();
    for (int o = 128; o > 0; o >>= 1) {
        if (tid < o) red[tid] = fmaxf(red[tid], red[tid + o]);
        __syncthreads();
    }
    mx = red[0]; __syncthreads();

    float sum = 0.f;
    for (int i = tid; i < len; i += 256) {
        float e = expf(row[i] - mx);
        row[i] = e;
        sum += e;
    }
    red[tid] = sum; __syncthreads();
    for (int o = 128; o > 0; o >>= 1) {
        if (tid < o) red[tid] += red[tid + o];
        __syncthreads();
    }
    const float inv = 1.f / red[0];
    for (int i = tid; i < len; i += 256)
        pr[i] = __float2half_rn(row[i] * inv);
    const __half z = __float2half_rn(0.f);
    for (int i = len + tid; i < S_; i += 256) pr[i] = z;
}

// ---------------------------------------------------------------------------
// Single-pass fp16 GEMM: out = alpha * A[M,K] @ B[N,K]^T (+ bias).
//   EPI: 0 = fp32 store, 1 = gelu -> fp16, 2 = fp32 accumulate, 3 = fp16 store.
//   CAUS: skip blocks with n0 > row0+127. CAUSK: K limited to row0+128.
//   z-batched via sA/sB/sC.
// ---------------------------------------------------------------------------
template <int EPI, int BN, bool CAUS, bool CAUSK>
__global__ void __launch_bounds__(256, 1) gemm_hf(
    const __half* __restrict__ A, int lda, long long sA,
    const __half* __restrict__ B, int ldb, long long sB,
    const float* __restrict__ bias,
    float* __restrict__ C, __half* __restrict__ H16,
    int ldc, long long sC,
    int K, float alpha) {

    constexpr int MI  = (BN == 256) ? 4 : 2;
    constexpr int BUF = 16384 + BN * 128;

    extern __shared__ char smem[];
    const uint32_t sb = smem_u32(smem);
    const int tid  = threadIdx.x;
    const int lane = tid & 31;
    const int wid  = tid >> 5;
    const int wm   = (BN == 256) ? (wid & 1) : (wid & 3);
    const int wn   = (BN == 256) ? (wid >> 1) : (wid >> 2);
    const int row0 = blockIdx.x * 128;
    const int n0   = blockIdx.y * BN;

    if (CAUS && n0 > row0 + 127) return;

    A += (size_t)blockIdx.z * sA;
    B += (size_t)blockIdx.z * sB;
    if (C)   C   += (size_t)blockIdx.z * sC;
    if (H16) H16 += (size_t)blockIdx.z * sC;

    float acc[MI][8][4];
#pragma unroll
    for (int i = 0; i < MI; i++)
#pragma unroll
        for (int j = 0; j < 8; j++)
#pragma unroll
            for (int e = 0; e < 4; e++) acc[i][j][e] = 0.f;

    const int nch = CAUSK ? ((row0 + 128) >> 6) : (K >> 6);

    for (int c = 0; c <= nch; c++) {
        if (c < nch) {
            const uint32_t bufo = (uint32_t)(c & 1) * BUF;
            const int k0 = c << 6;
#pragma unroll
            for (int i = 0; i < 4; i++) {
                int idx = tid + i * 256;
                int r  = idx >> 3;
                int cc = (idx & 7) * 8;
                uint32_t soff = swz((uint32_t)(r * 128 + cc * 2));
                cpa16(sb + bufo + soff, A + (size_t)(row0 + r) * lda + k0 + cc);
            }
#pragma unroll
            for (int i = 0; i < BN / 32; i++) {
                int idx = tid + i * 256;
                int r  = idx >> 3;
                int cc = (idx & 7) * 8;
                uint32_t soff = swz((uint32_t)(r * 128 + cc * 2));
                cpa16(sb + bufo + 16384 + soff, B + (size_t)(n0 + r) * ldb + k0 + cc);
            }
            asm volatile("cp.async.commit_group;" ::: "memory");
        }
        if (c >= 1) {
            if (c < nch) asm volatile("cp.async.wait_group 1;" ::: "memory");
            else         asm volatile("cp.async.wait_group 0;" ::: "memory");
            __syncthreads();

            const uint32_t bufo = (uint32_t)((c - 1) & 1) * BUF;
            const uint32_t sA16 = sb + bufo;
            const uint32_t sB16 = sA16 + 16384;

#pragma unroll
            for (int ks = 0; ks < 4; ks++) {
                const int kk = ks * 16;
                uint32_t ah[MI][4];
                {
                    const uint32_t arow = (uint32_t)(wm * (MI * 16) + (lane & 15));
                    const uint32_t acol = (uint32_t)(kk + (lane >> 4) * 8);
#pragma unroll
                    for (int mi = 0; mi < MI; mi++) {
                        uint32_t off = swz((arow + mi * 16) * 128 + acol * 2);
                        ldsm4(ah[mi], sA16 + off);
                    }
                }
                const uint32_t brow = (uint32_t)(wn * 64 + ((lane >> 4) & 1) * 8 + (lane & 7));
                const uint32_t bcol = (uint32_t)(kk + ((lane >> 3) & 1) * 8);
#pragma unroll
                for (int ng = 0; ng < 4; ng++) {
                    uint32_t bh[4];
                    uint32_t off = swz((brow + ng * 16) * 128 + bcol * 2);
                    ldsm4(bh, sB16 + off);
#pragma unroll
                    for (int mi = 0; mi < MI; mi++) {
#pragma unroll
                        for (int half = 0; half < 2; half++) {
                            mma16816h(acc[mi][ng * 2 + half], ah[mi], bh + half * 2);
                        }
                    }
                }
            }
            __syncthreads();
        }
    }

    const int g = lane >> 2;
    const int t = lane & 3;
#pragma unroll
    for (int mi = 0; mi < MI; mi++) {
        const int r = row0 + wm * (MI * 16) + mi * 16 + g;
#pragma unroll
        for (int nt = 0; nt < 8; nt++) {
            const int col = n0 + wn * 64 + nt * 8 + 2 * t;
            float2 v0 = make_float2(acc[mi][nt][0] * alpha, acc[mi][nt][1] * alpha);
            float2 v1 = make_float2(acc[mi][nt][2] * alpha, acc[mi][nt][3] * alpha);
            if (bias) {
                float2 bv = *(const float2*)(bias + col);
                v0.x += bv.x; v0.y += bv.y;
                v1.x += bv.x; v1.y += bv.y;
            }
            if (EPI == 1 || EPI == 3) {
                if (EPI == 1) {
                    v0.x = gelu_f(v0.x); v0.y = gelu_f(v0.y);
                    v1.x = gelu_f(v1.x); v1.y = gelu_f(v1.y);
                }
                *(__half2*)(H16 + (size_t)r * ldc + col)       = __floats2half2_rn(v0.x, v0.y);
                *(__half2*)(H16 + (size_t)(r + 8) * ldc + col) = __floats2half2_rn(v1.x, v1.y);
            } else {
                float* p0 = C + (size_t)r * ldc + col;
                float* p1 = C + (size_t)(r + 8) * ldc + col;
                if (EPI == 2) {
                    float2 o0 = *(const float2*)p0;
                    float2 o1 = *(const float2*)p1;
                    v0.x += o0.x; v0.y += o0.y;
                    v1.x += o1.x; v1.y += o1.y;
                }
                *(float2*)p0 = v0;
                *(float2*)p1 = v1;
            }
        }
    }
}

// ---------------------------------------------------------------------------
// Embedding gather
// ---------------------------------------------------------------------------
__global__ void embed_kernel(const int* __restrict__ x,
                             const float* __restrict__ embed,
                             float* __restrict__ h) {
    int s = blockIdx.y;
    int c = blockIdx.x * 256 + threadIdx.x;
    h[(size_t)s * H_ + c] = embed[(size_t)x[s] * H_ + c];
}

// ---------------------------------------------------------------------------
// Launcher with 3-stream fork/join (capture-safe: full join before return)
// ---------------------------------------------------------------------------
#define SM_H256 (2 * (16384 + 256 * 128))
#define SM_H128 (2 * (16384 + 128 * 128))

extern "C" void kernel_launch(void* const* d_in, const int* in_sizes, int n_in,
                              void* d_out, int out_size) {
    const int*   x        = (const int*)  d_in[0];
    const float* embed    = (const float*)d_in[1];
    const float* ln1_g    = (const float*)d_in[2];
    const float* ln1_b    = (const float*)d_in[3];
    const float* ln2_g    = (const float*)d_in[4];
    const float* ln2_b    = (const float*)d_in[5];
    const float* qkv_w    = (const float*)d_in[6];
    const float* qkv_b    = (const float*)d_in[7];
    const float* dense_w  = (const float*)d_in[8];
    const float* dense_b  = (const float*)d_in[9];
    const float* fc1_w    = (const float*)d_in[10];
    const float* fc1_b    = (const float*)d_in[11];
    const float* fc2_w    = (const float*)d_in[12];
    const float* fc2_b    = (const float*)d_in[13];
    const float* fln_g    = (const float*)d_in[14];
    const float* fln_b    = (const float*)d_in[15];
    const float* logits_w = (const float*)d_in[16];
    float* out = (float*)d_out;

    float *h, *mlp, *scores;
    __half *a1f, *a2f, *ff, *qf, *vtf, *pf, *ctxf, *af;
    __half *wq, *wd, *wf1, *wf2, *wlf;
    cudaGetSymbolAddress((void**)&h,      g_h);
    cudaGetSymbolAddress((void**)&mlp,    g_mlp);
    cudaGetSymbolAddress((void**)&scores, g_scores);
    cudaGetSymbolAddress((void**)&a1f,    g_a1f);
    cudaGetSymbolAddress((void**)&a2f,    g_a2f);
    cudaGetSymbolAddress((void**)&ff,     g_ff);
    cudaGetSymbolAddress((void**)&qf,     g_qf);
    cudaGetSymbolAddress((void**)&vtf,    g_vtf);
    cudaGetSymbolAddress((void**)&pf,     g_pf);
    cudaGetSymbolAddress((void**)&ctxf,   g_ctxf);
    cudaGetSymbolAddress((void**)&af,     g_af);
    cudaGetSymbolAddress((void**)&wq,     g_wq);
    cudaGetSymbolAddress((void**)&wd,     g_wd);
    cudaGetSymbolAddress((void**)&wf1,    g_wf1);
    cudaGetSymbolAddress((void**)&wf2,    g_wf2);
    cudaGetSymbolAddress((void**)&wlf,    g_wlf);

    cudaFuncSetAttribute((const void*)gemm_hf<0, 256, false, false>,
                         cudaFuncAttributeMaxDynamicSharedMemorySize, SM_H256);
    cudaFuncSetAttribute((const void*)gemm_hf<1, 256, false, false>,
                         cudaFuncAttributeMaxDynamicSharedMemorySize, SM_H256);
    cudaFuncSetAttribute((const void*)gemm_hf<2, 256, false, false>,
                         cudaFuncAttributeMaxDynamicSharedMemorySize, SM_H256);
    cudaFuncSetAttribute((const void*)gemm_hf<3, 256, false, false>,
                         cudaFuncAttributeMaxDynamicSharedMemorySize, SM_H256);
    cudaFuncSetAttribute((const void*)gemm_hf<0, 256, true, false>,
                         cudaFuncAttributeMaxDynamicSharedMemorySize, SM_H256);
    cudaFuncSetAttribute((const void*)gemm_hf<3, 128, false, true>,
                         cudaFuncAttributeMaxDynamicSharedMemorySize, SM_H128);

    // streams/events created once (first call is the non-captured correctness run)
    static cudaStream_t sW = 0, sM = 0;
    static cudaEvent_t evFork, evW[5], evLn2[L_], evMlp[L_];
    if (!sW) {
        cudaStreamCreateWithFlags(&sW, cudaStreamNonBlocking);
        cudaStreamCreateWithFlags(&sM, cudaStreamNonBlocking);
        cudaEventCreateWithFlags(&evFork, cudaEventDisableTiming);
        for (int i = 0; i < 5; i++) cudaEventCreateWithFlags(&evW[i], cudaEventDisableTiming);
        for (int i = 0; i < L_; i++) {
            cudaEventCreateWithFlags(&evLn2[i], cudaEventDisableTiming);
            cudaEventCreateWithFlags(&evMlp[i], cudaEventDisableTiming);
        }
    }

    const float inv_sqrt_hd = 0.08838834764831845f;  // 1/sqrt(128)

    // ---- fork ----
    cudaEventRecord(evFork, 0);
    cudaStreamWaitEvent(sW, evFork, 0);
    cudaStreamWaitEvent(sM, evFork, 0);

    // ---- weight prep on sW (fp16, z batches both layers) ----
    wsplitf_kernel<<<dim3(H_ / 32, 3 * H_ / 32, L_), 256, 0, sW>>>(
        qkv_w, 3 * H_, H_, 3 * H_, (long long)H_ * 3 * H_, (long long)H_ * 3 * H_, wq);
    cudaEventRecord(evW[0], sW);
    wsplitf_kernel<<<dim3(H_ / 32, FF_ / 32, L_), 256, 0, sW>>>(
        fc1_w, FF_, H_, FF_, (long long)H_ * FF_, (long long)H_ * FF_, wf1);
    cudaEventRecord(evW[1], sW);
    wsplitf_kernel<<<dim3(FF_ / 32, H_ / 32, L_), 256, 0, sW>>>(
        fc2_w, H_, FF_, H_, (long long)FF_ * H_, (long long)FF_ * H_, wf2);
    cudaEventRecord(evW[2], sW);
    wsplitf_kernel<<<dim3(H_ / 32, H_ / 32, L_), 256, 0, sW>>>(
        dense_w, H_, H_, H_, (long long)H_ * H_, (long long)H_ * H_, wd);
    cudaEventRecord(evW[3], sW);
    wsplitf_kernel<<<dim3(H_ / 32, V_ / 32, 1), 256, 0, sW>>>(
        logits_w, V_, H_, V_, 0, 0, wlf);
    cudaEventRecord(evW[4], sW);

    // ---- main path ----
    embed_kernel<<<dim3(H_ / 256, S_), 256>>>(x, embed, h);

    for (int l = 0; l < L_; l++) {
        // both LN read pre-update h
        ln_f16_kernel<<<S_, 256>>>(h, ln1_g + (size_t)l * H_, ln1_b + (size_t)l * H_, a1f);
        ln_f16_kernel<<<S_, 256>>>(h, ln2_g + (size_t)l * H_, ln2_b + (size_t)l * H_, a2f);
        cudaEventRecord(evLn2[l], 0);

        // ---- MLP branch on sM ----
        cudaStreamWaitEvent(sM, evLn2[l], 0);
        cudaStreamWaitEvent(sM, evW[1], 0);
        gemm_hf<1, 256, false, false><<<dim3(S_ / 128, FF_ / 256, 1), 256, SM_H256, sM>>>(
            a2f, H_, 0, wf1 + (size_t)l * H_ * FF_, H_, 0,
            fc1_b + (size_t)l * FF_, nullptr, ff, FF_, 0, H_, 1.f);
        cudaStreamWaitEvent(sM, evW[2], 0);
        gemm_hf<0, 256, false, false><<<dim3(S_ / 128, H_ / 256, 1), 256, SM_H256, sM>>>(
            ff, FF_, 0, wf2 + (size_t)l * FF_ * H_, FF_, 0,
            fc2_b + (size_t)l * H_, mlp, nullptr, H_, 0, FF_, 1.f);
        cudaEventRecord(evMlp[l], sM);

        // ---- attention branch on main ----
        cudaStreamWaitEvent(0, evW[0], 0);
        gemm_hf<3, 256, false, false><<<dim3(S_ / 128, 3 * H_ / 256, 1), 256, SM_H256>>>(
            a1f, H_, 0, wq + (size_t)l * H_ * 3 * H_, H_, 0,
            qkv_b + (size_t)l * 3 * H_, nullptr, qf, 3 * H_, 0, H_, 1.f);

        rotaryf_kernel<<<(S_ * NH_ * 16) / 256, 256>>>(qf);
        vtranf_kernel<<<dim3(S_ / 32, HD_ / 32, NH_), 256>>>(
            qf + 2 * HD_, 3 * H_, S_, HD_, 3 * HD_, (long long)HD_ * S_, vtf);

        // scores = q @ k^T * 1/sqrt(HD)  (fp16, causal block-skip)
        gemm_hf<0, 256, true, false><<<dim3(S_ / 128, S_ / 256, NH_), 256, SM_H256>>>(
            qf, 3 * H_, 3 * HD_,
            qf + HD_, 3 * H_, 3 * HD_,
            nullptr, scores, nullptr, S_, (long long)S_ * S_,
            HD_, inv_sqrt_hd);

        softmax_f16_kernel<<<dim3(S_, NH_), 256>>>(scores, pf);

        // ctx = probs @ v  (fp16, causal K-limit) -> ctxf fp16
        gemm_hf<3, 128, false, true><<<dim3(S_ / 128, 1, NH_), 256, SM_H128>>>(
            pf, S_, (long long)S_ * S_,
            vtf, S_, (long long)HD_ * S_,
            nullptr, nullptr, ctxf, H_, HD_,
            S_, 1.f);

        // h += ctx @ dense_w + dense_b
        cudaStreamWaitEvent(0, evW[3], 0);
        gemm_hf<2, 256, false, false><<<dim3(S_ / 128, H_ / 256, 1), 256, SM_H256>>>(
            ctxf, H_, 0, wd + (size_t)l * H_ * H_, H_, 0,
            dense_b + (size_t)l * H_, h, nullptr, H_, 0, H_, 1.f);

        // join MLP, h += mlp
        cudaStreamWaitEvent(0, evMlp[l], 0);
        add_kernel<<<(S_ * H_) / 1024, 256>>>(h, mlp);
    }

    // Final LN (fp16) + single-pass fp16 logits GEMM (joins sW via evW[4])
    ln_f16_kernel<<<S_, 256>>>(h, fln_g, fln_b, af);
    cudaStreamWaitEvent(0, evW[4], 0);
    gemm_hf<0, 256, false, false><<<dim3(S_ / 128, V_ / 256, 1), 256, SM_H256>>>(
        af, H_, 0, wlf, H_, 0, nullptr, out, nullptr, V_, 0, H_, 1.f);
}